// round 1
// baseline (speedup 1.0000x reference)
#include <cuda_runtime.h>
#include <math.h>

#define CB   2
#define CS   2048
#define CE   1024
#define CR   256
#define CH   16
#define CHD  64
#define CDQK 128
#define MTOK (CB*CS)   // 4096

// ---------------- scratch (no allocation allowed -> __device__ globals) ----
__device__ float g_qlat [MTOK*CR];
__device__ float g_krlat[MTOK*CR];
__device__ float g_kv   [MTOK*CR];
__device__ float g_tmp  [MTOK*CE];
__device__ float g_Qt   [CB*CH*CDQK*CS];   // [b,h,d,s]
__device__ float g_Kt   [CB*CH*CDQK*CS];   // [b,h,d,s]
__device__ float g_V    [CB*CH*CS*CHD];    // [b,h,s,d]
__device__ float g_Y    [MTOK*CE];

// ======================= SGEMM NT: C[M,N] = A[M,K] * W[N,K]^T =============
#define GLD 132   // padded smem row (128+4): float4-aligned, reduces store conflicts

__global__ __launch_bounds__(256) void sgemm_nt(
    const float* __restrict__ A, const float* __restrict__ W,
    float* __restrict__ C, int M, int N, int K)
{
    __shared__ float As[16 * GLD];
    __shared__ float Bs[16 * GLD];
    const int tid = threadIdx.x;
    const int tx  = tid & 15, ty = tid >> 4;
    const int m0  = blockIdx.y * 128, n0 = blockIdx.x * 128;
    const int lr  = tid >> 2;          // 0..63
    const int lc4 = (tid & 3) * 4;     // 0,4,8,12

    const float* Ag = A + (size_t)(m0 + lr) * K + lc4;
    const float* Bg = W + (size_t)(n0 + lr) * K + lc4;

    float acc[8][8];
#pragma unroll
    for (int i = 0; i < 8; i++)
#pragma unroll
        for (int j = 0; j < 8; j++) acc[i][j] = 0.f;

    // prefetch tile 0
    float4 a0 = *(const float4*)(Ag);
    float4 a1 = *(const float4*)(Ag + (size_t)64 * K);
    float4 b0 = *(const float4*)(Bg);
    float4 b1 = *(const float4*)(Bg + (size_t)64 * K);

    for (int k0 = 0; k0 < K; k0 += 16) {
        __syncthreads();
        As[(lc4+0)*GLD + lr]      = a0.x; As[(lc4+1)*GLD + lr]      = a0.y;
        As[(lc4+2)*GLD + lr]      = a0.z; As[(lc4+3)*GLD + lr]      = a0.w;
        As[(lc4+0)*GLD + lr + 64] = a1.x; As[(lc4+1)*GLD + lr + 64] = a1.y;
        As[(lc4+2)*GLD + lr + 64] = a1.z; As[(lc4+3)*GLD + lr + 64] = a1.w;
        Bs[(lc4+0)*GLD + lr]      = b0.x; Bs[(lc4+1)*GLD + lr]      = b0.y;
        Bs[(lc4+2)*GLD + lr]      = b0.z; Bs[(lc4+3)*GLD + lr]      = b0.w;
        Bs[(lc4+0)*GLD + lr + 64] = b1.x; Bs[(lc4+1)*GLD + lr + 64] = b1.y;
        Bs[(lc4+2)*GLD + lr + 64] = b1.z; Bs[(lc4+3)*GLD + lr + 64] = b1.w;
        __syncthreads();

        if (k0 + 16 < K) {   // prefetch next tile (LDG latency hidden by compute)
            a0 = *(const float4*)(Ag + k0 + 16);
            a1 = *(const float4*)(Ag + (size_t)64 * K + k0 + 16);
            b0 = *(const float4*)(Bg + k0 + 16);
            b1 = *(const float4*)(Bg + (size_t)64 * K + k0 + 16);
        }

#pragma unroll
        for (int kk = 0; kk < 16; kk++) {
            float4 pa0 = *(const float4*)&As[kk*GLD + ty*4];
            float4 pa1 = *(const float4*)&As[kk*GLD + 64 + ty*4];
            float4 pb0 = *(const float4*)&Bs[kk*GLD + tx*4];
            float4 pb1 = *(const float4*)&Bs[kk*GLD + 64 + tx*4];
            float a[8] = {pa0.x,pa0.y,pa0.z,pa0.w, pa1.x,pa1.y,pa1.z,pa1.w};
            float b[8] = {pb0.x,pb0.y,pb0.z,pb0.w, pb1.x,pb1.y,pb1.z,pb1.w};
#pragma unroll
            for (int i = 0; i < 8; i++)
#pragma unroll
                for (int j = 0; j < 8; j++) acc[i][j] += a[i] * b[j];
        }
    }

#pragma unroll
    for (int i = 0; i < 8; i++) {
        int r = m0 + ((i < 4) ? (ty*4 + i) : (64 + ty*4 + i - 4));
        float4 c0 = make_float4(acc[i][0], acc[i][1], acc[i][2], acc[i][3]);
        float4 c1 = make_float4(acc[i][4], acc[i][5], acc[i][6], acc[i][7]);
        *(float4*)(C + (size_t)r * N + n0 + tx*4)      = c0;
        *(float4*)(C + (size_t)r * N + n0 + 64 + tx*4) = c1;
    }
}

// ================== rope + scatter to transposed head layout ===============
// src: [b,s,E] (E = 16 heads x 64), dst: [b,h,128,S]; rope half-rotation, D=64
__global__ void rope_scatter(const float* __restrict__ src, float* __restrict__ dst)
{
    int idx = blockIdx.x * blockDim.x + threadIdx.x;   // CB*CH*32*CS = 2^21
    int s  = idx & (CS - 1);
    int i  = (idx >> 11) & 31;
    int hb = idx >> 16;               // b*16 + h
    int h  = hb & 15, b = hb >> 4;
    const float* p = src + (size_t)(b*CS + s) * CE + h*CHD;
    float x1 = p[i];
    float x2 = p[i + 32];
    // inv_freq = 10000^(-i/32) ; log2(10000)/32 = 0.41524101186109
    float ang = (float)s * exp2f(-(float)i * 0.41524101186109f);
    float sn, cs;
    sincosf(ang, &sn, &cs);
    float* q = dst + (size_t)(hb * CDQK) * CS;
    q[(size_t)(i)      * CS + s] = x1 * cs - x2 * sn;
    q[(size_t)(i + 32) * CS + s] = x2 * cs + x1 * sn;
}

// src: [b,s,E] -> dst[b,h, 64+j, s]   (nope half of q/k)
__global__ void nope_scatter(const float* __restrict__ src, float* __restrict__ dst)
{
    int idx = blockIdx.x * blockDim.x + threadIdx.x;   // CB*CH*64*CS = 2^22
    int s  = idx & (CS - 1);
    int j  = (idx >> 11) & 63;
    int hb = idx >> 17;
    int h  = hb & 15, b = hb >> 4;
    dst[(size_t)(hb*CDQK + 64 + j) * CS + s] =
        src[(size_t)(b*CS + s) * CE + h*CHD + j];
}

// src: [b,s,E] -> dst[b,h,s,64]   (v), float4
__global__ void v_scatter(const float* __restrict__ src, float* __restrict__ dst)
{
    int idx = blockIdx.x * blockDim.x + threadIdx.x;   // CB*CH*CS*16 = 2^20
    int d4 = (idx & 15) * 4;
    int s  = (idx >> 4) & (CS - 1);
    int hb = idx >> 15;
    int h  = hb & 15, b = hb >> 4;
    *(float4*)(dst + (size_t)(hb*CS + s) * CHD + d4) =
        *(const float4*)(src + (size_t)(b*CS + s) * CE + h*CHD + d4);
}

// =================== causal flash attention ================================
// Qt,Kt: [b,h,128,S] (d-major); V: [b,h,S,64]; Y out: [b,s,E]
#define LQ 68   // padded smem row for 64-wide tiles

__global__ __launch_bounds__(256) void flash_attn(
    const float* __restrict__ Qt, const float* __restrict__ Kt,
    const float* __restrict__ V,  float* __restrict__ Y)
{
    extern __shared__ float sm[];
    float* Qs = sm;                       // [128][LQ]  Qs[d][r]
    float* Ks = Qs + CDQK * LQ;           // [128][LQ]  Ks[d][c]
    float* Vs = Ks + CDQK * LQ;           // [64][LQ]   Vs[k][c]
    float* Ps = Vs + 64 * LQ;             // [64][LQ]   Ps[r][k]

    const int tid = threadIdx.x;
    const int tx  = tid & 15, ty = tid >> 4;
    const int bh  = blockIdx.y;
    const int qb  = blockIdx.x;
    const int q0  = qb * 64;

    const float* Qg = Qt + (size_t)bh * CDQK * CS;
    const float* Kg = Kt + (size_t)bh * CDQK * CS;
    const float* Vg = V  + (size_t)bh * CS * CHD;

    for (int i = tid; i < CDQK * 16; i += 256) {
        int d = i >> 4, r4 = (i & 15) * 4;
        *(float4*)&Qs[d*LQ + r4] = *(const float4*)(Qg + (size_t)d*CS + q0 + r4);
    }

    float mI[4], lI[4], O[4][4];
#pragma unroll
    for (int i = 0; i < 4; i++) {
        mI[i] = -1e30f; lI[i] = 0.f;
#pragma unroll
        for (int j = 0; j < 4; j++) O[i][j] = 0.f;
    }
    const float scale = 0.08838834764831845f;   // 1/sqrt(128)

    for (int kb = 0; kb <= qb; kb++) {
        const int k0 = kb * 64;
        __syncthreads();
        for (int i = tid; i < CDQK * 16; i += 256) {
            int d = i >> 4, r4 = (i & 15) * 4;
            *(float4*)&Ks[d*LQ + r4] = *(const float4*)(Kg + (size_t)d*CS + k0 + r4);
        }
        for (int i = tid; i < 64 * 16; i += 256) {
            int r = i >> 4, d4 = (i & 15) * 4;
            *(float4*)&Vs[r*LQ + d4] = *(const float4*)(Vg + (size_t)(k0 + r)*CHD + d4);
        }
        __syncthreads();

        float sc[4][4];
#pragma unroll
        for (int i = 0; i < 4; i++)
#pragma unroll
            for (int j = 0; j < 4; j++) sc[i][j] = 0.f;

#pragma unroll 4
        for (int d = 0; d < CDQK; d++) {
            float4 a  = *(const float4*)&Qs[d*LQ + ty*4];
            float4 bv = *(const float4*)&Ks[d*LQ + tx*4];
            sc[0][0] += a.x*bv.x; sc[0][1] += a.x*bv.y; sc[0][2] += a.x*bv.z; sc[0][3] += a.x*bv.w;
            sc[1][0] += a.y*bv.x; sc[1][1] += a.y*bv.y; sc[1][2] += a.y*bv.z; sc[1][3] += a.y*bv.w;
            sc[2][0] += a.z*bv.x; sc[2][1] += a.z*bv.y; sc[2][2] += a.z*bv.z; sc[2][3] += a.z*bv.w;
            sc[3][0] += a.w*bv.x; sc[3][1] += a.w*bv.y; sc[3][2] += a.w*bv.z; sc[3][3] += a.w*bv.w;
        }

        if (kb == qb) {
#pragma unroll
            for (int i = 0; i < 4; i++)
#pragma unroll
                for (int j = 0; j < 4; j++) {
                    if (k0 + tx*4 + j > q0 + ty*4 + i) sc[i][j] = -1e30f;
                    else                               sc[i][j] *= scale;
                }
        } else {
#pragma unroll
            for (int i = 0; i < 4; i++)
#pragma unroll
                for (int j = 0; j < 4; j++) sc[i][j] *= scale;
        }

#pragma unroll
        for (int i = 0; i < 4; i++) {
            float mx = fmaxf(fmaxf(sc[i][0], sc[i][1]), fmaxf(sc[i][2], sc[i][3]));
#pragma unroll
            for (int o = 8; o; o >>= 1) mx = fmaxf(mx, __shfl_xor_sync(0xffffffffu, mx, o));
            float mn = fmaxf(mI[i], mx);
            float alpha = __expf(mI[i] - mn);
            mI[i] = mn;
            float p0 = __expf(sc[i][0] - mn);
            float p1 = __expf(sc[i][1] - mn);
            float p2 = __expf(sc[i][2] - mn);
            float p3 = __expf(sc[i][3] - mn);
            float rs = p0 + p1 + p2 + p3;
#pragma unroll
            for (int o = 8; o; o >>= 1) rs += __shfl_xor_sync(0xffffffffu, rs, o);
            lI[i] = lI[i] * alpha + rs;
            O[i][0] *= alpha; O[i][1] *= alpha; O[i][2] *= alpha; O[i][3] *= alpha;
            *(float4*)&Ps[(ty*4 + i)*LQ + tx*4] = make_float4(p0, p1, p2, p3);
        }
        __syncthreads();

#pragma unroll 4
        for (int k = 0; k < 64; k++) {
            float4 vv = *(const float4*)&Vs[k*LQ + tx*4];
            float p0 = Ps[(ty*4 + 0)*LQ + k];
            float p1 = Ps[(ty*4 + 1)*LQ + k];
            float p2 = Ps[(ty*4 + 2)*LQ + k];
            float p3 = Ps[(ty*4 + 3)*LQ + k];
            O[0][0] += p0*vv.x; O[0][1] += p0*vv.y; O[0][2] += p0*vv.z; O[0][3] += p0*vv.w;
            O[1][0] += p1*vv.x; O[1][1] += p1*vv.y; O[1][2] += p1*vv.z; O[1][3] += p1*vv.w;
            O[2][0] += p2*vv.x; O[2][1] += p2*vv.y; O[2][2] += p2*vv.z; O[2][3] += p2*vv.w;
            O[3][0] += p3*vv.x; O[3][1] += p3*vv.y; O[3][2] += p3*vv.z; O[3][3] += p3*vv.w;
        }
    }

    const int b = bh >> 4, h = bh & 15;
#pragma unroll
    for (int i = 0; i < 4; i++) {
        float inv = 1.f / lI[i];
        int srow = q0 + ty*4 + i;
        *(float4*)(Y + (size_t)(b*CS + srow) * CE + h*CHD + tx*4) =
            make_float4(O[i][0]*inv, O[i][1]*inv, O[i][2]*inv, O[i][3]*inv);
    }
}

// ============================== launcher ===================================
extern "C" void kernel_launch(void* const* d_in, const int* in_sizes, int n_in,
                              void* d_out, int out_size)
{
    const float* x        = (const float*)d_in[0];
    const float* wq_down  = (const float*)d_in[1];
    const float* wk_rope  = (const float*)d_in[2];
    const float* wkv_down = (const float*)d_in[3];
    const float* wq_rope  = (const float*)d_in[4];
    const float* wq_up    = (const float*)d_in[5];
    const float* wk_up    = (const float*)d_in[6];
    const float* wv_up    = (const float*)d_in[7];
    const float* wo       = (const float*)d_in[8];
    float* out = (float*)d_out;

    float *qlat, *krlat, *kv, *tmp, *Qt, *Kt, *Vv, *Y;
    cudaGetSymbolAddress((void**)&qlat,  g_qlat);
    cudaGetSymbolAddress((void**)&krlat, g_krlat);
    cudaGetSymbolAddress((void**)&kv,    g_kv);
    cudaGetSymbolAddress((void**)&tmp,   g_tmp);
    cudaGetSymbolAddress((void**)&Qt,    g_Qt);
    cudaGetSymbolAddress((void**)&Kt,    g_Kt);
    cudaGetSymbolAddress((void**)&Vv,    g_V);
    cudaGetSymbolAddress((void**)&Y,     g_Y);

    const int smemFlash = (CDQK*LQ*2 + 64*LQ*2) * (int)sizeof(float);  // 104448
    cudaFuncSetAttribute(flash_attn, cudaFuncAttributeMaxDynamicSharedMemorySize, smemFlash);

    dim3 blk(256);
    // down projections: (4096 x 256) = x(4096x1024) @ W(256x1024)^T
    sgemm_nt<<<dim3(2, 32), blk>>>(x, wq_down,  qlat,  MTOK, CR, CE);
    sgemm_nt<<<dim3(2, 32), blk>>>(x, wk_rope,  krlat, MTOK, CR, CE);
    sgemm_nt<<<dim3(2, 32), blk>>>(x, wkv_down, kv,    MTOK, CR, CE);

    // q rope: q_lat @ wq_rope^T -> rope -> Qt[:, :, 0:64, :]
    sgemm_nt<<<dim3(8, 32), blk>>>(qlat, wq_rope, tmp, MTOK, CE, CR);
    rope_scatter<<<8192, 256>>>(tmp, Qt);
    // q nope: q_lat @ wq_up^T -> Qt[:, :, 64:128, :]
    sgemm_nt<<<dim3(8, 32), blk>>>(qlat, wq_up, tmp, MTOK, CE, CR);
    nope_scatter<<<16384, 256>>>(tmp, Qt);
    // k rope: (x @ wk_rope^T) @ wk_up^T -> rope -> Kt[:, :, 0:64, :]
    sgemm_nt<<<dim3(8, 32), blk>>>(krlat, wk_up, tmp, MTOK, CE, CR);
    rope_scatter<<<8192, 256>>>(tmp, Kt);
    // k nope: kv @ wk_up^T -> Kt[:, :, 64:128, :]
    sgemm_nt<<<dim3(8, 32), blk>>>(kv, wk_up, tmp, MTOK, CE, CR);
    nope_scatter<<<16384, 256>>>(tmp, Kt);
    // v: kv @ wv_up^T -> V[b,h,s,64]
    sgemm_nt<<<dim3(8, 32), blk>>>(kv, wv_up, tmp, MTOK, CE, CR);
    v_scatter<<<4096, 256>>>(tmp, Vv);

    // causal flash attention -> Y[b,s,E]
    flash_attn<<<dim3(CS/64, CB*CH), blk, smemFlash>>>(Qt, Kt, Vv, Y);

    // output projection: Y @ wo^T -> out
    sgemm_nt<<<dim3(8, 32), blk>>>(Y, wo, out, MTOK, CE, CE);
}

// round 3
// speedup vs baseline: 1.2905x; 1.2905x over previous
#include <cuda_runtime.h>
#include <cuda_bf16.h>
#include <cstdint>
#include <math.h>

#define CB   2
#define CS   2048
#define CE   1024
#define CR   256
#define CH   16
#define CHD  64
#define CDQK 128
#define MTOK (CB*CS)   // 4096

// ---------------- scratch (no allocation allowed -> __device__ globals) ----
__device__ float g_qlat [MTOK*CR];
__device__ float g_krlat[MTOK*CR];
__device__ float g_kv   [MTOK*CR];
__device__ float g_tmp  [MTOK*CE];
__device__ float g_Qt   [CB*CH*CDQK*CS];   // [b,h,d,s]
__device__ float g_Kt   [CB*CH*CDQK*CS];   // [b,h,d,s]
__device__ float g_V    [CB*CH*CS*CHD];    // [b,h,s,d]
__device__ float g_Y    [MTOK*CE];

// bf16 hi/lo split copies (activations + weights)
__device__ __nv_bfloat16 g_xh [MTOK*CE],  g_xl [MTOK*CE];
__device__ __nv_bfloat16 g_qlh[MTOK*CR],  g_qll[MTOK*CR];
__device__ __nv_bfloat16 g_krh[MTOK*CR],  g_krl[MTOK*CR];
__device__ __nv_bfloat16 g_kvh[MTOK*CR],  g_kvl[MTOK*CR];
__device__ __nv_bfloat16 g_Yh [MTOK*CE],  g_Yl [MTOK*CE];
__device__ __nv_bfloat16 g_w0h[CR*CE], g_w0l[CR*CE];   // wq_down
__device__ __nv_bfloat16 g_w1h[CR*CE], g_w1l[CR*CE];   // wk_rope
__device__ __nv_bfloat16 g_w2h[CR*CE], g_w2l[CR*CE];   // wkv_down
__device__ __nv_bfloat16 g_w3h[CE*CR], g_w3l[CE*CR];   // wq_rope
__device__ __nv_bfloat16 g_w4h[CE*CR], g_w4l[CE*CR];   // wq_up
__device__ __nv_bfloat16 g_w5h[CE*CR], g_w5l[CE*CR];   // wk_up
__device__ __nv_bfloat16 g_w6h[CE*CR], g_w6l[CE*CR];   // wv_up
__device__ __nv_bfloat16 g_w7h[CE*CE], g_w7l[CE*CE];   // wo

// ===================== generic helpers =====================================
__device__ __forceinline__ uint32_t smem_to_u32(const void* p) {
    uint32_t a;
    asm("{ .reg .u64 t; cvta.to.shared.u64 t, %1; cvt.u32.u64 %0, t; }" : "=r"(a) : "l"(p));
    return a;
}

// portable tensor-core primitives (sm_80+, legal on plain sm_103 target)
#define LDSM_X4(r0,r1,r2,r3, addr) \
    asm volatile("ldmatrix.sync.aligned.m8n8.x4.shared.b16 {%0,%1,%2,%3}, [%4];" \
        : "=r"(r0), "=r"(r1), "=r"(r2), "=r"(r3) : "r"(addr))

#define MMA16816(c, a, b) \
    asm volatile("mma.sync.aligned.m16n8k16.row.col.f32.bf16.bf16.f32 " \
        "{%0,%1,%2,%3}, {%4,%5,%6,%7}, {%8,%9}, {%0,%1,%2,%3};" \
        : "+f"((c)[0]), "+f"((c)[1]), "+f"((c)[2]), "+f"((c)[3]) \
        : "r"((a)[0]), "r"((a)[1]), "r"((a)[2]), "r"((a)[3]), "r"((b)[0]), "r"((b)[1]))

// ===================== tcgen05 helpers (only expanded under sm_103a) =======
__device__ __forceinline__ uint32_t elect_one_pred() {
    uint32_t pred;
    asm volatile("{\n\t.reg .pred p;\n\telect.sync _|p, 0xFFFFFFFF;\n\tselp.b32 %0, 1, 0, p;\n\t}" : "=r"(pred));
    return pred;
}
#define TCGEN05_ALLOC(smem_addr, nCols) \
    asm volatile("tcgen05.alloc.cta_group::1.sync.aligned.shared::cta.b32 [%0], %1;" \
        :: "r"((uint32_t)(smem_addr)), "r"((uint32_t)(nCols)) : "memory")
#define TCGEN05_DEALLOC(tmem_addr, nCols) \
    asm volatile("tcgen05.dealloc.cta_group::1.sync.aligned.b32 %0, %1;" :: "r"(tmem_addr), "r"((uint32_t)(nCols)))
#define TCGEN05_COMMIT(mbar) \
    asm volatile("tcgen05.commit.cta_group::1.mbarrier::arrive::one.shared::cluster.b64 [%0];" \
        :: "r"((uint32_t)(mbar)) : "memory")
#define TCGEN05_WAIT_LD() asm volatile("tcgen05.wait::ld.sync.aligned;" ::: "memory")
#define TCGEN05_FENCE_BEFORE() asm volatile("tcgen05.fence::before_thread_sync;" ::: "memory")
#define TCGEN05_FENCE_AFTER()  asm volatile("tcgen05.fence::after_thread_sync;" ::: "memory")
#define FENCE_PROXY_ASYNC_SHARED_CTA() asm volatile("fence.proxy.async.shared::cta;" ::: "memory")
#define MBARRIER_INIT(mbar, cnt) \
    asm volatile("mbarrier.init.shared.b64 [%0], %1;" :: "r"((uint32_t)(mbar)), "r"((uint32_t)(cnt)) : "memory")
#define MBARRIER_INVAL(mbar) \
    asm volatile("mbarrier.inval.shared.b64 [%0];" :: "r"((uint32_t)(mbar)) : "memory")
#define MBARRIER_WAIT_PARITY(mbar, par) do { \
    uint32_t _m = (uint32_t)(mbar); uint32_t _p = (uint32_t)(par); uint32_t _done; \
    asm volatile("{\n\t.reg .pred p;\n\tmbarrier.try_wait.parity.acquire.cta.shared::cta.b64 p, [%1], %2;\n\tselp.b32 %0, 1, 0, p;\n\t}" \
        : "=r"(_done) : "r"(_m), "r"(_p) : "memory"); \
    if (!_done) { \
        asm volatile("{\n\t.reg .pred P1;\n\tWL_%=:\n\tmbarrier.try_wait.parity.acquire.cta.shared::cta.b64 P1, [%0], %1, 0x989680;\n\t@P1 bra.uni WD_%=;\n\tbra.uni WL_%=;\n\tWD_%=:\n\t}" \
            :: "r"(_m), "r"(_p) : "memory"); \
    } } while (0)
#define TCGEN05_LD_32X32B_X32(r, tmem_addr) \
    asm volatile("tcgen05.ld.sync.aligned.32x32b.x32.b32 " \
        "{%0, %1, %2, %3, %4, %5, %6, %7, %8, %9, %10, %11, %12, %13, %14, %15, " \
        " %16, %17, %18, %19, %20, %21, %22, %23, %24, %25, %26, %27, %28, %29, %30, %31}, [%32];" \
        : "=r"((r)[0]),  "=r"((r)[1]),  "=r"((r)[2]),  "=r"((r)[3]), \
          "=r"((r)[4]),  "=r"((r)[5]),  "=r"((r)[6]),  "=r"((r)[7]), \
          "=r"((r)[8]),  "=r"((r)[9]),  "=r"((r)[10]), "=r"((r)[11]), \
          "=r"((r)[12]), "=r"((r)[13]), "=r"((r)[14]), "=r"((r)[15]), \
          "=r"((r)[16]), "=r"((r)[17]), "=r"((r)[18]), "=r"((r)[19]), \
          "=r"((r)[20]), "=r"((r)[21]), "=r"((r)[22]), "=r"((r)[23]), \
          "=r"((r)[24]), "=r"((r)[25]), "=r"((r)[26]), "=r"((r)[27]), \
          "=r"((r)[28]), "=r"((r)[29]), "=r"((r)[30]), "=r"((r)[31]) \
        : "r"(tmem_addr))

static constexpr uint64_t SMEM_DESC_BASE_SW128 =
    (uint64_t(2)  << 61) | (uint64_t(1) << 46) | (uint64_t(64) << 32) | (uint64_t(1) << 16);
#define MAKE_SMEM_DESC(base_addr) (SMEM_DESC_BASE_SW128 | ((uint64_t)((base_addr) >> 4) & 0x3FFF))
#define SMEM_SWIZZLE_128B(off) ((off) ^ (((off) >> 3) & 0x70))
// idesc kind::f16: dtype=F32, atype=BF16, btype=BF16, N=128, M=128
#define GEMM_IDESC ((1u<<4) | (1u<<7) | (1u<<10) | ((128u/8)<<17) | ((128u/16)<<24))

#if defined(__CUDA_ARCH__) && defined(__CUDA_ARCH_FEAT_SM103_ALL)
__device__ __forceinline__ void mma_f16_ss(uint32_t d, uint64_t ad, uint64_t bd,
                                           uint32_t idesc, uint32_t en) {
    asm volatile(
        "{\n\t.reg .pred p;\n\tsetp.ne.u32 p, %5, 0;\n\t"
        "tcgen05.mma.cta_group::1.kind::f16 [%0], %1, %2, %3, {%4, %4, %4, %4}, p;\n\t}"
        :: "r"(d), "l"(ad), "l"(bd), "r"(idesc), "r"(0u), "r"(en) : "memory");
}
#endif

// ===================== split-fp32 convert ==================================
__global__ void cvt_split(const float* __restrict__ src,
                          __nv_bfloat16* __restrict__ hi, __nv_bfloat16* __restrict__ lo, int n)
{
    int i = blockIdx.x * blockDim.x + threadIdx.x;
    if (i < n) {
        float v = src[i];
        __nv_bfloat16 h = __float2bfloat16(v);
        hi[i] = h;
        lo[i] = __float2bfloat16(v - __bfloat162float(h));
    }
}

// ============= tensor-core split-bf16 GEMM NT: C = A * W^T =================
// A (hi/lo) [M,K] bf16 row-major, W (hi/lo) [N,K] bf16 row-major, C [M,N] fp32
// CTA tile 128x128, 256 threads. Two code paths selected at compile time.
#define OFF_PTR  0
#define OFF_MBAR 8
#define OFF_AH   1024
#define OFF_AL   (1024 + 16384)
#define OFF_BH   (1024 + 2*16384)
#define OFF_BL   (1024 + 3*16384)
#define GEMM_SMEM (1024 + 4*16384)   // 66560 (covers both paths)

// mma.sync path smem layout (K-chunk 32, 64B rows, xor-swizzled)
#define MS_AH 0
#define MS_AL 8192
#define MS_BH 16384
#define MS_BL 24576
__device__ __forceinline__ uint32_t msw(int row, int c) {
    return (uint32_t)(row * 64 + ((c ^ ((row >> 1) & 3)) << 4));
}

__global__ __launch_bounds__(256) void gemm_bb(
    const __nv_bfloat16* __restrict__ Ah, const __nv_bfloat16* __restrict__ Al,
    const __nv_bfloat16* __restrict__ Bh, const __nv_bfloat16* __restrict__ Bl,
    float* __restrict__ C, int M, int N, int K)
{
    extern __shared__ char smem[];
    const int tid = threadIdx.x, wid = tid >> 5, lid = tid & 31;
    const int m0 = blockIdx.y * 128, n0 = blockIdx.x * 128;
    uint32_t sb = smem_to_u32(smem);

#if defined(__CUDA_ARCH__) && defined(__CUDA_ARCH_FEAT_SM103_ALL)
    // ---------------- tcgen05 path (sm_103a) -------------------------------
    if (wid == 0) {
        TCGEN05_ALLOC(sb + OFF_PTR, 128);
        if (elect_one_pred()) MBARRIER_INIT(sb + OFF_MBAR, 1);
    }
    __syncthreads();
    uint32_t tmem;
    asm volatile("ld.shared.b32 %0, [%1];" : "=r"(tmem) : "r"(sb + OFF_PTR));

    const int rbase = tid >> 3;        // 0..31
    const int cc    = tid & 7;         // 16B chunk within 128B row
    const uint64_t dAh = MAKE_SMEM_DESC(sb + OFF_AH);
    const uint64_t dAl = MAKE_SMEM_DESC(sb + OFF_AL);
    const uint64_t dBh = MAKE_SMEM_DESC(sb + OFF_BH);
    const uint64_t dBl = MAKE_SMEM_DESC(sb + OFF_BL);

    int ph = 0;
    for (int k0 = 0; k0 < K; k0 += 64) {
#pragma unroll
        for (int it = 0; it < 4; it++) {
            int row = it * 32 + rbase;
            uint32_t so = SMEM_SWIZZLE_128B((uint32_t)(row * 128 + cc * 16));
            size_t ga = (size_t)(m0 + row) * K + k0 + cc * 8;
            size_t gb = (size_t)(n0 + row) * K + k0 + cc * 8;
            *(uint4*)(smem + OFF_AH + so) = *(const uint4*)(Ah + ga);
            *(uint4*)(smem + OFF_AL + so) = *(const uint4*)(Al + ga);
            *(uint4*)(smem + OFF_BH + so) = *(const uint4*)(Bh + gb);
            *(uint4*)(smem + OFF_BL + so) = *(const uint4*)(Bl + gb);
        }
        FENCE_PROXY_ASYNC_SHARED_CTA();
        __syncthreads();

        if (wid == 0 && elect_one_pred()) {
#pragma unroll
            for (int kk = 0; kk < 4; kk++)
                mma_f16_ss(tmem, dAh + kk*2, dBh + kk*2, GEMM_IDESC, (k0 > 0) | (kk > 0));
#pragma unroll
            for (int kk = 0; kk < 4; kk++)
                mma_f16_ss(tmem, dAh + kk*2, dBl + kk*2, GEMM_IDESC, 1u);
#pragma unroll
            for (int kk = 0; kk < 4; kk++)
                mma_f16_ss(tmem, dAl + kk*2, dBh + kk*2, GEMM_IDESC, 1u);
            TCGEN05_COMMIT(sb + OFF_MBAR);
        }
        MBARRIER_WAIT_PARITY(sb + OFF_MBAR, ph);
        ph ^= 1;
        __syncthreads();
    }

    TCGEN05_FENCE_AFTER();
    const int mrow  = m0 + (wid & 3) * 32 + lid;
    const int cbase = (wid >> 2) * 64;
#pragma unroll
    for (int cof = 0; cof < 64; cof += 32) {
        uint32_t dr[32];
        TCGEN05_LD_32X32B_X32(dr, tmem + cbase + cof);
        TCGEN05_WAIT_LD();
        float* cp = C + (size_t)mrow * N + n0 + cbase + cof;
#pragma unroll
        for (int j = 0; j < 32; j += 4)
            *(float4*)(cp + j) = make_float4(__uint_as_float(dr[j]),   __uint_as_float(dr[j+1]),
                                             __uint_as_float(dr[j+2]), __uint_as_float(dr[j+3]));
    }
    TCGEN05_FENCE_BEFORE();
    __syncthreads();
    if (wid == 0) {
        if (elect_one_pred()) MBARRIER_INVAL(sb + OFF_MBAR);
        TCGEN05_DEALLOC(tmem, 128);
    }
#else
    // ---------------- mma.sync path (portable sm_80+) ----------------------
    // 8 warps: mw = wid&3 (M, 32 rows each), nw = wid>>2 (N, 64 cols each)
    const int mw = wid & 3, nw = wid >> 2;

    // ldmatrix per-lane addressing helpers
    const int a_tr = (lid & 7) + ((lid >> 3) & 1) * 8;  // row within m16
    const int a_kq = lid >> 4;                          // k-quad 0/1
    const int b_tr = (lid & 7) + (lid >> 4) * 8;        // row within n16
    const int b_kq = (lid >> 3) & 1;

    float acc[2][8][4];
#pragma unroll
    for (int i = 0; i < 2; i++)
#pragma unroll
        for (int j = 0; j < 8; j++)
#pragma unroll
            for (int q = 0; q < 4; q++) acc[i][j][q] = 0.f;

    // global prefetch: per array, 2 iters; row = it*64 + (tid>>2), chunk = tid&3
    const int prow = tid >> 2, pc = tid & 3;
    uint4 ra[2], rl[2], rb[2], rm[2];
#pragma unroll
    for (int it = 0; it < 2; it++) {
        int row = it * 64 + prow;
        size_t ga = (size_t)(m0 + row) * K + pc * 8;
        size_t gb = (size_t)(n0 + row) * K + pc * 8;
        ra[it] = *(const uint4*)(Ah + ga);
        rl[it] = *(const uint4*)(Al + ga);
        rb[it] = *(const uint4*)(Bh + gb);
        rm[it] = *(const uint4*)(Bl + gb);
    }

    for (int k0 = 0; k0 < K; k0 += 32) {
        __syncthreads();
#pragma unroll
        for (int it = 0; it < 2; it++) {
            int row = it * 64 + prow;
            uint32_t so = msw(row, pc);
            *(uint4*)(smem + MS_AH + so) = ra[it];
            *(uint4*)(smem + MS_AL + so) = rl[it];
            *(uint4*)(smem + MS_BH + so) = rb[it];
            *(uint4*)(smem + MS_BL + so) = rm[it];
        }
        __syncthreads();
        if (k0 + 32 < K) {
#pragma unroll
            for (int it = 0; it < 2; it++) {
                int row = it * 64 + prow;
                size_t ga = (size_t)(m0 + row) * K + k0 + 32 + pc * 8;
                size_t gb = (size_t)(n0 + row) * K + k0 + 32 + pc * 8;
                ra[it] = *(const uint4*)(Ah + ga);
                rl[it] = *(const uint4*)(Al + ga);
                rb[it] = *(const uint4*)(Bh + gb);
                rm[it] = *(const uint4*)(Bl + gb);
            }
        }

#pragma unroll
        for (int ks = 0; ks < 2; ks++) {
            uint32_t ah[2][4], al[2][4], bh[8][2], bl[8][2];
#pragma unroll
            for (int ma = 0; ma < 2; ma++) {
                int row = mw * 32 + ma * 16 + a_tr;
                int c = ks * 2 + a_kq;
                uint32_t ad = sb + MS_AH + msw(row, c);
                LDSM_X4(ah[ma][0], ah[ma][1], ah[ma][2], ah[ma][3], ad);
                uint32_t ad2 = sb + MS_AL + msw(row, c);
                LDSM_X4(al[ma][0], al[ma][1], al[ma][2], al[ma][3], ad2);
            }
#pragma unroll
            for (int nb = 0; nb < 4; nb++) {
                int row = nw * 64 + nb * 16 + b_tr;
                int c = ks * 2 + b_kq;
                uint32_t bd = sb + MS_BH + msw(row, c);
                LDSM_X4(bh[nb*2][0], bh[nb*2][1], bh[nb*2+1][0], bh[nb*2+1][1], bd);
                uint32_t bd2 = sb + MS_BL + msw(row, c);
                LDSM_X4(bl[nb*2][0], bl[nb*2][1], bl[nb*2+1][0], bl[nb*2+1][1], bd2);
            }
#pragma unroll
            for (int ma = 0; ma < 2; ma++)
#pragma unroll
                for (int na = 0; na < 8; na++) {
                    MMA16816(acc[ma][na], ah[ma], bh[na]);
                    MMA16816(acc[ma][na], ah[ma], bl[na]);
                    MMA16816(acc[ma][na], al[ma], bh[na]);
                }
        }
    }

    // epilogue: thread (g = lid>>2, t = lid&3)
    const int g = lid >> 2, t4 = lid & 3;
#pragma unroll
    for (int ma = 0; ma < 2; ma++) {
        int row0 = m0 + mw * 32 + ma * 16 + g;
#pragma unroll
        for (int na = 0; na < 8; na++) {
            int col = n0 + nw * 64 + na * 8 + t4 * 2;
            *(float2*)(C + (size_t)row0 * N + col) =
                make_float2(acc[ma][na][0], acc[ma][na][1]);
            *(float2*)(C + (size_t)(row0 + 8) * N + col) =
                make_float2(acc[ma][na][2], acc[ma][na][3]);
        }
    }
#endif
}

// ================== rope + scatter to transposed head layout ===============
__global__ void rope_scatter(const float* __restrict__ src, float* __restrict__ dst)
{
    int idx = blockIdx.x * blockDim.x + threadIdx.x;   // CB*CH*32*CS = 2^21
    int s  = idx & (CS - 1);
    int i  = (idx >> 11) & 31;
    int hb = idx >> 16;
    int h  = hb & 15, b = hb >> 4;
    const float* p = src + (size_t)(b*CS + s) * CE + h*CHD;
    float x1 = p[i];
    float x2 = p[i + 32];
    float ang = (float)s * exp2f(-(float)i * 0.41524101186109f);
    float sn, cs;
    sincosf(ang, &sn, &cs);
    float* q = dst + (size_t)(hb * CDQK) * CS;
    q[(size_t)(i)      * CS + s] = x1 * cs - x2 * sn;
    q[(size_t)(i + 32) * CS + s] = x2 * cs + x1 * sn;
}

__global__ void nope_scatter(const float* __restrict__ src, float* __restrict__ dst)
{
    int idx = blockIdx.x * blockDim.x + threadIdx.x;   // 2^22
    int s  = idx & (CS - 1);
    int j  = (idx >> 11) & 63;
    int hb = idx >> 17;
    int h  = hb & 15, b = hb >> 4;
    dst[(size_t)(hb*CDQK + 64 + j) * CS + s] =
        src[(size_t)(b*CS + s) * CE + h*CHD + j];
}

__global__ void v_scatter(const float* __restrict__ src, float* __restrict__ dst)
{
    int idx = blockIdx.x * blockDim.x + threadIdx.x;   // 2^20
    int d4 = (idx & 15) * 4;
    int s  = (idx >> 4) & (CS - 1);
    int hb = idx >> 15;
    int h  = hb & 15, b = hb >> 4;
    *(float4*)(dst + (size_t)(hb*CS + s) * CHD + d4) =
        *(const float4*)(src + (size_t)(b*CS + s) * CE + h*CHD + d4);
}

// =================== causal flash attention (fp32) =========================
#define LQ 68

__global__ __launch_bounds__(256) void flash_attn(
    const float* __restrict__ Qt, const float* __restrict__ Kt,
    const float* __restrict__ V,  float* __restrict__ Y)
{
    extern __shared__ float sm[];
    float* Qs = sm;
    float* Ks = Qs + CDQK * LQ;
    float* Vs = Ks + CDQK * LQ;
    float* Ps = Vs + 64 * LQ;

    const int tid = threadIdx.x;
    const int tx  = tid & 15, ty = tid >> 4;
    const int bh  = blockIdx.y;
    const int qb  = blockIdx.x;
    const int q0  = qb * 64;

    const float* Qg = Qt + (size_t)bh * CDQK * CS;
    const float* Kg = Kt + (size_t)bh * CDQK * CS;
    const float* Vg = V  + (size_t)bh * CS * CHD;

    for (int i = tid; i < CDQK * 16; i += 256) {
        int d = i >> 4, r4 = (i & 15) * 4;
        *(float4*)&Qs[d*LQ + r4] = *(const float4*)(Qg + (size_t)d*CS + q0 + r4);
    }

    float mI[4], lI[4], O[4][4];
#pragma unroll
    for (int i = 0; i < 4; i++) {
        mI[i] = -1e30f; lI[i] = 0.f;
#pragma unroll
        for (int j = 0; j < 4; j++) O[i][j] = 0.f;
    }
    const float scale = 0.08838834764831845f;

    for (int kb = 0; kb <= qb; kb++) {
        const int k0 = kb * 64;
        __syncthreads();
        for (int i = tid; i < CDQK * 16; i += 256) {
            int d = i >> 4, r4 = (i & 15) * 4;
            *(float4*)&Ks[d*LQ + r4] = *(const float4*)(Kg + (size_t)d*CS + k0 + r4);
        }
        for (int i = tid; i < 64 * 16; i += 256) {
            int r = i >> 4, d4 = (i & 15) * 4;
            *(float4*)&Vs[r*LQ + d4] = *(const float4*)(Vg + (size_t)(k0 + r)*CHD + d4);
        }
        __syncthreads();

        float sc[4][4];
#pragma unroll
        for (int i = 0; i < 4; i++)
#pragma unroll
            for (int j = 0; j < 4; j++) sc[i][j] = 0.f;

#pragma unroll 4
        for (int d = 0; d < CDQK; d++) {
            float4 a  = *(const float4*)&Qs[d*LQ + ty*4];
            float4 bv = *(const float4*)&Ks[d*LQ + tx*4];
            sc[0][0] += a.x*bv.x; sc[0][1] += a.x*bv.y; sc[0][2] += a.x*bv.z; sc[0][3] += a.x*bv.w;
            sc[1][0] += a.y*bv.x; sc[1][1] += a.y*bv.y; sc[1][2] += a.y*bv.z; sc[1][3] += a.y*bv.w;
            sc[2][0] += a.z*bv.x; sc[2][1] += a.z*bv.y; sc[2][2] += a.z*bv.z; sc[2][3] += a.z*bv.w;
            sc[3][0] += a.w*bv.x; sc[3][1] += a.w*bv.y; sc[3][2] += a.w*bv.z; sc[3][3] += a.w*bv.w;
        }

        if (kb == qb) {
#pragma unroll
            for (int i = 0; i < 4; i++)
#pragma unroll
                for (int j = 0; j < 4; j++) {
                    if (k0 + tx*4 + j > q0 + ty*4 + i) sc[i][j] = -1e30f;
                    else                               sc[i][j] *= scale;
                }
        } else {
#pragma unroll
            for (int i = 0; i < 4; i++)
#pragma unroll
                for (int j = 0; j < 4; j++) sc[i][j] *= scale;
        }

#pragma unroll
        for (int i = 0; i < 4; i++) {
            float mx = fmaxf(fmaxf(sc[i][0], sc[i][1]), fmaxf(sc[i][2], sc[i][3]));
#pragma unroll
            for (int o = 8; o; o >>= 1) mx = fmaxf(mx, __shfl_xor_sync(0xffffffffu, mx, o));
            float mn = fmaxf(mI[i], mx);
            float alpha = __expf(mI[i] - mn);
            mI[i] = mn;
            float p0 = __expf(sc[i][0] - mn);
            float p1 = __expf(sc[i][1] - mn);
            float p2 = __expf(sc[i][2] - mn);
            float p3 = __expf(sc[i][3] - mn);
            float rs = p0 + p1 + p2 + p3;
#pragma unroll
            for (int o = 8; o; o >>= 1) rs += __shfl_xor_sync(0xffffffffu, rs, o);
            lI[i] = lI[i] * alpha + rs;
            O[i][0] *= alpha; O[i][1] *= alpha; O[i][2] *= alpha; O[i][3] *= alpha;
            *(float4*)&Ps[(ty*4 + i)*LQ + tx*4] = make_float4(p0, p1, p2, p3);
        }
        __syncthreads();

#pragma unroll 4
        for (int k = 0; k < 64; k++) {
            float4 vv = *(const float4*)&Vs[k*LQ + tx*4];
            float p0 = Ps[(ty*4 + 0)*LQ + k];
            float p1 = Ps[(ty*4 + 1)*LQ + k];
            float p2 = Ps[(ty*4 + 2)*LQ + k];
            float p3 = Ps[(ty*4 + 3)*LQ + k];
            O[0][0] += p0*vv.x; O[0][1] += p0*vv.y; O[0][2] += p0*vv.z; O[0][3] += p0*vv.w;
            O[1][0] += p1*vv.x; O[1][1] += p1*vv.y; O[1][2] += p1*vv.z; O[1][3] += p1*vv.w;
            O[2][0] += p2*vv.x; O[2][1] += p2*vv.y; O[2][2] += p2*vv.z; O[2][3] += p2*vv.w;
            O[3][0] += p3*vv.x; O[3][1] += p3*vv.y; O[3][2] += p3*vv.z; O[3][3] += p3*vv.w;
        }
    }

    const int b = bh >> 4, h = bh & 15;
#pragma unroll
    for (int i = 0; i < 4; i++) {
        float inv = 1.f / lI[i];
        int srow = q0 + ty*4 + i;
        *(float4*)(Y + (size_t)(b*CS + srow) * CE + h*CHD + tx*4) =
            make_float4(O[i][0]*inv, O[i][1]*inv, O[i][2]*inv, O[i][3]*inv);
    }
}

// ============================== launcher ===================================
static inline void launch_cvt(const float* s, __nv_bfloat16* h, __nv_bfloat16* l, int n) {
    cvt_split<<<(n + 255) / 256, 256>>>(s, h, l, n);
}

extern "C" void kernel_launch(void* const* d_in, const int* in_sizes, int n_in,
                              void* d_out, int out_size)
{
    const float* x        = (const float*)d_in[0];
    const float* wq_down  = (const float*)d_in[1];
    const float* wk_rope  = (const float*)d_in[2];
    const float* wkv_down = (const float*)d_in[3];
    const float* wq_rope  = (const float*)d_in[4];
    const float* wq_up    = (const float*)d_in[5];
    const float* wk_up    = (const float*)d_in[6];
    const float* wv_up    = (const float*)d_in[7];
    const float* wo       = (const float*)d_in[8];
    float* out = (float*)d_out;

    float *qlat, *krlat, *kv, *tmp, *Qt, *Kt, *Vv, *Y;
    cudaGetSymbolAddress((void**)&qlat,  g_qlat);
    cudaGetSymbolAddress((void**)&krlat, g_krlat);
    cudaGetSymbolAddress((void**)&kv,    g_kv);
    cudaGetSymbolAddress((void**)&tmp,   g_tmp);
    cudaGetSymbolAddress((void**)&Qt,    g_Qt);
    cudaGetSymbolAddress((void**)&Kt,    g_Kt);
    cudaGetSymbolAddress((void**)&Vv,    g_V);
    cudaGetSymbolAddress((void**)&Y,     g_Y);

    __nv_bfloat16 *xh,*xl,*qlh,*qll,*krh,*krl,*kvh,*kvl,*Yh,*Yl;
    __nv_bfloat16 *w0h,*w0l,*w1h,*w1l,*w2h,*w2l,*w3h,*w3l,*w4h,*w4l,*w5h,*w5l,*w6h,*w6l,*w7h,*w7l;
    cudaGetSymbolAddress((void**)&xh,  g_xh);  cudaGetSymbolAddress((void**)&xl,  g_xl);
    cudaGetSymbolAddress((void**)&qlh, g_qlh); cudaGetSymbolAddress((void**)&qll, g_qll);
    cudaGetSymbolAddress((void**)&krh, g_krh); cudaGetSymbolAddress((void**)&krl, g_krl);
    cudaGetSymbolAddress((void**)&kvh, g_kvh); cudaGetSymbolAddress((void**)&kvl, g_kvl);
    cudaGetSymbolAddress((void**)&Yh,  g_Yh);  cudaGetSymbolAddress((void**)&Yl,  g_Yl);
    cudaGetSymbolAddress((void**)&w0h, g_w0h); cudaGetSymbolAddress((void**)&w0l, g_w0l);
    cudaGetSymbolAddress((void**)&w1h, g_w1h); cudaGetSymbolAddress((void**)&w1l, g_w1l);
    cudaGetSymbolAddress((void**)&w2h, g_w2h); cudaGetSymbolAddress((void**)&w2l, g_w2l);
    cudaGetSymbolAddress((void**)&w3h, g_w3h); cudaGetSymbolAddress((void**)&w3l, g_w3l);
    cudaGetSymbolAddress((void**)&w4h, g_w4h); cudaGetSymbolAddress((void**)&w4l, g_w4l);
    cudaGetSymbolAddress((void**)&w5h, g_w5h); cudaGetSymbolAddress((void**)&w5l, g_w5l);
    cudaGetSymbolAddress((void**)&w6h, g_w6h); cudaGetSymbolAddress((void**)&w6l, g_w6l);
    cudaGetSymbolAddress((void**)&w7h, g_w7h); cudaGetSymbolAddress((void**)&w7l, g_w7l);

    const int smemFlash = (CDQK*LQ*2 + 64*LQ*2) * (int)sizeof(float);
    cudaFuncSetAttribute(flash_attn, cudaFuncAttributeMaxDynamicSharedMemorySize, smemFlash);
    cudaFuncSetAttribute(gemm_bb, cudaFuncAttributeMaxDynamicSharedMemorySize, GEMM_SMEM);

    // split conversions: inputs + weights
    launch_cvt(x,        xh,  xl,  MTOK*CE);
    launch_cvt(wq_down,  w0h, w0l, CR*CE);
    launch_cvt(wk_rope,  w1h, w1l, CR*CE);
    launch_cvt(wkv_down, w2h, w2l, CR*CE);
    launch_cvt(wq_rope,  w3h, w3l, CE*CR);
    launch_cvt(wq_up,    w4h, w4l, CE*CR);
    launch_cvt(wk_up,    w5h, w5l, CE*CR);
    launch_cvt(wv_up,    w6h, w6l, CE*CR);
    launch_cvt(wo,       w7h, w7l, CE*CE);

    dim3 blk(256);
    // down projections: [4096,256] = x[4096,1024] @ W[256,1024]^T
    gemm_bb<<<dim3(CR/128, MTOK/128), blk, GEMM_SMEM>>>(xh, xl, w0h, w0l, qlat,  MTOK, CR, CE);
    gemm_bb<<<dim3(CR/128, MTOK/128), blk, GEMM_SMEM>>>(xh, xl, w1h, w1l, krlat, MTOK, CR, CE);
    gemm_bb<<<dim3(CR/128, MTOK/128), blk, GEMM_SMEM>>>(xh, xl, w2h, w2l, kv,    MTOK, CR, CE);
    launch_cvt(qlat,  qlh, qll, MTOK*CR);
    launch_cvt(krlat, krh, krl, MTOK*CR);
    launch_cvt(kv,    kvh, kvl, MTOK*CR);

    // q rope
    gemm_bb<<<dim3(CE/128, MTOK/128), blk, GEMM_SMEM>>>(qlh, qll, w3h, w3l, tmp, MTOK, CE, CR);
    rope_scatter<<<8192, 256>>>(tmp, Qt);
    // q nope
    gemm_bb<<<dim3(CE/128, MTOK/128), blk, GEMM_SMEM>>>(qlh, qll, w4h, w4l, tmp, MTOK, CE, CR);
    nope_scatter<<<16384, 256>>>(tmp, Qt);
    // k rope
    gemm_bb<<<dim3(CE/128, MTOK/128), blk, GEMM_SMEM>>>(krh, krl, w5h, w5l, tmp, MTOK, CE, CR);
    rope_scatter<<<8192, 256>>>(tmp, Kt);
    // k nope
    gemm_bb<<<dim3(CE/128, MTOK/128), blk, GEMM_SMEM>>>(kvh, kvl, w5h, w5l, tmp, MTOK, CE, CR);
    nope_scatter<<<16384, 256>>>(tmp, Kt);
    // v
    gemm_bb<<<dim3(CE/128, MTOK/128), blk, GEMM_SMEM>>>(kvh, kvl, w6h, w6l, tmp, MTOK, CE, CR);
    v_scatter<<<4096, 256>>>(tmp, Vv);

    // causal flash attention -> Y
    flash_attn<<<dim3(CS/64, CB*CH), 256, smemFlash>>>(Qt, Kt, Vv, Y);

    // output projection
    launch_cvt(Y, Yh, Yl, MTOK*CE);
    gemm_bb<<<dim3(CE/128, MTOK/128), blk, GEMM_SMEM>>>(Yh, Yl, w7h, w7l, out, MTOK, CE, CE);
}

// round 5
// speedup vs baseline: 2.2723x; 1.7608x over previous
#include <cuda_runtime.h>
#include <cuda_bf16.h>
#include <cstdint>
#include <math.h>

#define CB   2
#define CS   2048
#define CE   1024
#define CR   256
#define CH   16
#define CHD  64
#define CDQK 128
#define MTOK (CB*CS)   // 4096

// ---------------- scratch (no allocation allowed -> __device__ globals) ----
__device__ float g_qlat [MTOK*CR];
__device__ float g_krlat[MTOK*CR];
__device__ float g_kv   [MTOK*CR];
__device__ float g_tmp  [MTOK*CE];
__device__ float g_Y    [MTOK*CE];

// bf16 hi/lo split copies (activations + weights)
__device__ __nv_bfloat16 g_xh [MTOK*CE],  g_xl [MTOK*CE];
__device__ __nv_bfloat16 g_qlh[MTOK*CR],  g_qll[MTOK*CR];
__device__ __nv_bfloat16 g_krh[MTOK*CR],  g_krl[MTOK*CR];
__device__ __nv_bfloat16 g_kvh[MTOK*CR],  g_kvl[MTOK*CR];
__device__ __nv_bfloat16 g_Yh [MTOK*CE],  g_Yl [MTOK*CE];
__device__ __nv_bfloat16 g_w0h[CR*CE], g_w0l[CR*CE];   // wq_down
__device__ __nv_bfloat16 g_w1h[CR*CE], g_w1l[CR*CE];   // wk_rope
__device__ __nv_bfloat16 g_w2h[CR*CE], g_w2l[CR*CE];   // wkv_down
__device__ __nv_bfloat16 g_w3h[CE*CR], g_w3l[CE*CR];   // wq_rope
__device__ __nv_bfloat16 g_w4h[CE*CR], g_w4l[CE*CR];   // wq_up
__device__ __nv_bfloat16 g_w5h[CE*CR], g_w5l[CE*CR];   // wk_up
__device__ __nv_bfloat16 g_w6h[CE*CR], g_w6l[CE*CR];   // wv_up
__device__ __nv_bfloat16 g_w7h[CE*CE], g_w7l[CE*CE];   // wo

// attention operand buffers (hi/lo bf16)
__device__ __nv_bfloat16 g_Qbh[CB*CH*CS*CDQK], g_Qbl[CB*CH*CS*CDQK];  // [b,h,s,128]
__device__ __nv_bfloat16 g_Kbh[CB*CH*CS*CDQK], g_Kbl[CB*CH*CS*CDQK];  // [b,h,s,128]
__device__ __nv_bfloat16 g_Vbh[CB*CH*CHD*CS],  g_Vbl[CB*CH*CHD*CS];   // [b,h,d,s]

// ===================== generic helpers =====================================
__device__ __forceinline__ uint32_t smem_to_u32(const void* p) {
    uint32_t a;
    asm("{ .reg .u64 t; cvta.to.shared.u64 t, %1; cvt.u32.u64 %0, t; }" : "=r"(a) : "l"(p));
    return a;
}

// portable tensor-core primitives (sm_80+, legal on plain sm_103 target)
#define LDSM_X4(r0,r1,r2,r3, addr) \
    asm volatile("ldmatrix.sync.aligned.m8n8.x4.shared.b16 {%0,%1,%2,%3}, [%4];" \
        : "=r"(r0), "=r"(r1), "=r"(r2), "=r"(r3) : "r"(addr))

#define MMA16816(c, a, b) \
    asm volatile("mma.sync.aligned.m16n8k16.row.col.f32.bf16.bf16.f32 " \
        "{%0,%1,%2,%3}, {%4,%5,%6,%7}, {%8,%9}, {%0,%1,%2,%3};" \
        : "+f"((c)[0]), "+f"((c)[1]), "+f"((c)[2]), "+f"((c)[3]) \
        : "r"((a)[0]), "r"((a)[1]), "r"((a)[2]), "r"((a)[3]), "r"((b)[0]), "r"((b)[1]))

// split two floats into packed bf16 hi pair + residual lo pair
__device__ __forceinline__ void split2(float a, float b, uint32_t& hi, uint32_t& lo) {
    __nv_bfloat16 ha = __float2bfloat16(a), hb = __float2bfloat16(b);
    float ra = a - __bfloat162float(ha);
    float rb = b - __bfloat162float(hb);
    __nv_bfloat162 hh; hh.x = ha; hh.y = hb;
    hi = *(uint32_t*)&hh;
    __nv_bfloat162 ll = __floats2bfloat162_rn(ra, rb);
    lo = *(uint32_t*)&ll;
}

// ===================== tcgen05 helpers (only expanded under sm_103a) =======
__device__ __forceinline__ uint32_t elect_one_pred() {
    uint32_t pred;
    asm volatile("{\n\t.reg .pred p;\n\telect.sync _|p, 0xFFFFFFFF;\n\tselp.b32 %0, 1, 0, p;\n\t}" : "=r"(pred));
    return pred;
}
#define TCGEN05_ALLOC(smem_addr, nCols) \
    asm volatile("tcgen05.alloc.cta_group::1.sync.aligned.shared::cta.b32 [%0], %1;" \
        :: "r"((uint32_t)(smem_addr)), "r"((uint32_t)(nCols)) : "memory")
#define TCGEN05_DEALLOC(tmem_addr, nCols) \
    asm volatile("tcgen05.dealloc.cta_group::1.sync.aligned.b32 %0, %1;" :: "r"(tmem_addr), "r"((uint32_t)(nCols)))
#define TCGEN05_COMMIT(mbar) \
    asm volatile("tcgen05.commit.cta_group::1.mbarrier::arrive::one.shared::cluster.b64 [%0];" \
        :: "r"((uint32_t)(mbar)) : "memory")
#define TCGEN05_WAIT_LD() asm volatile("tcgen05.wait::ld.sync.aligned;" ::: "memory")
#define TCGEN05_FENCE_BEFORE() asm volatile("tcgen05.fence::before_thread_sync;" ::: "memory")
#define TCGEN05_FENCE_AFTER()  asm volatile("tcgen05.fence::after_thread_sync;" ::: "memory")
#define FENCE_PROXY_ASYNC_SHARED_CTA() asm volatile("fence.proxy.async.shared::cta;" ::: "memory")
#define MBARRIER_INIT(mbar, cnt) \
    asm volatile("mbarrier.init.shared.b64 [%0], %1;" :: "r"((uint32_t)(mbar)), "r"((uint32_t)(cnt)) : "memory")
#define MBARRIER_INVAL(mbar) \
    asm volatile("mbarrier.inval.shared.b64 [%0];" :: "r"((uint32_t)(mbar)) : "memory")
#define MBARRIER_WAIT_PARITY(mbar, par) do { \
    uint32_t _m = (uint32_t)(mbar); uint32_t _p = (uint32_t)(par); uint32_t _done; \
    asm volatile("{\n\t.reg .pred p;\n\tmbarrier.try_wait.parity.acquire.cta.shared::cta.b64 p, [%1], %2;\n\tselp.b32 %0, 1, 0, p;\n\t}" \
        : "=r"(_done) : "r"(_m), "r"(_p) : "memory"); \
    if (!_done) { \
        asm volatile("{\n\t.reg .pred P1;\n\tWL_%=:\n\tmbarrier.try_wait.parity.acquire.cta.shared::cta.b64 P1, [%0], %1, 0x989680;\n\t@P1 bra.uni WD_%=;\n\tbra.uni WL_%=;\n\tWD_%=:\n\t}" \
            :: "r"(_m), "r"(_p) : "memory"); \
    } } while (0)
#define TCGEN05_LD_32X32B_X32(r, tmem_addr) \
    asm volatile("tcgen05.ld.sync.aligned.32x32b.x32.b32 " \
        "{%0, %1, %2, %3, %4, %5, %6, %7, %8, %9, %10, %11, %12, %13, %14, %15, " \
        " %16, %17, %18, %19, %20, %21, %22, %23, %24, %25, %26, %27, %28, %29, %30, %31}, [%32];" \
        : "=r"((r)[0]),  "=r"((r)[1]),  "=r"((r)[2]),  "=r"((r)[3]), \
          "=r"((r)[4]),  "=r"((r)[5]),  "=r"((r)[6]),  "=r"((r)[7]), \
          "=r"((r)[8]),  "=r"((r)[9]),  "=r"((r)[10]), "=r"((r)[11]), \
          "=r"((r)[12]), "=r"((r)[13]), "=r"((r)[14]), "=r"((r)[15]), \
          "=r"((r)[16]), "=r"((r)[17]), "=r"((r)[18]), "=r"((r)[19]), \
          "=r"((r)[20]), "=r"((r)[21]), "=r"((r)[22]), "=r"((r)[23]), \
          "=r"((r)[24]), "=r"((r)[25]), "=r"((r)[26]), "=r"((r)[27]), \
          "=r"((r)[28]), "=r"((r)[29]), "=r"((r)[30]), "=r"((r)[31]) \
        : "r"(tmem_addr))

static constexpr uint64_t SMEM_DESC_BASE_SW128 =
    (uint64_t(2)  << 61) | (uint64_t(1) << 46) | (uint64_t(64) << 32) | (uint64_t(1) << 16);
#define MAKE_SMEM_DESC(base_addr) (SMEM_DESC_BASE_SW128 | ((uint64_t)((base_addr) >> 4) & 0x3FFF))
#define SMEM_SWIZZLE_128B(off) ((off) ^ (((off) >> 3) & 0x70))
#define GEMM_IDESC ((1u<<4) | (1u<<7) | (1u<<10) | ((128u/8)<<17) | ((128u/16)<<24))

#if defined(__CUDA_ARCH__) && defined(__CUDA_ARCH_FEAT_SM103_ALL)
__device__ __forceinline__ void mma_f16_ss(uint32_t d, uint64_t ad, uint64_t bd,
                                           uint32_t idesc, uint32_t en) {
    asm volatile(
        "{\n\t.reg .pred p;\n\tsetp.ne.u32 p, %5, 0;\n\t"
        "tcgen05.mma.cta_group::1.kind::f16 [%0], %1, %2, %3, {%4, %4, %4, %4}, p;\n\t}"
        :: "r"(d), "l"(ad), "l"(bd), "r"(idesc), "r"(0u), "r"(en) : "memory");
}
#endif

// ===================== split-fp32 convert ==================================
__global__ void cvt_split(const float* __restrict__ src,
                          __nv_bfloat16* __restrict__ hi, __nv_bfloat16* __restrict__ lo, int n)
{
    int i = blockIdx.x * blockDim.x + threadIdx.x;
    if (i < n) {
        float v = src[i];
        __nv_bfloat16 h = __float2bfloat16(v);
        hi[i] = h;
        lo[i] = __float2bfloat16(v - __bfloat162float(h));
    }
}

// ============= tensor-core split-bf16 GEMM NT: C = A * W^T =================
#define OFF_PTR  0
#define OFF_MBAR 8
#define OFF_AH   1024
#define OFF_AL   (1024 + 16384)
#define OFF_BH   (1024 + 2*16384)
#define OFF_BL   (1024 + 3*16384)
#define GEMM_SMEM (1024 + 4*16384)

#define MS_AH 0
#define MS_AL 8192
#define MS_BH 16384
#define MS_BL 24576
__device__ __forceinline__ uint32_t msw(int row, int c) {
    return (uint32_t)(row * 64 + ((c ^ ((row >> 1) & 3)) << 4));
}

__global__ __launch_bounds__(256) void gemm_bb(
    const __nv_bfloat16* __restrict__ Ah, const __nv_bfloat16* __restrict__ Al,
    const __nv_bfloat16* __restrict__ Bh, const __nv_bfloat16* __restrict__ Bl,
    float* __restrict__ C, int M, int N, int K)
{
    extern __shared__ char smem[];
    const int tid = threadIdx.x, wid = tid >> 5, lid = tid & 31;
    const int m0 = blockIdx.y * 128, n0 = blockIdx.x * 128;
    uint32_t sb = smem_to_u32(smem);

#if defined(__CUDA_ARCH__) && defined(__CUDA_ARCH_FEAT_SM103_ALL)
    // ---------------- tcgen05 path (sm_103a) -------------------------------
    if (wid == 0) {
        TCGEN05_ALLOC(sb + OFF_PTR, 128);
        if (elect_one_pred()) MBARRIER_INIT(sb + OFF_MBAR, 1);
    }
    __syncthreads();
    uint32_t tmem;
    asm volatile("ld.shared.b32 %0, [%1];" : "=r"(tmem) : "r"(sb + OFF_PTR));

    const int rbase = tid >> 3;
    const int cc    = tid & 7;
    const uint64_t dAh = MAKE_SMEM_DESC(sb + OFF_AH);
    const uint64_t dAl = MAKE_SMEM_DESC(sb + OFF_AL);
    const uint64_t dBh = MAKE_SMEM_DESC(sb + OFF_BH);
    const uint64_t dBl = MAKE_SMEM_DESC(sb + OFF_BL);

    int ph = 0;
    for (int k0 = 0; k0 < K; k0 += 64) {
#pragma unroll
        for (int it = 0; it < 4; it++) {
            int row = it * 32 + rbase;
            uint32_t so = SMEM_SWIZZLE_128B((uint32_t)(row * 128 + cc * 16));
            size_t ga = (size_t)(m0 + row) * K + k0 + cc * 8;
            size_t gb = (size_t)(n0 + row) * K + k0 + cc * 8;
            *(uint4*)(smem + OFF_AH + so) = *(const uint4*)(Ah + ga);
            *(uint4*)(smem + OFF_AL + so) = *(const uint4*)(Al + ga);
            *(uint4*)(smem + OFF_BH + so) = *(const uint4*)(Bh + gb);
            *(uint4*)(smem + OFF_BL + so) = *(const uint4*)(Bl + gb);
        }
        FENCE_PROXY_ASYNC_SHARED_CTA();
        __syncthreads();

        if (wid == 0 && elect_one_pred()) {
#pragma unroll
            for (int kk = 0; kk < 4; kk++)
                mma_f16_ss(tmem, dAh + kk*2, dBh + kk*2, GEMM_IDESC, (k0 > 0) | (kk > 0));
#pragma unroll
            for (int kk = 0; kk < 4; kk++)
                mma_f16_ss(tmem, dAh + kk*2, dBl + kk*2, GEMM_IDESC, 1u);
#pragma unroll
            for (int kk = 0; kk < 4; kk++)
                mma_f16_ss(tmem, dAl + kk*2, dBh + kk*2, GEMM_IDESC, 1u);
            TCGEN05_COMMIT(sb + OFF_MBAR);
        }
        MBARRIER_WAIT_PARITY(sb + OFF_MBAR, ph);
        ph ^= 1;
        __syncthreads();
    }

    TCGEN05_FENCE_AFTER();
    const int mrow  = m0 + (wid & 3) * 32 + lid;
    const int cbase = (wid >> 2) * 64;
#pragma unroll
    for (int cof = 0; cof < 64; cof += 32) {
        uint32_t dr[32];
        TCGEN05_LD_32X32B_X32(dr, tmem + cbase + cof);
        TCGEN05_WAIT_LD();
        float* cp = C + (size_t)mrow * N + n0 + cbase + cof;
#pragma unroll
        for (int j = 0; j < 32; j += 4)
            *(float4*)(cp + j) = make_float4(__uint_as_float(dr[j]),   __uint_as_float(dr[j+1]),
                                             __uint_as_float(dr[j+2]), __uint_as_float(dr[j+3]));
    }
    TCGEN05_FENCE_BEFORE();
    __syncthreads();
    if (wid == 0) {
        if (elect_one_pred()) MBARRIER_INVAL(sb + OFF_MBAR);
        TCGEN05_DEALLOC(tmem, 128);
    }
#else
    // ---------------- mma.sync path (portable sm_80+) ----------------------
    const int mw = wid & 3, nw = wid >> 2;
    const int a_tr = (lid & 7) + ((lid >> 3) & 1) * 8;
    const int a_kq = lid >> 4;
    const int b_tr = (lid & 7) + (lid >> 4) * 8;
    const int b_kq = (lid >> 3) & 1;

    float acc[2][8][4];
#pragma unroll
    for (int i = 0; i < 2; i++)
#pragma unroll
        for (int j = 0; j < 8; j++)
#pragma unroll
            for (int q = 0; q < 4; q++) acc[i][j][q] = 0.f;

    const int prow = tid >> 2, pc = tid & 3;
    uint4 ra[2], rl[2], rb[2], rm[2];
#pragma unroll
    for (int it = 0; it < 2; it++) {
        int row = it * 64 + prow;
        size_t ga = (size_t)(m0 + row) * K + pc * 8;
        size_t gb = (size_t)(n0 + row) * K + pc * 8;
        ra[it] = *(const uint4*)(Ah + ga);
        rl[it] = *(const uint4*)(Al + ga);
        rb[it] = *(const uint4*)(Bh + gb);
        rm[it] = *(const uint4*)(Bl + gb);
    }

    for (int k0 = 0; k0 < K; k0 += 32) {
        __syncthreads();
#pragma unroll
        for (int it = 0; it < 2; it++) {
            int row = it * 64 + prow;
            uint32_t so = msw(row, pc);
            *(uint4*)(smem + MS_AH + so) = ra[it];
            *(uint4*)(smem + MS_AL + so) = rl[it];
            *(uint4*)(smem + MS_BH + so) = rb[it];
            *(uint4*)(smem + MS_BL + so) = rm[it];
        }
        __syncthreads();
        if (k0 + 32 < K) {
#pragma unroll
            for (int it = 0; it < 2; it++) {
                int row = it * 64 + prow;
                size_t ga = (size_t)(m0 + row) * K + k0 + 32 + pc * 8;
                size_t gb = (size_t)(n0 + row) * K + k0 + 32 + pc * 8;
                ra[it] = *(const uint4*)(Ah + ga);
                rl[it] = *(const uint4*)(Al + ga);
                rb[it] = *(const uint4*)(Bh + gb);
                rm[it] = *(const uint4*)(Bl + gb);
            }
        }

#pragma unroll
        for (int ks = 0; ks < 2; ks++) {
            uint32_t ah[2][4], al[2][4], bh[8][2], bl[8][2];
#pragma unroll
            for (int ma = 0; ma < 2; ma++) {
                int row = mw * 32 + ma * 16 + a_tr;
                int c = ks * 2 + a_kq;
                uint32_t ad = sb + MS_AH + msw(row, c);
                LDSM_X4(ah[ma][0], ah[ma][1], ah[ma][2], ah[ma][3], ad);
                uint32_t ad2 = sb + MS_AL + msw(row, c);
                LDSM_X4(al[ma][0], al[ma][1], al[ma][2], al[ma][3], ad2);
            }
#pragma unroll
            for (int nb = 0; nb < 4; nb++) {
                int row = nw * 64 + nb * 16 + b_tr;
                int c = ks * 2 + b_kq;
                uint32_t bd = sb + MS_BH + msw(row, c);
                LDSM_X4(bh[nb*2][0], bh[nb*2][1], bh[nb*2+1][0], bh[nb*2+1][1], bd);
                uint32_t bd2 = sb + MS_BL + msw(row, c);
                LDSM_X4(bl[nb*2][0], bl[nb*2][1], bl[nb*2+1][0], bl[nb*2+1][1], bd2);
            }
#pragma unroll
            for (int ma = 0; ma < 2; ma++)
#pragma unroll
                for (int na = 0; na < 8; na++) {
                    MMA16816(acc[ma][na], ah[ma], bh[na]);
                    MMA16816(acc[ma][na], ah[ma], bl[na]);
                    MMA16816(acc[ma][na], al[ma], bh[na]);
                }
        }
    }

    const int g = lid >> 2, t4 = lid & 3;
#pragma unroll
    for (int ma = 0; ma < 2; ma++) {
        int row0 = m0 + mw * 32 + ma * 16 + g;
#pragma unroll
        for (int na = 0; na < 8; na++) {
            int col = n0 + nw * 64 + na * 8 + t4 * 2;
            *(float2*)(C + (size_t)row0 * N + col) =
                make_float2(acc[ma][na][0], acc[ma][na][1]);
            *(float2*)(C + (size_t)(row0 + 8) * N + col) =
                make_float2(acc[ma][na][2], acc[ma][na][3]);
        }
    }
#endif
}

// ================== rope + scatter (emit bf16 hi/lo, [b,h,s,d]) ============
__global__ void rope_scatter(const float* __restrict__ src,
                             __nv_bfloat16* __restrict__ dh, __nv_bfloat16* __restrict__ dl)
{
    int idx = blockIdx.x * blockDim.x + threadIdx.x;   // 2^21
    int i  = idx & 31;
    int s  = (idx >> 5) & (CS - 1);
    int hb = idx >> 16;
    int h  = hb & 15, b = hb >> 4;
    const float* p = src + (size_t)(b*CS + s) * CE + h*CHD;
    float x1 = p[i];
    float x2 = p[i + 32];
    float ang = (float)s * exp2f(-(float)i * 0.41524101186109f);
    float sn, cs;
    sincosf(ang, &sn, &cs);
    float o1 = x1 * cs - x2 * sn;
    float o2 = x2 * cs + x1 * sn;
    size_t base = ((size_t)hb * CS + s) * CDQK;
    __nv_bfloat16 h1 = __float2bfloat16(o1);
    __nv_bfloat16 h2 = __float2bfloat16(o2);
    dh[base + i]      = h1;  dl[base + i]      = __float2bfloat16(o1 - __bfloat162float(h1));
    dh[base + i + 32] = h2;  dl[base + i + 32] = __float2bfloat16(o2 - __bfloat162float(h2));
}

__global__ void nope_scatter(const float* __restrict__ src,
                             __nv_bfloat16* __restrict__ dh, __nv_bfloat16* __restrict__ dl)
{
    int idx = blockIdx.x * blockDim.x + threadIdx.x;   // 2^22
    int j  = idx & 63;
    int s  = (idx >> 6) & (CS - 1);
    int hb = idx >> 17;
    int h  = hb & 15, b = hb >> 4;
    float v = src[(size_t)(b*CS + s) * CE + h*CHD + j];
    size_t o = ((size_t)hb * CS + s) * CDQK + 64 + j;
    __nv_bfloat16 hv = __float2bfloat16(v);
    dh[o] = hv;
    dl[o] = __float2bfloat16(v - __bfloat162float(hv));
}

// V transposed: [b,h,d,s]
__global__ void vt_scatter(const float* __restrict__ src,
                           __nv_bfloat16* __restrict__ dh, __nv_bfloat16* __restrict__ dl)
{
    int idx = blockIdx.x * blockDim.x + threadIdx.x;   // 2^22
    int s  = idx & (CS - 1);
    int d  = (idx >> 11) & 63;
    int hb = idx >> 17;
    int h  = hb & 15, b = hb >> 4;
    float v = src[(size_t)(b*CS + s) * CE + h*CHD + d];
    size_t o = ((size_t)hb * CHD + d) * CS + s;
    __nv_bfloat16 hv = __float2bfloat16(v);
    dh[o] = hv;
    dl[o] = __float2bfloat16(v - __bfloat162float(hv));
}

// =================== causal flash attention (mma.sync bf16) ================
// Q,K: [b,h,s,128] hi/lo; V: [b,h,d,s] hi/lo; Y: [b,s,E] fp32
#define FQH 0
#define FQL 16384
#define FKH 32768
#define FKL 49152
#define FVH 65536
#define FVL 73728
#define FLASH_SMEM 81920

// 64 rows x 128 bf16 (256B pitch); swizzled 16B chunks within each 128B half
__device__ __forceinline__ uint32_t fsw(int row, int chunk) {
    return (uint32_t)(row * 256 + ((chunk >> 3) << 7) + (((chunk & 7) ^ (row & 7)) << 4));
}
// 64 rows x 64 bf16 (128B pitch)
__device__ __forceinline__ uint32_t vsw(int row, int chunk) {
    return (uint32_t)(row * 128 + ((chunk ^ (row & 7)) << 4));
}

__global__ __launch_bounds__(128) void flash_attn_mma(
    const __nv_bfloat16* __restrict__ Qh, const __nv_bfloat16* __restrict__ Ql,
    const __nv_bfloat16* __restrict__ Kh, const __nv_bfloat16* __restrict__ Kl,
    const __nv_bfloat16* __restrict__ Vh, const __nv_bfloat16* __restrict__ Vl,
    float* __restrict__ Y)
{
    extern __shared__ char smem[];
    uint32_t sb = smem_to_u32(smem);
    const int tid = threadIdx.x, wid = tid >> 5, lid = tid & 31;
    const int qb = blockIdx.x, bh = blockIdx.y;
    const int q0 = qb * 64;
    const int g = lid >> 2, t = lid & 3;

    const __nv_bfloat16* Qhg = Qh + (size_t)bh * CS * CDQK;
    const __nv_bfloat16* Qlg = Ql + (size_t)bh * CS * CDQK;
    const __nv_bfloat16* Khg = Kh + (size_t)bh * CS * CDQK;
    const __nv_bfloat16* Klg = Kl + (size_t)bh * CS * CDQK;
    const __nv_bfloat16* Vhg = Vh + (size_t)bh * CHD * CS;
    const __nv_bfloat16* Vlg = Vl + (size_t)bh * CHD * CS;

    // load Q tile [64 rows][128 d] (hi/lo)
#pragma unroll
    for (int it = 0; it < 8; it++) {
        int i = it * 128 + tid;
        int row = i >> 4, ch = i & 15;
        size_t off = (size_t)(q0 + row) * CDQK + ch * 8;
        *(uint4*)(smem + FQH + fsw(row, ch)) = *(const uint4*)(Qhg + off);
        *(uint4*)(smem + FQL + fsw(row, ch)) = *(const uint4*)(Qlg + off);
    }

    // ldmatrix lane mappings (identical to the verified GEMM path)
    const int a_tr = (lid & 7) + ((lid >> 3) & 1) * 8;
    const int a_kq = lid >> 4;
    const int b_tr = (lid & 7) + (lid >> 4) * 8;
    const int b_kq = (lid >> 3) & 1;

    float O[8][4];
#pragma unroll
    for (int na = 0; na < 8; na++)
#pragma unroll
        for (int e = 0; e < 4; e++) O[na][e] = 0.f;
    float mI0 = -1e30f, mI1 = -1e30f, lI0 = 0.f, lI1 = 0.f;
    const float scale = 0.08838834764831845f;   // 1/sqrt(128)

    for (int kb = 0; kb <= qb; kb++) {
        const int k0 = kb * 64;
        __syncthreads();
        // K tile [64 rows][128 d]
#pragma unroll
        for (int it = 0; it < 8; it++) {
            int i = it * 128 + tid;
            int row = i >> 4, ch = i & 15;
            size_t off = (size_t)(k0 + row) * CDQK + ch * 8;
            *(uint4*)(smem + FKH + fsw(row, ch)) = *(const uint4*)(Khg + off);
            *(uint4*)(smem + FKL + fsw(row, ch)) = *(const uint4*)(Klg + off);
        }
        // V tile transposed [64 d][64 kpos]
#pragma unroll
        for (int it = 0; it < 4; it++) {
            int i = it * 128 + tid;
            int row = i >> 3, ch = i & 7;
            size_t off = (size_t)row * CS + k0 + ch * 8;
            *(uint4*)(smem + FVH + vsw(row, ch)) = *(const uint4*)(Vhg + off);
            *(uint4*)(smem + FVL + vsw(row, ch)) = *(const uint4*)(Vlg + off);
        }
        __syncthreads();

        // ---- S = Q K^T (split bf16x3) ----
        float sc[8][4];
#pragma unroll
        for (int na = 0; na < 8; na++)
#pragma unroll
            for (int e = 0; e < 4; e++) sc[na][e] = 0.f;

#pragma unroll
        for (int ks = 0; ks < 8; ks++) {
            uint32_t ah[4], al[4], khf[8][2], klf[8][2];
            uint32_t qa = sb + FQH + fsw(wid * 16 + a_tr, ks * 2 + a_kq);
            LDSM_X4(ah[0], ah[1], ah[2], ah[3], qa);
            uint32_t qa2 = sb + FQL + fsw(wid * 16 + a_tr, ks * 2 + a_kq);
            LDSM_X4(al[0], al[1], al[2], al[3], qa2);
#pragma unroll
            for (int nb = 0; nb < 4; nb++) {
                uint32_t ka = sb + FKH + fsw(nb * 16 + b_tr, ks * 2 + b_kq);
                LDSM_X4(khf[nb*2][0], khf[nb*2][1], khf[nb*2+1][0], khf[nb*2+1][1], ka);
                uint32_t ka2 = sb + FKL + fsw(nb * 16 + b_tr, ks * 2 + b_kq);
                LDSM_X4(klf[nb*2][0], klf[nb*2][1], klf[nb*2+1][0], klf[nb*2+1][1], ka2);
            }
#pragma unroll
            for (int na = 0; na < 8; na++) {
                MMA16816(sc[na], ah, khf[na]);
                MMA16816(sc[na], ah, klf[na]);
                MMA16816(sc[na], al, khf[na]);
            }
        }

        // ---- scale + causal mask ----
        if (kb == qb) {
#pragma unroll
            for (int na = 0; na < 8; na++)
#pragma unroll
                for (int e = 0; e < 4; e++) {
                    int qr = wid * 16 + g + ((e >> 1) << 3);
                    int kc = na * 8 + 2 * t + (e & 1);
                    sc[na][e] = (kc > qr) ? -1e30f : sc[na][e] * scale;
                }
        } else {
#pragma unroll
            for (int na = 0; na < 8; na++)
#pragma unroll
                for (int e = 0; e < 4; e++) sc[na][e] *= scale;
        }

        // ---- online softmax (rows g and g+8) ----
        float mx0 = -1e30f, mx1 = -1e30f;
#pragma unroll
        for (int na = 0; na < 8; na++) {
            mx0 = fmaxf(mx0, fmaxf(sc[na][0], sc[na][1]));
            mx1 = fmaxf(mx1, fmaxf(sc[na][2], sc[na][3]));
        }
        mx0 = fmaxf(mx0, __shfl_xor_sync(0xffffffffu, mx0, 1));
        mx0 = fmaxf(mx0, __shfl_xor_sync(0xffffffffu, mx0, 2));
        mx1 = fmaxf(mx1, __shfl_xor_sync(0xffffffffu, mx1, 1));
        mx1 = fmaxf(mx1, __shfl_xor_sync(0xffffffffu, mx1, 2));

        float mn0 = fmaxf(mI0, mx0), mn1 = fmaxf(mI1, mx1);
        float al0 = __expf(mI0 - mn0), al1 = __expf(mI1 - mn1);
        mI0 = mn0; mI1 = mn1;

        float rs0 = 0.f, rs1 = 0.f;
#pragma unroll
        for (int na = 0; na < 8; na++) {
            sc[na][0] = __expf(sc[na][0] - mn0); rs0 += sc[na][0];
            sc[na][1] = __expf(sc[na][1] - mn0); rs0 += sc[na][1];
            sc[na][2] = __expf(sc[na][2] - mn1); rs1 += sc[na][2];
            sc[na][3] = __expf(sc[na][3] - mn1); rs1 += sc[na][3];
        }
        rs0 += __shfl_xor_sync(0xffffffffu, rs0, 1);
        rs0 += __shfl_xor_sync(0xffffffffu, rs0, 2);
        rs1 += __shfl_xor_sync(0xffffffffu, rs1, 1);
        rs1 += __shfl_xor_sync(0xffffffffu, rs1, 2);
        lI0 = lI0 * al0 + rs0;
        lI1 = lI1 * al1 + rs1;

#pragma unroll
        for (int na = 0; na < 8; na++) {
            O[na][0] *= al0; O[na][1] *= al0;
            O[na][2] *= al1; O[na][3] *= al1;
        }

        // ---- O += P V  (P split hi/lo bf16; V hi/lo from smem) ----
#pragma unroll
        for (int kk = 0; kk < 4; kk++) {
            uint32_t pah[4], pal[4];
            split2(sc[2*kk][0],   sc[2*kk][1],   pah[0], pal[0]);
            split2(sc[2*kk][2],   sc[2*kk][3],   pah[1], pal[1]);
            split2(sc[2*kk+1][0], sc[2*kk+1][1], pah[2], pal[2]);
            split2(sc[2*kk+1][2], sc[2*kk+1][3], pah[3], pal[3]);
            uint32_t vhf[8][2], vlf[8][2];
#pragma unroll
            for (int nb = 0; nb < 4; nb++) {
                uint32_t va = sb + FVH + vsw(nb * 16 + b_tr, kk * 2 + b_kq);
                LDSM_X4(vhf[nb*2][0], vhf[nb*2][1], vhf[nb*2+1][0], vhf[nb*2+1][1], va);
                uint32_t va2 = sb + FVL + vsw(nb * 16 + b_tr, kk * 2 + b_kq);
                LDSM_X4(vlf[nb*2][0], vlf[nb*2][1], vlf[nb*2+1][0], vlf[nb*2+1][1], va2);
            }
#pragma unroll
            for (int na = 0; na < 8; na++) {
                MMA16816(O[na], pah, vhf[na]);
                MMA16816(O[na], pal, vhf[na]);
                MMA16816(O[na], pah, vlf[na]);
            }
        }
    }

    // ---- epilogue ----
    const int b = bh >> 4, h = bh & 15;
    const float inv0 = 1.f / lI0, inv1 = 1.f / lI1;
    const int qr0 = q0 + wid * 16 + g;
#pragma unroll
    for (int na = 0; na < 8; na++) {
        int col = h * CHD + na * 8 + 2 * t;
        *(float2*)(Y + (size_t)(b*CS + qr0) * CE + col) =
            make_float2(O[na][0] * inv0, O[na][1] * inv0);
        *(float2*)(Y + (size_t)(b*CS + qr0 + 8) * CE + col) =
            make_float2(O[na][2] * inv1, O[na][3] * inv1);
    }
}

// ============================== launcher ===================================
static inline void launch_cvt(const float* s, __nv_bfloat16* h, __nv_bfloat16* l, int n) {
    cvt_split<<<(n + 255) / 256, 256>>>(s, h, l, n);
}

extern "C" void kernel_launch(void* const* d_in, const int* in_sizes, int n_in,
                              void* d_out, int out_size)
{
    const float* x        = (const float*)d_in[0];
    const float* wq_down  = (const float*)d_in[1];
    const float* wk_rope  = (const float*)d_in[2];
    const float* wkv_down = (const float*)d_in[3];
    const float* wq_rope  = (const float*)d_in[4];
    const float* wq_up    = (const float*)d_in[5];
    const float* wk_up    = (const float*)d_in[6];
    const float* wv_up    = (const float*)d_in[7];
    const float* wo       = (const float*)d_in[8];
    float* out = (float*)d_out;

    float *qlat, *krlat, *kv, *tmp, *Y;
    cudaGetSymbolAddress((void**)&qlat,  g_qlat);
    cudaGetSymbolAddress((void**)&krlat, g_krlat);
    cudaGetSymbolAddress((void**)&kv,    g_kv);
    cudaGetSymbolAddress((void**)&tmp,   g_tmp);
    cudaGetSymbolAddress((void**)&Y,     g_Y);

    __nv_bfloat16 *xh,*xl,*qlh,*qll,*krh,*krl,*kvh,*kvl,*Yh,*Yl;
    __nv_bfloat16 *w0h,*w0l,*w1h,*w1l,*w2h,*w2l,*w3h,*w3l,*w4h,*w4l,*w5h,*w5l,*w6h,*w6l,*w7h,*w7l;
    __nv_bfloat16 *Qbh,*Qbl,*Kbh,*Kbl,*Vbh,*Vbl;
    cudaGetSymbolAddress((void**)&xh,  g_xh);  cudaGetSymbolAddress((void**)&xl,  g_xl);
    cudaGetSymbolAddress((void**)&qlh, g_qlh); cudaGetSymbolAddress((void**)&qll, g_qll);
    cudaGetSymbolAddress((void**)&krh, g_krh); cudaGetSymbolAddress((void**)&krl, g_krl);
    cudaGetSymbolAddress((void**)&kvh, g_kvh); cudaGetSymbolAddress((void**)&kvl, g_kvl);
    cudaGetSymbolAddress((void**)&Yh,  g_Yh);  cudaGetSymbolAddress((void**)&Yl,  g_Yl);
    cudaGetSymbolAddress((void**)&w0h, g_w0h); cudaGetSymbolAddress((void**)&w0l, g_w0l);
    cudaGetSymbolAddress((void**)&w1h, g_w1h); cudaGetSymbolAddress((void**)&w1l, g_w1l);
    cudaGetSymbolAddress((void**)&w2h, g_w2h); cudaGetSymbolAddress((void**)&w2l, g_w2l);
    cudaGetSymbolAddress((void**)&w3h, g_w3h); cudaGetSymbolAddress((void**)&w3l, g_w3l);
    cudaGetSymbolAddress((void**)&w4h, g_w4h); cudaGetSymbolAddress((void**)&w4l, g_w4l);
    cudaGetSymbolAddress((void**)&w5h, g_w5h); cudaGetSymbolAddress((void**)&w5l, g_w5l);
    cudaGetSymbolAddress((void**)&w6h, g_w6h); cudaGetSymbolAddress((void**)&w6l, g_w6l);
    cudaGetSymbolAddress((void**)&w7h, g_w7h); cudaGetSymbolAddress((void**)&w7l, g_w7l);
    cudaGetSymbolAddress((void**)&Qbh, g_Qbh); cudaGetSymbolAddress((void**)&Qbl, g_Qbl);
    cudaGetSymbolAddress((void**)&Kbh, g_Kbh); cudaGetSymbolAddress((void**)&Kbl, g_Kbl);
    cudaGetSymbolAddress((void**)&Vbh, g_Vbh); cudaGetSymbolAddress((void**)&Vbl, g_Vbl);

    cudaFuncSetAttribute(gemm_bb, cudaFuncAttributeMaxDynamicSharedMemorySize, GEMM_SMEM);
    cudaFuncSetAttribute(flash_attn_mma, cudaFuncAttributeMaxDynamicSharedMemorySize, FLASH_SMEM);

    // split conversions: inputs + weights
    launch_cvt(x,        xh,  xl,  MTOK*CE);
    launch_cvt(wq_down,  w0h, w0l, CR*CE);
    launch_cvt(wk_rope,  w1h, w1l, CR*CE);
    launch_cvt(wkv_down, w2h, w2l, CR*CE);
    launch_cvt(wq_rope,  w3h, w3l, CE*CR);
    launch_cvt(wq_up,    w4h, w4l, CE*CR);
    launch_cvt(wk_up,    w5h, w5l, CE*CR);
    launch_cvt(wv_up,    w6h, w6l, CE*CR);
    launch_cvt(wo,       w7h, w7l, CE*CE);

    dim3 blk(256);
    // down projections
    gemm_bb<<<dim3(CR/128, MTOK/128), blk, GEMM_SMEM>>>(xh, xl, w0h, w0l, qlat,  MTOK, CR, CE);
    gemm_bb<<<dim3(CR/128, MTOK/128), blk, GEMM_SMEM>>>(xh, xl, w1h, w1l, krlat, MTOK, CR, CE);
    gemm_bb<<<dim3(CR/128, MTOK/128), blk, GEMM_SMEM>>>(xh, xl, w2h, w2l, kv,    MTOK, CR, CE);
    launch_cvt(qlat,  qlh, qll, MTOK*CR);
    launch_cvt(krlat, krh, krl, MTOK*CR);
    launch_cvt(kv,    kvh, kvl, MTOK*CR);

    // q rope
    gemm_bb<<<dim3(CE/128, MTOK/128), blk, GEMM_SMEM>>>(qlh, qll, w3h, w3l, tmp, MTOK, CE, CR);
    rope_scatter<<<8192, 256>>>(tmp, Qbh, Qbl);
    // q nope
    gemm_bb<<<dim3(CE/128, MTOK/128), blk, GEMM_SMEM>>>(qlh, qll, w4h, w4l, tmp, MTOK, CE, CR);
    nope_scatter<<<16384, 256>>>(tmp, Qbh, Qbl);
    // k rope
    gemm_bb<<<dim3(CE/128, MTOK/128), blk, GEMM_SMEM>>>(krh, krl, w5h, w5l, tmp, MTOK, CE, CR);
    rope_scatter<<<8192, 256>>>(tmp, Kbh, Kbl);
    // k nope
    gemm_bb<<<dim3(CE/128, MTOK/128), blk, GEMM_SMEM>>>(kvh, kvl, w5h, w5l, tmp, MTOK, CE, CR);
    nope_scatter<<<16384, 256>>>(tmp, Kbh, Kbl);
    // v (transposed)
    gemm_bb<<<dim3(CE/128, MTOK/128), blk, GEMM_SMEM>>>(kvh, kvl, w6h, w6l, tmp, MTOK, CE, CR);
    vt_scatter<<<16384, 256>>>(tmp, Vbh, Vbl);

    // causal flash attention (tensor cores) -> Y
    flash_attn_mma<<<dim3(CS/64, CB*CH), 128, FLASH_SMEM>>>(Qbh, Qbl, Kbh, Kbl, Vbh, Vbl, Y);

    // output projection
    launch_cvt(Y, Yh, Yl, MTOK*CE);
    gemm_bb<<<dim3(CE/128, MTOK/128), blk, GEMM_SMEM>>>(Yh, Yl, w7h, w7l, out, MTOK, CE, CE);
}

// round 6
// speedup vs baseline: 2.6376x; 1.1608x over previous
#include <cuda_runtime.h>
#include <cuda_bf16.h>
#include <cstdint>
#include <math.h>

#define CB   2
#define CS   2048
#define CE   1024
#define CR   256
#define CH   16
#define CHD  64
#define CDQK 128
#define MTOK (CB*CS)   // 4096
#define NLAT 768       // 3 x 256 concatenated latents

// ---------------- scratch (no allocation allowed -> __device__ globals) ----
__device__ __nv_bfloat16 g_xh [MTOK*CE],  g_xl [MTOK*CE];
__device__ __nv_bfloat16 g_lath[MTOK*NLAT], g_latl[MTOK*NLAT];  // [q|kr|kv] latents
__device__ __nv_bfloat16 g_Yh [MTOK*CE],  g_Yl [MTOK*CE];
__device__ __nv_bfloat16 g_wdh[NLAT*CE], g_wdl[NLAT*CE];        // wq_down|wk_rope|wkv_down
__device__ __nv_bfloat16 g_w3h[CE*CR], g_w3l[CE*CR];   // wq_rope
__device__ __nv_bfloat16 g_w4h[CE*CR], g_w4l[CE*CR];   // wq_up
__device__ __nv_bfloat16 g_w5h[CE*CR], g_w5l[CE*CR];   // wk_up
__device__ __nv_bfloat16 g_w6h[CE*CR], g_w6l[CE*CR];   // wv_up
__device__ __nv_bfloat16 g_w7h[CE*CE], g_w7l[CE*CE];   // wo

// attention operand buffers (hi/lo bf16)
__device__ __nv_bfloat16 g_Qbh[CB*CH*CS*CDQK], g_Qbl[CB*CH*CS*CDQK];  // [b,h,s,128]
__device__ __nv_bfloat16 g_Kbh[CB*CH*CS*CDQK], g_Kbl[CB*CH*CS*CDQK];  // [b,h,s,128]
__device__ __nv_bfloat16 g_Vbh[CB*CH*CHD*CS],  g_Vbl[CB*CH*CHD*CS];   // [b,h,d,s]

// ===================== generic helpers =====================================
__device__ __forceinline__ uint32_t smem_to_u32(const void* p) {
    uint32_t a;
    asm("{ .reg .u64 t; cvta.to.shared.u64 t, %1; cvt.u32.u64 %0, t; }" : "=r"(a) : "l"(p));
    return a;
}

#define LDSM_X4(r0,r1,r2,r3, addr) \
    asm volatile("ldmatrix.sync.aligned.m8n8.x4.shared.b16 {%0,%1,%2,%3}, [%4];" \
        : "=r"(r0), "=r"(r1), "=r"(r2), "=r"(r3) : "r"(addr))

#define MMA16816(c, a, b) \
    asm volatile("mma.sync.aligned.m16n8k16.row.col.f32.bf16.bf16.f32 " \
        "{%0,%1,%2,%3}, {%4,%5,%6,%7}, {%8,%9}, {%0,%1,%2,%3};" \
        : "+f"((c)[0]), "+f"((c)[1]), "+f"((c)[2]), "+f"((c)[3]) \
        : "r"((a)[0]), "r"((a)[1]), "r"((a)[2]), "r"((a)[3]), "r"((b)[0]), "r"((b)[1]))

// split two floats into packed bf16 hi pair + residual lo pair
__device__ __forceinline__ void split2(float a, float b, uint32_t& hi, uint32_t& lo) {
    __nv_bfloat16 ha = __float2bfloat16(a), hb = __float2bfloat16(b);
    float ra = a - __bfloat162float(ha);
    float rb = b - __bfloat162float(hb);
    __nv_bfloat162 hh; hh.x = ha; hh.y = hb;
    hi = *(uint32_t*)&hh;
    __nv_bfloat162 ll = __floats2bfloat162_rn(ra, rb);
    lo = *(uint32_t*)&ll;
}

// ===================== split-fp32 convert ==================================
__global__ void cvt_split(const float* __restrict__ src,
                          __nv_bfloat16* __restrict__ hi, __nv_bfloat16* __restrict__ lo, int n)
{
    int i = blockIdx.x * blockDim.x + threadIdx.x;
    if (i < n) {
        float v = src[i];
        __nv_bfloat16 h = __float2bfloat16(v);
        hi[i] = h;
        lo[i] = __float2bfloat16(v - __bfloat162float(h));
    }
}

// ============= tensor-core split-bf16 GEMM NT with fused epilogues =========
// C[M,N] = A[M,K] * B[N,K]^T, A/B bf16 hi+lo. CTA tile 128x128, 256 threads.
// MODE 0: fp32 store to Cf[row*ldc+col]
// MODE 1: split bf16 hi/lo store to Ch/Cl[row*ldc+col]
// MODE 2: rope -> Ch/Cl are Q or K [b,h,s,128] (cols of warp tile = one head)
// MODE 3: nope -> Ch/Cl at [b,h,s,64+d]
// MODE 4: v transposed -> Ch/Cl are V [b,h,d,s]
#define GEMM_SMEM 32768
#define MS_AH 0
#define MS_AL 8192
#define MS_BH 16384
#define MS_BL 24576
#define ROPE_L 0.41524101186109f   // log2(10000)/32

__device__ __forceinline__ uint32_t msw(int row, int c) {
    return (uint32_t)(row * 64 + ((c ^ ((row >> 1) & 3)) << 4));
}

template<int MODE>
__global__ __launch_bounds__(256) void gemm_ms(
    const __nv_bfloat16* __restrict__ Ah, const __nv_bfloat16* __restrict__ Al, int lda,
    const __nv_bfloat16* __restrict__ Bh, const __nv_bfloat16* __restrict__ Bl, int ldb,
    float* __restrict__ Cf, __nv_bfloat16* __restrict__ Ch, __nv_bfloat16* __restrict__ Cl,
    int ldc, int K)
{
    extern __shared__ char smem[];
    const int tid = threadIdx.x, wid = tid >> 5, lid = tid & 31;
    const int m0 = blockIdx.y * 128, n0 = blockIdx.x * 128;
    uint32_t sb = smem_to_u32(smem);

    const int mw = wid & 3, nw = wid >> 2;
    const int a_tr = (lid & 7) + ((lid >> 3) & 1) * 8;
    const int a_kq = lid >> 4;
    const int b_tr = (lid & 7) + (lid >> 4) * 8;
    const int b_kq = (lid >> 3) & 1;

    float acc[2][8][4];
#pragma unroll
    for (int i = 0; i < 2; i++)
#pragma unroll
        for (int j = 0; j < 8; j++)
#pragma unroll
            for (int q = 0; q < 4; q++) acc[i][j][q] = 0.f;

    const int prow = tid >> 2, pc = tid & 3;
    uint4 ra[2], rl[2], rb[2], rm[2];
#pragma unroll
    for (int it = 0; it < 2; it++) {
        int row = it * 64 + prow;
        size_t ga = (size_t)(m0 + row) * lda + pc * 8;
        size_t gb = (size_t)(n0 + row) * ldb + pc * 8;
        ra[it] = *(const uint4*)(Ah + ga);
        rl[it] = *(const uint4*)(Al + ga);
        rb[it] = *(const uint4*)(Bh + gb);
        rm[it] = *(const uint4*)(Bl + gb);
    }

    for (int k0 = 0; k0 < K; k0 += 32) {
        __syncthreads();
#pragma unroll
        for (int it = 0; it < 2; it++) {
            int row = it * 64 + prow;
            uint32_t so = msw(row, pc);
            *(uint4*)(smem + MS_AH + so) = ra[it];
            *(uint4*)(smem + MS_AL + so) = rl[it];
            *(uint4*)(smem + MS_BH + so) = rb[it];
            *(uint4*)(smem + MS_BL + so) = rm[it];
        }
        __syncthreads();
        if (k0 + 32 < K) {
#pragma unroll
            for (int it = 0; it < 2; it++) {
                int row = it * 64 + prow;
                size_t ga = (size_t)(m0 + row) * lda + k0 + 32 + pc * 8;
                size_t gb = (size_t)(n0 + row) * ldb + k0 + 32 + pc * 8;
                ra[it] = *(const uint4*)(Ah + ga);
                rl[it] = *(const uint4*)(Al + ga);
                rb[it] = *(const uint4*)(Bh + gb);
                rm[it] = *(const uint4*)(Bl + gb);
            }
        }

#pragma unroll
        for (int ks = 0; ks < 2; ks++) {
            uint32_t ah[2][4], al[2][4], bh[8][2], bl[8][2];
#pragma unroll
            for (int ma = 0; ma < 2; ma++) {
                int row = mw * 32 + ma * 16 + a_tr;
                int c = ks * 2 + a_kq;
                uint32_t ad = sb + MS_AH + msw(row, c);
                LDSM_X4(ah[ma][0], ah[ma][1], ah[ma][2], ah[ma][3], ad);
                uint32_t ad2 = sb + MS_AL + msw(row, c);
                LDSM_X4(al[ma][0], al[ma][1], al[ma][2], al[ma][3], ad2);
            }
#pragma unroll
            for (int nb = 0; nb < 4; nb++) {
                int row = nw * 64 + nb * 16 + b_tr;
                int c = ks * 2 + b_kq;
                uint32_t bd = sb + MS_BH + msw(row, c);
                LDSM_X4(bh[nb*2][0], bh[nb*2][1], bh[nb*2+1][0], bh[nb*2+1][1], bd);
                uint32_t bd2 = sb + MS_BL + msw(row, c);
                LDSM_X4(bl[nb*2][0], bl[nb*2][1], bl[nb*2+1][0], bl[nb*2+1][1], bd2);
            }
#pragma unroll
            for (int ma = 0; ma < 2; ma++)
#pragma unroll
                for (int na = 0; na < 8; na++) {
                    MMA16816(acc[ma][na], ah[ma], bh[na]);
                    MMA16816(acc[ma][na], ah[ma], bl[na]);
                    MMA16816(acc[ma][na], al[ma], bh[na]);
                }
        }
    }

    // ----------------------- fused epilogues -------------------------------
    const int g = lid >> 2, t4 = lid & 3;

    if (MODE == 0) {
#pragma unroll
        for (int ma = 0; ma < 2; ma++) {
            int row0 = m0 + mw * 32 + ma * 16 + g;
#pragma unroll
            for (int na = 0; na < 8; na++) {
                int col = n0 + nw * 64 + na * 8 + t4 * 2;
                *(float2*)(Cf + (size_t)row0 * ldc + col) =
                    make_float2(acc[ma][na][0], acc[ma][na][1]);
                *(float2*)(Cf + (size_t)(row0 + 8) * ldc + col) =
                    make_float2(acc[ma][na][2], acc[ma][na][3]);
            }
        }
    } else if (MODE == 1) {
#pragma unroll
        for (int ma = 0; ma < 2; ma++) {
            int row0 = m0 + mw * 32 + ma * 16 + g;
#pragma unroll
            for (int na = 0; na < 8; na++) {
                int col = n0 + nw * 64 + na * 8 + t4 * 2;
                uint32_t h0, l0;
                split2(acc[ma][na][0], acc[ma][na][1], h0, l0);
                *(uint32_t*)(Ch + (size_t)row0 * ldc + col) = h0;
                *(uint32_t*)(Cl + (size_t)row0 * ldc + col) = l0;
                split2(acc[ma][na][2], acc[ma][na][3], h0, l0);
                *(uint32_t*)(Ch + (size_t)(row0 + 8) * ldc + col) = h0;
                *(uint32_t*)(Cl + (size_t)(row0 + 8) * ldc + col) = l0;
            }
        }
    } else if (MODE == 2) {
        // rope: warp tile covers one head's 64 cols; pairs (i, i+32) = (na, na+4)
        const int hq = (n0 + nw * 64) >> 6;
#pragma unroll
        for (int ma = 0; ma < 2; ma++) {
            int r0 = m0 + mw * 32 + ma * 16 + g;
            int b = r0 >> 11;
            size_t bb = (size_t)((b << 4) + hq) * CS * CDQK;
#pragma unroll
            for (int rh = 0; rh < 2; rh++) {
                int s = (r0 + rh * 8) & (CS - 1);
                size_t base = bb + (size_t)s * CDQK;
                float fs = (float)s;
#pragma unroll
                for (int na = 0; na < 4; na++) {
                    int e = rh * 2;
                    int i0 = na * 8 + t4 * 2;
                    float x1a = acc[ma][na][e],     x1b = acc[ma][na][e+1];
                    float x2a = acc[ma][na+4][e],   x2b = acc[ma][na+4][e+1];
                    float sn0, cs0, sn1, cs1;
                    sincosf(fs * exp2f(-(float)i0 * ROPE_L), &sn0, &cs0);
                    sincosf(fs * exp2f(-(float)(i0+1) * ROPE_L), &sn1, &cs1);
                    float o1a = x1a*cs0 - x2a*sn0, o1b = x1b*cs1 - x2b*sn1;
                    float o2a = x2a*cs0 + x1a*sn0, o2b = x2b*cs1 + x1b*sn1;
                    uint32_t h0, l0;
                    split2(o1a, o1b, h0, l0);
                    *(uint32_t*)(Ch + base + i0) = h0;
                    *(uint32_t*)(Cl + base + i0) = l0;
                    split2(o2a, o2b, h0, l0);
                    *(uint32_t*)(Ch + base + 32 + i0) = h0;
                    *(uint32_t*)(Cl + base + 32 + i0) = l0;
                }
            }
        }
    } else if (MODE == 3) {
        const int hq = (n0 + nw * 64) >> 6;
#pragma unroll
        for (int ma = 0; ma < 2; ma++) {
            int r0 = m0 + mw * 32 + ma * 16 + g;
            int b = r0 >> 11;
            size_t bb = (size_t)((b << 4) + hq) * CS * CDQK;
#pragma unroll
            for (int rh = 0; rh < 2; rh++) {
                int s = (r0 + rh * 8) & (CS - 1);
                size_t base = bb + (size_t)s * CDQK + 64;
#pragma unroll
                for (int na = 0; na < 8; na++) {
                    int d0 = na * 8 + t4 * 2;
                    uint32_t h0, l0;
                    split2(acc[ma][na][rh*2], acc[ma][na][rh*2+1], h0, l0);
                    *(uint32_t*)(Ch + base + d0) = h0;
                    *(uint32_t*)(Cl + base + d0) = l0;
                }
            }
        }
    } else {
        // vt: V [b,h,d,s]
        const int hq = (n0 + nw * 64) >> 6;
#pragma unroll
        for (int ma = 0; ma < 2; ma++) {
            int r0 = m0 + mw * 32 + ma * 16 + g;
            int b = r0 >> 11;
            size_t bb = (size_t)((b << 4) + hq) * CHD;
#pragma unroll
            for (int rh = 0; rh < 2; rh++) {
                int s = (r0 + rh * 8) & (CS - 1);
#pragma unroll
                for (int na = 0; na < 8; na++) {
#pragma unroll
                    for (int j = 0; j < 2; j++) {
                        int d = na * 8 + t4 * 2 + j;
                        float v = acc[ma][na][rh*2 + j];
                        __nv_bfloat16 hv = __float2bfloat16(v);
                        size_t o = (bb + d) * CS + s;
                        Ch[o] = hv;
                        Cl[o] = __float2bfloat16(v - __bfloat162float(hv));
                    }
                }
            }
        }
    }
}

// =================== causal flash attention (mma.sync bf16) ================
// Q,K: [b,h,s,128] hi/lo; V: [b,h,d,s] hi/lo; out: Yh/Yl [b,s,E] bf16 hi/lo
#define FQH 0
#define FQL 16384
#define FKH 32768
#define FKL 49152
#define FVH 65536
#define FVL 73728
#define FLASH_SMEM 81920

__device__ __forceinline__ uint32_t fsw(int row, int chunk) {
    return (uint32_t)(row * 256 + ((chunk >> 3) << 7) + (((chunk & 7) ^ (row & 7)) << 4));
}
__device__ __forceinline__ uint32_t vsw(int row, int chunk) {
    return (uint32_t)(row * 128 + ((chunk ^ (row & 7)) << 4));
}

__global__ __launch_bounds__(128) void flash_attn_mma(
    const __nv_bfloat16* __restrict__ Qh, const __nv_bfloat16* __restrict__ Ql,
    const __nv_bfloat16* __restrict__ Kh, const __nv_bfloat16* __restrict__ Kl,
    const __nv_bfloat16* __restrict__ Vh, const __nv_bfloat16* __restrict__ Vl,
    __nv_bfloat16* __restrict__ Yh, __nv_bfloat16* __restrict__ Yl)
{
    extern __shared__ char smem[];
    uint32_t sb = smem_to_u32(smem);
    const int tid = threadIdx.x, wid = tid >> 5, lid = tid & 31;
    const int qb = blockIdx.x, bh = blockIdx.y;
    const int q0 = qb * 64;
    const int g = lid >> 2, t = lid & 3;

    const __nv_bfloat16* Qhg = Qh + (size_t)bh * CS * CDQK;
    const __nv_bfloat16* Qlg = Ql + (size_t)bh * CS * CDQK;
    const __nv_bfloat16* Khg = Kh + (size_t)bh * CS * CDQK;
    const __nv_bfloat16* Klg = Kl + (size_t)bh * CS * CDQK;
    const __nv_bfloat16* Vhg = Vh + (size_t)bh * CHD * CS;
    const __nv_bfloat16* Vlg = Vl + (size_t)bh * CHD * CS;

#pragma unroll
    for (int it = 0; it < 8; it++) {
        int i = it * 128 + tid;
        int row = i >> 4, ch = i & 15;
        size_t off = (size_t)(q0 + row) * CDQK + ch * 8;
        *(uint4*)(smem + FQH + fsw(row, ch)) = *(const uint4*)(Qhg + off);
        *(uint4*)(smem + FQL + fsw(row, ch)) = *(const uint4*)(Qlg + off);
    }

    const int a_tr = (lid & 7) + ((lid >> 3) & 1) * 8;
    const int a_kq = lid >> 4;
    const int b_tr = (lid & 7) + (lid >> 4) * 8;
    const int b_kq = (lid >> 3) & 1;

    float O[8][4];
#pragma unroll
    for (int na = 0; na < 8; na++)
#pragma unroll
        for (int e = 0; e < 4; e++) O[na][e] = 0.f;
    float mI0 = -1e30f, mI1 = -1e30f, lI0 = 0.f, lI1 = 0.f;
    const float scale = 0.08838834764831845f;

    for (int kb = 0; kb <= qb; kb++) {
        const int k0 = kb * 64;
        __syncthreads();
#pragma unroll
        for (int it = 0; it < 8; it++) {
            int i = it * 128 + tid;
            int row = i >> 4, ch = i & 15;
            size_t off = (size_t)(k0 + row) * CDQK + ch * 8;
            *(uint4*)(smem + FKH + fsw(row, ch)) = *(const uint4*)(Khg + off);
            *(uint4*)(smem + FKL + fsw(row, ch)) = *(const uint4*)(Klg + off);
        }
#pragma unroll
        for (int it = 0; it < 4; it++) {
            int i = it * 128 + tid;
            int row = i >> 3, ch = i & 7;
            size_t off = (size_t)row * CS + k0 + ch * 8;
            *(uint4*)(smem + FVH + vsw(row, ch)) = *(const uint4*)(Vhg + off);
            *(uint4*)(smem + FVL + vsw(row, ch)) = *(const uint4*)(Vlg + off);
        }
        __syncthreads();

        float sc[8][4];
#pragma unroll
        for (int na = 0; na < 8; na++)
#pragma unroll
            for (int e = 0; e < 4; e++) sc[na][e] = 0.f;

#pragma unroll
        for (int ks = 0; ks < 8; ks++) {
            uint32_t ah[4], al[4], khf[8][2], klf[8][2];
            uint32_t qa = sb + FQH + fsw(wid * 16 + a_tr, ks * 2 + a_kq);
            LDSM_X4(ah[0], ah[1], ah[2], ah[3], qa);
            uint32_t qa2 = sb + FQL + fsw(wid * 16 + a_tr, ks * 2 + a_kq);
            LDSM_X4(al[0], al[1], al[2], al[3], qa2);
#pragma unroll
            for (int nb = 0; nb < 4; nb++) {
                uint32_t ka = sb + FKH + fsw(nb * 16 + b_tr, ks * 2 + b_kq);
                LDSM_X4(khf[nb*2][0], khf[nb*2][1], khf[nb*2+1][0], khf[nb*2+1][1], ka);
                uint32_t ka2 = sb + FKL + fsw(nb * 16 + b_tr, ks * 2 + b_kq);
                LDSM_X4(klf[nb*2][0], klf[nb*2][1], klf[nb*2+1][0], klf[nb*2+1][1], ka2);
            }
#pragma unroll
            for (int na = 0; na < 8; na++) {
                MMA16816(sc[na], ah, khf[na]);
                MMA16816(sc[na], ah, klf[na]);
                MMA16816(sc[na], al, khf[na]);
            }
        }

        if (kb == qb) {
#pragma unroll
            for (int na = 0; na < 8; na++)
#pragma unroll
                for (int e = 0; e < 4; e++) {
                    int qr = wid * 16 + g + ((e >> 1) << 3);
                    int kc = na * 8 + 2 * t + (e & 1);
                    sc[na][e] = (kc > qr) ? -1e30f : sc[na][e] * scale;
                }
        } else {
#pragma unroll
            for (int na = 0; na < 8; na++)
#pragma unroll
                for (int e = 0; e < 4; e++) sc[na][e] *= scale;
        }

        float mx0 = -1e30f, mx1 = -1e30f;
#pragma unroll
        for (int na = 0; na < 8; na++) {
            mx0 = fmaxf(mx0, fmaxf(sc[na][0], sc[na][1]));
            mx1 = fmaxf(mx1, fmaxf(sc[na][2], sc[na][3]));
        }
        mx0 = fmaxf(mx0, __shfl_xor_sync(0xffffffffu, mx0, 1));
        mx0 = fmaxf(mx0, __shfl_xor_sync(0xffffffffu, mx0, 2));
        mx1 = fmaxf(mx1, __shfl_xor_sync(0xffffffffu, mx1, 1));
        mx1 = fmaxf(mx1, __shfl_xor_sync(0xffffffffu, mx1, 2));

        float mn0 = fmaxf(mI0, mx0), mn1 = fmaxf(mI1, mx1);
        float al0 = __expf(mI0 - mn0), al1 = __expf(mI1 - mn1);
        mI0 = mn0; mI1 = mn1;

        float rs0 = 0.f, rs1 = 0.f;
#pragma unroll
        for (int na = 0; na < 8; na++) {
            sc[na][0] = __expf(sc[na][0] - mn0); rs0 += sc[na][0];
            sc[na][1] = __expf(sc[na][1] - mn0); rs0 += sc[na][1];
            sc[na][2] = __expf(sc[na][2] - mn1); rs1 += sc[na][2];
            sc[na][3] = __expf(sc[na][3] - mn1); rs1 += sc[na][3];
        }
        rs0 += __shfl_xor_sync(0xffffffffu, rs0, 1);
        rs0 += __shfl_xor_sync(0xffffffffu, rs0, 2);
        rs1 += __shfl_xor_sync(0xffffffffu, rs1, 1);
        rs1 += __shfl_xor_sync(0xffffffffu, rs1, 2);
        lI0 = lI0 * al0 + rs0;
        lI1 = lI1 * al1 + rs1;

#pragma unroll
        for (int na = 0; na < 8; na++) {
            O[na][0] *= al0; O[na][1] *= al0;
            O[na][2] *= al1; O[na][3] *= al1;
        }

#pragma unroll
        for (int kk = 0; kk < 4; kk++) {
            uint32_t pah[4], pal[4];
            split2(sc[2*kk][0],   sc[2*kk][1],   pah[0], pal[0]);
            split2(sc[2*kk][2],   sc[2*kk][3],   pah[1], pal[1]);
            split2(sc[2*kk+1][0], sc[2*kk+1][1], pah[2], pal[2]);
            split2(sc[2*kk+1][2], sc[2*kk+1][3], pah[3], pal[3]);
            uint32_t vhf[8][2], vlf[8][2];
#pragma unroll
            for (int nb = 0; nb < 4; nb++) {
                uint32_t va = sb + FVH + vsw(nb * 16 + b_tr, kk * 2 + b_kq);
                LDSM_X4(vhf[nb*2][0], vhf[nb*2][1], vhf[nb*2+1][0], vhf[nb*2+1][1], va);
                uint32_t va2 = sb + FVL + vsw(nb * 16 + b_tr, kk * 2 + b_kq);
                LDSM_X4(vlf[nb*2][0], vlf[nb*2][1], vlf[nb*2+1][0], vlf[nb*2+1][1], va2);
            }
#pragma unroll
            for (int na = 0; na < 8; na++) {
                MMA16816(O[na], pah, vhf[na]);
                MMA16816(O[na], pal, vhf[na]);
                MMA16816(O[na], pah, vlf[na]);
            }
        }
    }

    // ---- epilogue: write Y directly as bf16 hi/lo -------------------------
    const int b = bh >> 4, h = bh & 15;
    const float inv0 = 1.f / lI0, inv1 = 1.f / lI1;
    const int qr0 = q0 + wid * 16 + g;
#pragma unroll
    for (int na = 0; na < 8; na++) {
        int col = h * CHD + na * 8 + 2 * t;
        uint32_t h0, l0;
        split2(O[na][0] * inv0, O[na][1] * inv0, h0, l0);
        *(uint32_t*)(Yh + (size_t)(b*CS + qr0) * CE + col) = h0;
        *(uint32_t*)(Yl + (size_t)(b*CS + qr0) * CE + col) = l0;
        split2(O[na][2] * inv1, O[na][3] * inv1, h0, l0);
        *(uint32_t*)(Yh + (size_t)(b*CS + qr0 + 8) * CE + col) = h0;
        *(uint32_t*)(Yl + (size_t)(b*CS + qr0 + 8) * CE + col) = l0;
    }
}

// ============================== launcher ===================================
static inline void launch_cvt(const float* s, __nv_bfloat16* h, __nv_bfloat16* l, int n) {
    cvt_split<<<(n + 255) / 256, 256>>>(s, h, l, n);
}

extern "C" void kernel_launch(void* const* d_in, const int* in_sizes, int n_in,
                              void* d_out, int out_size)
{
    const float* x        = (const float*)d_in[0];
    const float* wq_down  = (const float*)d_in[1];
    const float* wk_rope  = (const float*)d_in[2];
    const float* wkv_down = (const float*)d_in[3];
    const float* wq_rope  = (const float*)d_in[4];
    const float* wq_up    = (const float*)d_in[5];
    const float* wk_up    = (const float*)d_in[6];
    const float* wv_up    = (const float*)d_in[7];
    const float* wo       = (const float*)d_in[8];
    float* out = (float*)d_out;

    __nv_bfloat16 *xh,*xl,*lath,*latl,*Yh,*Yl,*wdh,*wdl;
    __nv_bfloat16 *w3h,*w3l,*w4h,*w4l,*w5h,*w5l,*w6h,*w6l,*w7h,*w7l;
    __nv_bfloat16 *Qbh,*Qbl,*Kbh,*Kbl,*Vbh,*Vbl;
    cudaGetSymbolAddress((void**)&xh,   g_xh);   cudaGetSymbolAddress((void**)&xl,   g_xl);
    cudaGetSymbolAddress((void**)&lath, g_lath); cudaGetSymbolAddress((void**)&latl, g_latl);
    cudaGetSymbolAddress((void**)&Yh,   g_Yh);   cudaGetSymbolAddress((void**)&Yl,   g_Yl);
    cudaGetSymbolAddress((void**)&wdh,  g_wdh);  cudaGetSymbolAddress((void**)&wdl,  g_wdl);
    cudaGetSymbolAddress((void**)&w3h,  g_w3h);  cudaGetSymbolAddress((void**)&w3l,  g_w3l);
    cudaGetSymbolAddress((void**)&w4h,  g_w4h);  cudaGetSymbolAddress((void**)&w4l,  g_w4l);
    cudaGetSymbolAddress((void**)&w5h,  g_w5h);  cudaGetSymbolAddress((void**)&w5l,  g_w5l);
    cudaGetSymbolAddress((void**)&w6h,  g_w6h);  cudaGetSymbolAddress((void**)&w6l,  g_w6l);
    cudaGetSymbolAddress((void**)&w7h,  g_w7h);  cudaGetSymbolAddress((void**)&w7l,  g_w7l);
    cudaGetSymbolAddress((void**)&Qbh,  g_Qbh);  cudaGetSymbolAddress((void**)&Qbl,  g_Qbl);
    cudaGetSymbolAddress((void**)&Kbh,  g_Kbh);  cudaGetSymbolAddress((void**)&Kbl,  g_Kbl);
    cudaGetSymbolAddress((void**)&Vbh,  g_Vbh);  cudaGetSymbolAddress((void**)&Vbl,  g_Vbl);

    cudaFuncSetAttribute(gemm_ms<0>, cudaFuncAttributeMaxDynamicSharedMemorySize, GEMM_SMEM);
    cudaFuncSetAttribute(gemm_ms<1>, cudaFuncAttributeMaxDynamicSharedMemorySize, GEMM_SMEM);
    cudaFuncSetAttribute(gemm_ms<2>, cudaFuncAttributeMaxDynamicSharedMemorySize, GEMM_SMEM);
    cudaFuncSetAttribute(gemm_ms<3>, cudaFuncAttributeMaxDynamicSharedMemorySize, GEMM_SMEM);
    cudaFuncSetAttribute(gemm_ms<4>, cudaFuncAttributeMaxDynamicSharedMemorySize, GEMM_SMEM);
    cudaFuncSetAttribute(flash_attn_mma, cudaFuncAttributeMaxDynamicSharedMemorySize, FLASH_SMEM);

    // split conversions: input + weights (down-proj weights into one buffer)
    launch_cvt(x,        xh,  xl,  MTOK*CE);
    launch_cvt(wq_down,  wdh,             wdl,             CR*CE);
    launch_cvt(wk_rope,  wdh + CR*CE,     wdl + CR*CE,     CR*CE);
    launch_cvt(wkv_down, wdh + 2*CR*CE,   wdl + 2*CR*CE,   CR*CE);
    launch_cvt(wq_rope,  w3h, w3l, CE*CR);
    launch_cvt(wq_up,    w4h, w4l, CE*CR);
    launch_cvt(wk_up,    w5h, w5l, CE*CR);
    launch_cvt(wv_up,    w6h, w6l, CE*CR);
    launch_cvt(wo,       w7h, w7l, CE*CE);

    dim3 blk(256);
    // fused down projection: lat[4096, 768] = x @ [wq_down|wk_rope|wkv_down]^T
    gemm_ms<1><<<dim3(NLAT/128, MTOK/128), blk, GEMM_SMEM>>>(
        xh, xl, CE, wdh, wdl, CE, nullptr, lath, latl, NLAT, CE);

    // q rope: qlat @ wq_rope^T -> rope -> Q[:, :, :, 0:64]
    gemm_ms<2><<<dim3(CE/128, MTOK/128), blk, GEMM_SMEM>>>(
        lath, latl, NLAT, w3h, w3l, CR, nullptr, Qbh, Qbl, 0, CR);
    // q nope: qlat @ wq_up^T -> Q[:, :, :, 64:128]
    gemm_ms<3><<<dim3(CE/128, MTOK/128), blk, GEMM_SMEM>>>(
        lath, latl, NLAT, w4h, w4l, CR, nullptr, Qbh, Qbl, 0, CR);
    // k rope: krlat @ wk_up^T -> rope -> K[:, :, :, 0:64]
    gemm_ms<2><<<dim3(CE/128, MTOK/128), blk, GEMM_SMEM>>>(
        lath + CR, latl + CR, NLAT, w5h, w5l, CR, nullptr, Kbh, Kbl, 0, CR);
    // k nope: kv @ wk_up^T -> K[:, :, :, 64:128]
    gemm_ms<3><<<dim3(CE/128, MTOK/128), blk, GEMM_SMEM>>>(
        lath + 2*CR, latl + 2*CR, NLAT, w5h, w5l, CR, nullptr, Kbh, Kbl, 0, CR);
    // v: kv @ wv_up^T -> V[b,h,d,s] (transposed)
    gemm_ms<4><<<dim3(CE/128, MTOK/128), blk, GEMM_SMEM>>>(
        lath + 2*CR, latl + 2*CR, NLAT, w6h, w6l, CR, nullptr, Vbh, Vbl, 0, CR);

    // causal flash attention (tensor cores) -> Yh/Yl
    flash_attn_mma<<<dim3(CS/64, CB*CH), 128, FLASH_SMEM>>>(
        Qbh, Qbl, Kbh, Kbl, Vbh, Vbl, Yh, Yl);

    // output projection: Y @ wo^T -> out (fp32)
    gemm_ms<0><<<dim3(CE/128, MTOK/128), blk, GEMM_SMEM>>>(
        Yh, Yl, CE, w7h, w7l, CE, out, nullptr, nullptr, CE, CE);
}

// round 7
// speedup vs baseline: 2.8084x; 1.0648x over previous
#include <cuda_runtime.h>
#include <cuda_bf16.h>
#include <cstdint>
#include <math.h>

#define CB   2
#define CS   2048
#define CE   1024
#define CR   256
#define CH   16
#define CHD  64
#define CDQK 128
#define MTOK (CB*CS)   // 4096
#define NLAT 768       // 3 x 256 concatenated latents

// ---------------- scratch (no allocation allowed -> __device__ globals) ----
__device__ __nv_bfloat16 g_xh [MTOK*CE],  g_xl [MTOK*CE];
__device__ __nv_bfloat16 g_lath[MTOK*NLAT], g_latl[MTOK*NLAT];  // [q|kr|kv] latents
__device__ __nv_bfloat16 g_Yh [MTOK*CE],  g_Yl [MTOK*CE];
__device__ __nv_bfloat16 g_wdh[NLAT*CE], g_wdl[NLAT*CE];        // wq_down|wk_rope|wkv_down
__device__ __nv_bfloat16 g_w3h[CE*CR], g_w3l[CE*CR];   // wq_rope
__device__ __nv_bfloat16 g_w4h[CE*CR], g_w4l[CE*CR];   // wq_up
__device__ __nv_bfloat16 g_w5h[CE*CR], g_w5l[CE*CR];   // wk_up
__device__ __nv_bfloat16 g_w6h[CE*CR], g_w6l[CE*CR];   // wv_up
__device__ __nv_bfloat16 g_w7h[CE*CE], g_w7l[CE*CE];   // wo

// attention operand buffers (hi/lo bf16)
__device__ __nv_bfloat16 g_Qbh[CB*CH*CS*CDQK], g_Qbl[CB*CH*CS*CDQK];  // [b,h,s,128]
__device__ __nv_bfloat16 g_Kbh[CB*CH*CS*CDQK], g_Kbl[CB*CH*CS*CDQK];  // [b,h,s,128]
__device__ __nv_bfloat16 g_Vbh[CB*CH*CHD*CS],  g_Vbl[CB*CH*CHD*CS];   // [b,h,d,s]

// ===================== generic helpers =====================================
__device__ __forceinline__ uint32_t smem_to_u32(const void* p) {
    uint32_t a;
    asm("{ .reg .u64 t; cvta.to.shared.u64 t, %1; cvt.u32.u64 %0, t; }" : "=r"(a) : "l"(p));
    return a;
}

#define LDSM_X4(r0,r1,r2,r3, addr) \
    asm volatile("ldmatrix.sync.aligned.m8n8.x4.shared.b16 {%0,%1,%2,%3}, [%4];" \
        : "=r"(r0), "=r"(r1), "=r"(r2), "=r"(r3) : "r"(addr))

#define MMA16816(c, a, b) \
    asm volatile("mma.sync.aligned.m16n8k16.row.col.f32.bf16.bf16.f32 " \
        "{%0,%1,%2,%3}, {%4,%5,%6,%7}, {%8,%9}, {%0,%1,%2,%3};" \
        : "+f"((c)[0]), "+f"((c)[1]), "+f"((c)[2]), "+f"((c)[3]) \
        : "r"((a)[0]), "r"((a)[1]), "r"((a)[2]), "r"((a)[3]), "r"((b)[0]), "r"((b)[1]))

// split two floats into packed bf16 hi pair + residual lo pair
__device__ __forceinline__ void split2(float a, float b, uint32_t& hi, uint32_t& lo) {
    __nv_bfloat16 ha = __float2bfloat16(a), hb = __float2bfloat16(b);
    float ra = a - __bfloat162float(ha);
    float rb = b - __bfloat162float(hb);
    __nv_bfloat162 hh; hh.x = ha; hh.y = hb;
    hi = *(uint32_t*)&hh;
    __nv_bfloat162 ll = __floats2bfloat162_rn(ra, rb);
    lo = *(uint32_t*)&ll;
}

// ===================== split-fp32 convert ==================================
__global__ void cvt_split(const float* __restrict__ src,
                          __nv_bfloat16* __restrict__ hi, __nv_bfloat16* __restrict__ lo, int n)
{
    int i = blockIdx.x * blockDim.x + threadIdx.x;
    if (i < n) {
        float v = src[i];
        __nv_bfloat16 h = __float2bfloat16(v);
        hi[i] = h;
        lo[i] = __float2bfloat16(v - __bfloat162float(h));
    }
}

// ============= tensor-core split-bf16 GEMM NT with fused epilogues =========
// C[M,N] = A[M,K] * B[N,K]^T, A/B bf16 hi+lo. CTA tile 128x128, 256 threads.
// MODE 0: fp32 store; MODE 1: split bf16 hi/lo; MODE 2: rope -> Q/K rope half
// MODE 3: nope -> Q/K [64:128]; MODE 4: V transposed [b,h,d,s]
#define GEMM_SMEM 32768
#define MS_AH 0
#define MS_AL 8192
#define MS_BH 16384
#define MS_BL 24576
#define ROPE_L 0.41524101186109f   // log2(10000)/32

__device__ __forceinline__ uint32_t msw(int row, int c) {
    return (uint32_t)(row * 64 + ((c ^ ((row >> 1) & 3)) << 4));
}

template<int MODE>
__global__ __launch_bounds__(256) void gemm_ms(
    const __nv_bfloat16* __restrict__ Ah, const __nv_bfloat16* __restrict__ Al, int lda,
    const __nv_bfloat16* __restrict__ Bh, const __nv_bfloat16* __restrict__ Bl, int ldb,
    float* __restrict__ Cf, __nv_bfloat16* __restrict__ Ch, __nv_bfloat16* __restrict__ Cl,
    int ldc, int K)
{
    extern __shared__ char smem[];
    const int tid = threadIdx.x, wid = tid >> 5, lid = tid & 31;
    const int m0 = blockIdx.y * 128, n0 = blockIdx.x * 128;
    uint32_t sb = smem_to_u32(smem);

    const int mw = wid & 3, nw = wid >> 2;
    const int a_tr = (lid & 7) + ((lid >> 3) & 1) * 8;
    const int a_kq = lid >> 4;
    const int b_tr = (lid & 7) + (lid >> 4) * 8;
    const int b_kq = (lid >> 3) & 1;

    float acc[2][8][4];
#pragma unroll
    for (int i = 0; i < 2; i++)
#pragma unroll
        for (int j = 0; j < 8; j++)
#pragma unroll
            for (int q = 0; q < 4; q++) acc[i][j][q] = 0.f;

    const int prow = tid >> 2, pc = tid & 3;
    uint4 ra[2], rl[2], rb[2], rm[2];
#pragma unroll
    for (int it = 0; it < 2; it++) {
        int row = it * 64 + prow;
        size_t ga = (size_t)(m0 + row) * lda + pc * 8;
        size_t gb = (size_t)(n0 + row) * ldb + pc * 8;
        ra[it] = *(const uint4*)(Ah + ga);
        rl[it] = *(const uint4*)(Al + ga);
        rb[it] = *(const uint4*)(Bh + gb);
        rm[it] = *(const uint4*)(Bl + gb);
    }

    for (int k0 = 0; k0 < K; k0 += 32) {
        __syncthreads();
#pragma unroll
        for (int it = 0; it < 2; it++) {
            int row = it * 64 + prow;
            uint32_t so = msw(row, pc);
            *(uint4*)(smem + MS_AH + so) = ra[it];
            *(uint4*)(smem + MS_AL + so) = rl[it];
            *(uint4*)(smem + MS_BH + so) = rb[it];
            *(uint4*)(smem + MS_BL + so) = rm[it];
        }
        __syncthreads();
        if (k0 + 32 < K) {
#pragma unroll
            for (int it = 0; it < 2; it++) {
                int row = it * 64 + prow;
                size_t ga = (size_t)(m0 + row) * lda + k0 + 32 + pc * 8;
                size_t gb = (size_t)(n0 + row) * ldb + k0 + 32 + pc * 8;
                ra[it] = *(const uint4*)(Ah + ga);
                rl[it] = *(const uint4*)(Al + ga);
                rb[it] = *(const uint4*)(Bh + gb);
                rm[it] = *(const uint4*)(Bl + gb);
            }
        }

#pragma unroll
        for (int ks = 0; ks < 2; ks++) {
            uint32_t ah[2][4], al[2][4], bh[8][2], bl[8][2];
#pragma unroll
            for (int ma = 0; ma < 2; ma++) {
                int row = mw * 32 + ma * 16 + a_tr;
                int c = ks * 2 + a_kq;
                uint32_t ad = sb + MS_AH + msw(row, c);
                LDSM_X4(ah[ma][0], ah[ma][1], ah[ma][2], ah[ma][3], ad);
                uint32_t ad2 = sb + MS_AL + msw(row, c);
                LDSM_X4(al[ma][0], al[ma][1], al[ma][2], al[ma][3], ad2);
            }
#pragma unroll
            for (int nb = 0; nb < 4; nb++) {
                int row = nw * 64 + nb * 16 + b_tr;
                int c = ks * 2 + b_kq;
                uint32_t bd = sb + MS_BH + msw(row, c);
                LDSM_X4(bh[nb*2][0], bh[nb*2][1], bh[nb*2+1][0], bh[nb*2+1][1], bd);
                uint32_t bd2 = sb + MS_BL + msw(row, c);
                LDSM_X4(bl[nb*2][0], bl[nb*2][1], bl[nb*2+1][0], bl[nb*2+1][1], bd2);
            }
#pragma unroll
            for (int ma = 0; ma < 2; ma++)
#pragma unroll
                for (int na = 0; na < 8; na++) {
                    MMA16816(acc[ma][na], ah[ma], bh[na]);
                    MMA16816(acc[ma][na], ah[ma], bl[na]);
                    MMA16816(acc[ma][na], al[ma], bh[na]);
                }
        }
    }

    // ----------------------- fused epilogues -------------------------------
    const int g = lid >> 2, t4 = lid & 3;

    if (MODE == 0) {
#pragma unroll
        for (int ma = 0; ma < 2; ma++) {
            int row0 = m0 + mw * 32 + ma * 16 + g;
#pragma unroll
            for (int na = 0; na < 8; na++) {
                int col = n0 + nw * 64 + na * 8 + t4 * 2;
                *(float2*)(Cf + (size_t)row0 * ldc + col) =
                    make_float2(acc[ma][na][0], acc[ma][na][1]);
                *(float2*)(Cf + (size_t)(row0 + 8) * ldc + col) =
                    make_float2(acc[ma][na][2], acc[ma][na][3]);
            }
        }
    } else if (MODE == 1) {
#pragma unroll
        for (int ma = 0; ma < 2; ma++) {
            int row0 = m0 + mw * 32 + ma * 16 + g;
#pragma unroll
            for (int na = 0; na < 8; na++) {
                int col = n0 + nw * 64 + na * 8 + t4 * 2;
                uint32_t h0, l0;
                split2(acc[ma][na][0], acc[ma][na][1], h0, l0);
                *(uint32_t*)(Ch + (size_t)row0 * ldc + col) = h0;
                *(uint32_t*)(Cl + (size_t)row0 * ldc + col) = l0;
                split2(acc[ma][na][2], acc[ma][na][3], h0, l0);
                *(uint32_t*)(Ch + (size_t)(row0 + 8) * ldc + col) = h0;
                *(uint32_t*)(Cl + (size_t)(row0 + 8) * ldc + col) = l0;
            }
        }
    } else if (MODE == 2) {
        const int hq = (n0 + nw * 64) >> 6;
#pragma unroll
        for (int ma = 0; ma < 2; ma++) {
            int r0 = m0 + mw * 32 + ma * 16 + g;
            int b = r0 >> 11;
            size_t bb = (size_t)((b << 4) + hq) * CS * CDQK;
#pragma unroll
            for (int rh = 0; rh < 2; rh++) {
                int s = (r0 + rh * 8) & (CS - 1);
                size_t base = bb + (size_t)s * CDQK;
                float fs = (float)s;
#pragma unroll
                for (int na = 0; na < 4; na++) {
                    int e = rh * 2;
                    int i0 = na * 8 + t4 * 2;
                    float x1a = acc[ma][na][e],     x1b = acc[ma][na][e+1];
                    float x2a = acc[ma][na+4][e],   x2b = acc[ma][na+4][e+1];
                    float sn0, cs0, sn1, cs1;
                    sincosf(fs * exp2f(-(float)i0 * ROPE_L), &sn0, &cs0);
                    sincosf(fs * exp2f(-(float)(i0+1) * ROPE_L), &sn1, &cs1);
                    float o1a = x1a*cs0 - x2a*sn0, o1b = x1b*cs1 - x2b*sn1;
                    float o2a = x2a*cs0 + x1a*sn0, o2b = x2b*cs1 + x1b*sn1;
                    uint32_t h0, l0;
                    split2(o1a, o1b, h0, l0);
                    *(uint32_t*)(Ch + base + i0) = h0;
                    *(uint32_t*)(Cl + base + i0) = l0;
                    split2(o2a, o2b, h0, l0);
                    *(uint32_t*)(Ch + base + 32 + i0) = h0;
                    *(uint32_t*)(Cl + base + 32 + i0) = l0;
                }
            }
        }
    } else if (MODE == 3) {
        const int hq = (n0 + nw * 64) >> 6;
#pragma unroll
        for (int ma = 0; ma < 2; ma++) {
            int r0 = m0 + mw * 32 + ma * 16 + g;
            int b = r0 >> 11;
            size_t bb = (size_t)((b << 4) + hq) * CS * CDQK;
#pragma unroll
            for (int rh = 0; rh < 2; rh++) {
                int s = (r0 + rh * 8) & (CS - 1);
                size_t base = bb + (size_t)s * CDQK + 64;
#pragma unroll
                for (int na = 0; na < 8; na++) {
                    int d0 = na * 8 + t4 * 2;
                    uint32_t h0, l0;
                    split2(acc[ma][na][rh*2], acc[ma][na][rh*2+1], h0, l0);
                    *(uint32_t*)(Ch + base + d0) = h0;
                    *(uint32_t*)(Cl + base + d0) = l0;
                }
            }
        }
    } else {
        const int hq = (n0 + nw * 64) >> 6;
#pragma unroll
        for (int ma = 0; ma < 2; ma++) {
            int r0 = m0 + mw * 32 + ma * 16 + g;
            int b = r0 >> 11;
            size_t bb = (size_t)((b << 4) + hq) * CHD;
#pragma unroll
            for (int rh = 0; rh < 2; rh++) {
                int s = (r0 + rh * 8) & (CS - 1);
#pragma unroll
                for (int na = 0; na < 8; na++) {
#pragma unroll
                    for (int j = 0; j < 2; j++) {
                        int d = na * 8 + t4 * 2 + j;
                        float v = acc[ma][na][rh*2 + j];
                        __nv_bfloat16 hv = __float2bfloat16(v);
                        size_t o = (bb + d) * CS + s;
                        Ch[o] = hv;
                        Cl[o] = __float2bfloat16(v - __bfloat162float(hv));
                    }
                }
            }
        }
    }
}

// =================== causal flash attention (mma.sync bf16) ================
// BQ=128, 256 threads (8 warps x 16 q-rows); K/V tiles 64 wide.
// Q,K: [b,h,s,128] hi/lo; V: [b,h,d,s] hi/lo; out: Yh/Yl [b,s,E] bf16 hi/lo
#define FQH 0
#define FQL 32768
#define FKH 65536
#define FKL 81920
#define FVH 98304
#define FVL 106496
#define FLASH_SMEM 114688

__device__ __forceinline__ uint32_t fsw(int row, int chunk) {
    return (uint32_t)(row * 256 + ((chunk >> 3) << 7) + (((chunk & 7) ^ (row & 7)) << 4));
}
__device__ __forceinline__ uint32_t vsw(int row, int chunk) {
    return (uint32_t)(row * 128 + ((chunk ^ (row & 7)) << 4));
}

__global__ __launch_bounds__(256) void flash_attn_mma(
    const __nv_bfloat16* __restrict__ Qh, const __nv_bfloat16* __restrict__ Ql,
    const __nv_bfloat16* __restrict__ Kh, const __nv_bfloat16* __restrict__ Kl,
    const __nv_bfloat16* __restrict__ Vh, const __nv_bfloat16* __restrict__ Vl,
    __nv_bfloat16* __restrict__ Yh, __nv_bfloat16* __restrict__ Yl)
{
    extern __shared__ char smem[];
    uint32_t sb = smem_to_u32(smem);
    const int tid = threadIdx.x, wid = tid >> 5, lid = tid & 31;
    const int qb = blockIdx.x, bh = blockIdx.y;
    const int q0 = qb * 128;
    const int g = lid >> 2, t = lid & 3;

    const __nv_bfloat16* Qhg = Qh + (size_t)bh * CS * CDQK;
    const __nv_bfloat16* Qlg = Ql + (size_t)bh * CS * CDQK;
    const __nv_bfloat16* Khg = Kh + (size_t)bh * CS * CDQK;
    const __nv_bfloat16* Klg = Kl + (size_t)bh * CS * CDQK;
    const __nv_bfloat16* Vhg = Vh + (size_t)bh * CHD * CS;
    const __nv_bfloat16* Vlg = Vl + (size_t)bh * CHD * CS;

    // load Q tile [128 rows][128 d] hi/lo
#pragma unroll
    for (int it = 0; it < 8; it++) {
        int i = it * 256 + tid;
        int row = i >> 4, ch = i & 15;
        size_t off = (size_t)(q0 + row) * CDQK + ch * 8;
        *(uint4*)(smem + FQH + fsw(row, ch)) = *(const uint4*)(Qhg + off);
        *(uint4*)(smem + FQL + fsw(row, ch)) = *(const uint4*)(Qlg + off);
    }

    const int a_tr = (lid & 7) + ((lid >> 3) & 1) * 8;
    const int a_kq = lid >> 4;
    const int b_tr = (lid & 7) + (lid >> 4) * 8;
    const int b_kq = (lid >> 3) & 1;

    float O[8][4];
#pragma unroll
    for (int na = 0; na < 8; na++)
#pragma unroll
        for (int e = 0; e < 4; e++) O[na][e] = 0.f;
    float mI0 = -1e30f, mI1 = -1e30f, lI0 = 0.f, lI1 = 0.f;
    const float scale = 0.08838834764831845f;

    const int qw_last = q0 + wid * 16 + 15;   // this warp's last q row
    const int nkb = 2 * qb + 2;               // k-tiles covering rows < q0+128

    for (int kb = 0; kb < nkb; kb++) {
        const int k0 = kb * 64;
        __syncthreads();
#pragma unroll
        for (int it = 0; it < 4; it++) {
            int i = it * 256 + tid;
            int row = i >> 4, ch = i & 15;
            size_t off = (size_t)(k0 + row) * CDQK + ch * 8;
            *(uint4*)(smem + FKH + fsw(row, ch)) = *(const uint4*)(Khg + off);
            *(uint4*)(smem + FKL + fsw(row, ch)) = *(const uint4*)(Klg + off);
        }
#pragma unroll
        for (int it = 0; it < 2; it++) {
            int i = it * 256 + tid;
            int row = i >> 3, ch = i & 7;
            size_t off = (size_t)row * CS + k0 + ch * 8;
            *(uint4*)(smem + FVH + vsw(row, ch)) = *(const uint4*)(Vhg + off);
            *(uint4*)(smem + FVL + vsw(row, ch)) = *(const uint4*)(Vlg + off);
        }
        __syncthreads();

        if (k0 > qw_last) continue;   // fully-masked tile for this warp: identity

        float sc[8][4];
#pragma unroll
        for (int na = 0; na < 8; na++)
#pragma unroll
            for (int e = 0; e < 4; e++) sc[na][e] = 0.f;

#pragma unroll
        for (int ks = 0; ks < 8; ks++) {
            uint32_t ah[4], al[4], khf[8][2], klf[8][2];
            uint32_t qa = sb + FQH + fsw(wid * 16 + a_tr, ks * 2 + a_kq);
            LDSM_X4(ah[0], ah[1], ah[2], ah[3], qa);
            uint32_t qa2 = sb + FQL + fsw(wid * 16 + a_tr, ks * 2 + a_kq);
            LDSM_X4(al[0], al[1], al[2], al[3], qa2);
#pragma unroll
            for (int nb = 0; nb < 4; nb++) {
                uint32_t ka = sb + FKH + fsw(nb * 16 + b_tr, ks * 2 + b_kq);
                LDSM_X4(khf[nb*2][0], khf[nb*2][1], khf[nb*2+1][0], khf[nb*2+1][1], ka);
                uint32_t ka2 = sb + FKL + fsw(nb * 16 + b_tr, ks * 2 + b_kq);
                LDSM_X4(klf[nb*2][0], klf[nb*2][1], klf[nb*2+1][0], klf[nb*2+1][1], ka2);
            }
#pragma unroll
            for (int na = 0; na < 8; na++) {
                MMA16816(sc[na], ah, khf[na]);
                MMA16816(sc[na], ah, klf[na]);
                MMA16816(sc[na], al, khf[na]);
            }
        }

        // scale + causal mask (diagonal tiles only)
        if (k0 + 63 > qw_last - 15) {
#pragma unroll
            for (int na = 0; na < 8; na++)
#pragma unroll
                for (int e = 0; e < 4; e++) {
                    int qr = q0 + wid * 16 + g + ((e >> 1) << 3);
                    int kc = k0 + na * 8 + 2 * t + (e & 1);
                    sc[na][e] = (kc > qr) ? -1e30f : sc[na][e] * scale;
                }
        } else {
#pragma unroll
            for (int na = 0; na < 8; na++)
#pragma unroll
                for (int e = 0; e < 4; e++) sc[na][e] *= scale;
        }

        float mx0 = -1e30f, mx1 = -1e30f;
#pragma unroll
        for (int na = 0; na < 8; na++) {
            mx0 = fmaxf(mx0, fmaxf(sc[na][0], sc[na][1]));
            mx1 = fmaxf(mx1, fmaxf(sc[na][2], sc[na][3]));
        }
        mx0 = fmaxf(mx0, __shfl_xor_sync(0xffffffffu, mx0, 1));
        mx0 = fmaxf(mx0, __shfl_xor_sync(0xffffffffu, mx0, 2));
        mx1 = fmaxf(mx1, __shfl_xor_sync(0xffffffffu, mx1, 1));
        mx1 = fmaxf(mx1, __shfl_xor_sync(0xffffffffu, mx1, 2));

        float mn0 = fmaxf(mI0, mx0), mn1 = fmaxf(mI1, mx1);
        float al0 = __expf(mI0 - mn0), al1 = __expf(mI1 - mn1);
        mI0 = mn0; mI1 = mn1;

        float rs0 = 0.f, rs1 = 0.f;
#pragma unroll
        for (int na = 0; na < 8; na++) {
            sc[na][0] = __expf(sc[na][0] - mn0); rs0 += sc[na][0];
            sc[na][1] = __expf(sc[na][1] - mn0); rs0 += sc[na][1];
            sc[na][2] = __expf(sc[na][2] - mn1); rs1 += sc[na][2];
            sc[na][3] = __expf(sc[na][3] - mn1); rs1 += sc[na][3];
        }
        rs0 += __shfl_xor_sync(0xffffffffu, rs0, 1);
        rs0 += __shfl_xor_sync(0xffffffffu, rs0, 2);
        rs1 += __shfl_xor_sync(0xffffffffu, rs1, 1);
        rs1 += __shfl_xor_sync(0xffffffffu, rs1, 2);
        lI0 = lI0 * al0 + rs0;
        lI1 = lI1 * al1 + rs1;

#pragma unroll
        for (int na = 0; na < 8; na++) {
            O[na][0] *= al0; O[na][1] *= al0;
            O[na][2] *= al1; O[na][3] *= al1;
        }

#pragma unroll
        for (int kk = 0; kk < 4; kk++) {
            uint32_t pah[4], pal[4];
            split2(sc[2*kk][0],   sc[2*kk][1],   pah[0], pal[0]);
            split2(sc[2*kk][2],   sc[2*kk][3],   pah[1], pal[1]);
            split2(sc[2*kk+1][0], sc[2*kk+1][1], pah[2], pal[2]);
            split2(sc[2*kk+1][2], sc[2*kk+1][3], pah[3], pal[3]);
            uint32_t vhf[8][2], vlf[8][2];
#pragma unroll
            for (int nb = 0; nb < 4; nb++) {
                uint32_t va = sb + FVH + vsw(nb * 16 + b_tr, kk * 2 + b_kq);
                LDSM_X4(vhf[nb*2][0], vhf[nb*2][1], vhf[nb*2+1][0], vhf[nb*2+1][1], va);
                uint32_t va2 = sb + FVL + vsw(nb * 16 + b_tr, kk * 2 + b_kq);
                LDSM_X4(vlf[nb*2][0], vlf[nb*2][1], vlf[nb*2+1][0], vlf[nb*2+1][1], va2);
            }
#pragma unroll
            for (int na = 0; na < 8; na++) {
                MMA16816(O[na], pah, vhf[na]);
                MMA16816(O[na], pal, vhf[na]);
                MMA16816(O[na], pah, vlf[na]);
            }
        }
    }

    // ---- epilogue: write Y directly as bf16 hi/lo -------------------------
    const int b = bh >> 4, h = bh & 15;
    const float inv0 = 1.f / lI0, inv1 = 1.f / lI1;
    const int qr0 = q0 + wid * 16 + g;
#pragma unroll
    for (int na = 0; na < 8; na++) {
        int col = h * CHD + na * 8 + 2 * t;
        uint32_t h0, l0;
        split2(O[na][0] * inv0, O[na][1] * inv0, h0, l0);
        *(uint32_t*)(Yh + (size_t)(b*CS + qr0) * CE + col) = h0;
        *(uint32_t*)(Yl + (size_t)(b*CS + qr0) * CE + col) = l0;
        split2(O[na][2] * inv1, O[na][3] * inv1, h0, l0);
        *(uint32_t*)(Yh + (size_t)(b*CS + qr0 + 8) * CE + col) = h0;
        *(uint32_t*)(Yl + (size_t)(b*CS + qr0 + 8) * CE + col) = l0;
    }
}

// ============================== launcher ===================================
static inline void launch_cvt(const float* s, __nv_bfloat16* h, __nv_bfloat16* l, int n) {
    cvt_split<<<(n + 255) / 256, 256>>>(s, h, l, n);
}

extern "C" void kernel_launch(void* const* d_in, const int* in_sizes, int n_in,
                              void* d_out, int out_size)
{
    const float* x        = (const float*)d_in[0];
    const float* wq_down  = (const float*)d_in[1];
    const float* wk_rope  = (const float*)d_in[2];
    const float* wkv_down = (const float*)d_in[3];
    const float* wq_rope  = (const float*)d_in[4];
    const float* wq_up    = (const float*)d_in[5];
    const float* wk_up    = (const float*)d_in[6];
    const float* wv_up    = (const float*)d_in[7];
    const float* wo       = (const float*)d_in[8];
    float* out = (float*)d_out;

    __nv_bfloat16 *xh,*xl,*lath,*latl,*Yh,*Yl,*wdh,*wdl;
    __nv_bfloat16 *w3h,*w3l,*w4h,*w4l,*w5h,*w5l,*w6h,*w6l,*w7h,*w7l;
    __nv_bfloat16 *Qbh,*Qbl,*Kbh,*Kbl,*Vbh,*Vbl;
    cudaGetSymbolAddress((void**)&xh,   g_xh);   cudaGetSymbolAddress((void**)&xl,   g_xl);
    cudaGetSymbolAddress((void**)&lath, g_lath); cudaGetSymbolAddress((void**)&latl, g_latl);
    cudaGetSymbolAddress((void**)&Yh,   g_Yh);   cudaGetSymbolAddress((void**)&Yl,   g_Yl);
    cudaGetSymbolAddress((void**)&wdh,  g_wdh);  cudaGetSymbolAddress((void**)&wdl,  g_wdl);
    cudaGetSymbolAddress((void**)&w3h,  g_w3h);  cudaGetSymbolAddress((void**)&w3l,  g_w3l);
    cudaGetSymbolAddress((void**)&w4h,  g_w4h);  cudaGetSymbolAddress((void**)&w4l,  g_w4l);
    cudaGetSymbolAddress((void**)&w5h,  g_w5h);  cudaGetSymbolAddress((void**)&w5l,  g_w5l);
    cudaGetSymbolAddress((void**)&w6h,  g_w6h);  cudaGetSymbolAddress((void**)&w6l,  g_w6l);
    cudaGetSymbolAddress((void**)&w7h,  g_w7h);  cudaGetSymbolAddress((void**)&w7l,  g_w7l);
    cudaGetSymbolAddress((void**)&Qbh,  g_Qbh);  cudaGetSymbolAddress((void**)&Qbl,  g_Qbl);
    cudaGetSymbolAddress((void**)&Kbh,  g_Kbh);  cudaGetSymbolAddress((void**)&Kbl,  g_Kbl);
    cudaGetSymbolAddress((void**)&Vbh,  g_Vbh);  cudaGetSymbolAddress((void**)&Vbl,  g_Vbl);

    cudaFuncSetAttribute(gemm_ms<0>, cudaFuncAttributeMaxDynamicSharedMemorySize, GEMM_SMEM);
    cudaFuncSetAttribute(gemm_ms<1>, cudaFuncAttributeMaxDynamicSharedMemorySize, GEMM_SMEM);
    cudaFuncSetAttribute(gemm_ms<2>, cudaFuncAttributeMaxDynamicSharedMemorySize, GEMM_SMEM);
    cudaFuncSetAttribute(gemm_ms<3>, cudaFuncAttributeMaxDynamicSharedMemorySize, GEMM_SMEM);
    cudaFuncSetAttribute(gemm_ms<4>, cudaFuncAttributeMaxDynamicSharedMemorySize, GEMM_SMEM);
    cudaFuncSetAttribute(flash_attn_mma, cudaFuncAttributeMaxDynamicSharedMemorySize, FLASH_SMEM);

    // split conversions: input + weights (down-proj weights into one buffer)
    launch_cvt(x,        xh,  xl,  MTOK*CE);
    launch_cvt(wq_down,  wdh,             wdl,             CR*CE);
    launch_cvt(wk_rope,  wdh + CR*CE,     wdl + CR*CE,     CR*CE);
    launch_cvt(wkv_down, wdh + 2*CR*CE,   wdl + 2*CR*CE,   CR*CE);
    launch_cvt(wq_rope,  w3h, w3l, CE*CR);
    launch_cvt(wq_up,    w4h, w4l, CE*CR);
    launch_cvt(wk_up,    w5h, w5l, CE*CR);
    launch_cvt(wv_up,    w6h, w6l, CE*CR);
    launch_cvt(wo,       w7h, w7l, CE*CE);

    dim3 blk(256);
    // fused down projection: lat[4096, 768] = x @ [wq_down|wk_rope|wkv_down]^T
    gemm_ms<1><<<dim3(NLAT/128, MTOK/128), blk, GEMM_SMEM>>>(
        xh, xl, CE, wdh, wdl, CE, nullptr, lath, latl, NLAT, CE);

    // q rope
    gemm_ms<2><<<dim3(CE/128, MTOK/128), blk, GEMM_SMEM>>>(
        lath, latl, NLAT, w3h, w3l, CR, nullptr, Qbh, Qbl, 0, CR);
    // q nope
    gemm_ms<3><<<dim3(CE/128, MTOK/128), blk, GEMM_SMEM>>>(
        lath, latl, NLAT, w4h, w4l, CR, nullptr, Qbh, Qbl, 0, CR);
    // k rope
    gemm_ms<2><<<dim3(CE/128, MTOK/128), blk, GEMM_SMEM>>>(
        lath + CR, latl + CR, NLAT, w5h, w5l, CR, nullptr, Kbh, Kbl, 0, CR);
    // k nope
    gemm_ms<3><<<dim3(CE/128, MTOK/128), blk, GEMM_SMEM>>>(
        lath + 2*CR, latl + 2*CR, NLAT, w5h, w5l, CR, nullptr, Kbh, Kbl, 0, CR);
    // v (transposed)
    gemm_ms<4><<<dim3(CE/128, MTOK/128), blk, GEMM_SMEM>>>(
        lath + 2*CR, latl + 2*CR, NLAT, w6h, w6l, CR, nullptr, Vbh, Vbl, 0, CR);

    // causal flash attention (BQ=128, tensor cores) -> Yh/Yl
    flash_attn_mma<<<dim3(CS/128, CB*CH), 256, FLASH_SMEM>>>(
        Qbh, Qbl, Kbh, Kbl, Vbh, Vbl, Yh, Yl);

    // output projection: Y @ wo^T -> out (fp32)
    gemm_ms<0><<<dim3(CE/128, MTOK/128), blk, GEMM_SMEM>>>(
        Yh, Yl, CE, w7h, w7l, CE, out, nullptr, nullptr, CE, CE);
}

// round 8
// speedup vs baseline: 3.0907x; 1.1005x over previous
#include <cuda_runtime.h>
#include <cuda_bf16.h>
#include <cstdint>
#include <math.h>

#define CB   2
#define CS   2048
#define CE   1024
#define CR   256
#define CH   16
#define CHD  64
#define CDQK 128
#define MTOK (CB*CS)   // 4096
#define NLAT 768       // 3 x 256 concatenated latents

// ---------------- scratch (no allocation allowed -> __device__ globals) ----
__device__ __nv_bfloat16 g_xh [MTOK*CE],  g_xl [MTOK*CE];
__device__ __nv_bfloat16 g_lath[MTOK*NLAT], g_latl[MTOK*NLAT];
__device__ __nv_bfloat16 g_Yh [MTOK*CE],  g_Yl [MTOK*CE];
__device__ __nv_bfloat16 g_wdh[NLAT*CE], g_wdl[NLAT*CE];
__device__ __nv_bfloat16 g_w3h[CE*CR], g_w3l[CE*CR];   // wq_rope
__device__ __nv_bfloat16 g_w4h[CE*CR], g_w4l[CE*CR];   // wq_up
__device__ __nv_bfloat16 g_w5h[CE*CR], g_w5l[CE*CR];   // wk_up
__device__ __nv_bfloat16 g_w6h[CE*CR], g_w6l[CE*CR];   // wv_up
__device__ __nv_bfloat16 g_w7h[CE*CE], g_w7l[CE*CE];   // wo

__device__ __nv_bfloat16 g_Qbh[CB*CH*CS*CDQK], g_Qbl[CB*CH*CS*CDQK];  // [b,h,s,128]
__device__ __nv_bfloat16 g_Kbh[CB*CH*CS*CDQK], g_Kbl[CB*CH*CS*CDQK];  // [b,h,s,128]
__device__ __nv_bfloat16 g_Vbh[CB*CH*CHD*CS],  g_Vbl[CB*CH*CHD*CS];   // [b,h,d,s]

// ===================== generic helpers =====================================
__device__ __forceinline__ uint32_t smem_to_u32(const void* p) {
    uint32_t a;
    asm("{ .reg .u64 t; cvta.to.shared.u64 t, %1; cvt.u32.u64 %0, t; }" : "=r"(a) : "l"(p));
    return a;
}

#define LDSM_X4(r0,r1,r2,r3, addr) \
    asm volatile("ldmatrix.sync.aligned.m8n8.x4.shared.b16 {%0,%1,%2,%3}, [%4];" \
        : "=r"(r0), "=r"(r1), "=r"(r2), "=r"(r3) : "r"(addr))

#define MMA16816(c, a, b) \
    asm volatile("mma.sync.aligned.m16n8k16.row.col.f32.bf16.bf16.f32 " \
        "{%0,%1,%2,%3}, {%4,%5,%6,%7}, {%8,%9}, {%0,%1,%2,%3};" \
        : "+f"((c)[0]), "+f"((c)[1]), "+f"((c)[2]), "+f"((c)[3]) \
        : "r"((a)[0]), "r"((a)[1]), "r"((a)[2]), "r"((a)[3]), "r"((b)[0]), "r"((b)[1]))

#define CP_ASYNC16(dst, src) \
    asm volatile("cp.async.cg.shared.global [%0], [%1], 16;" :: "r"(dst), "l"(src))
#define CP_COMMIT() asm volatile("cp.async.commit_group;" ::: "memory")
#define CP_WAIT(n)  asm volatile("cp.async.wait_group %0;" :: "n"(n) : "memory")

__device__ __forceinline__ void split2(float a, float b, uint32_t& hi, uint32_t& lo) {
    __nv_bfloat16 ha = __float2bfloat16(a), hb = __float2bfloat16(b);
    float ra = a - __bfloat162float(ha);
    float rb = b - __bfloat162float(hb);
    __nv_bfloat162 hh; hh.x = ha; hh.y = hb;
    hi = *(uint32_t*)&hh;
    __nv_bfloat162 ll = __floats2bfloat162_rn(ra, rb);
    lo = *(uint32_t*)&ll;
}

// ===================== split-fp32 convert ==================================
__global__ void cvt_split(const float* __restrict__ src,
                          __nv_bfloat16* __restrict__ hi, __nv_bfloat16* __restrict__ lo, int n)
{
    int i = blockIdx.x * blockDim.x + threadIdx.x;
    if (i < n) {
        float v = src[i];
        __nv_bfloat16 h = __float2bfloat16(v);
        hi[i] = h;
        lo[i] = __float2bfloat16(v - __bfloat162float(h));
    }
}

// ============= tensor-core split-bf16 GEMM NT, cp.async 2-stage ============
// C[M,N] = A[M,K] * B[N,K]^T. CTA tile 128x128, 256 threads.
// MODE 0: fp32; 1: split hi/lo; 2: rope Q/K; 3: nope Q/K; 4: V transposed
#define GEMM_SMEM 65536
#define MS_AH 0
#define MS_AL 8192
#define MS_BH 16384
#define MS_BL 24576
#define MS_STAGE 32768
#define ROPE_L 0.41524101186109f

__device__ __forceinline__ uint32_t msw(int row, int c) {
    return (uint32_t)(row * 64 + ((c ^ ((row >> 1) & 3)) << 4));
}

template<int MODE>
__global__ __launch_bounds__(256) void gemm_ms(
    const __nv_bfloat16* __restrict__ Ah, const __nv_bfloat16* __restrict__ Al, int lda,
    const __nv_bfloat16* __restrict__ Bh, const __nv_bfloat16* __restrict__ Bl, int ldb,
    float* __restrict__ Cf, __nv_bfloat16* __restrict__ Ch, __nv_bfloat16* __restrict__ Cl,
    int ldc, int K)
{
    extern __shared__ char smem[];
    const int tid = threadIdx.x, wid = tid >> 5, lid = tid & 31;
    const int m0 = blockIdx.y * 128, n0 = blockIdx.x * 128;
    uint32_t sb = smem_to_u32(smem);

    const int mw = wid & 3, nw = wid >> 2;
    const int a_tr = (lid & 7) + ((lid >> 3) & 1) * 8;
    const int a_kq = lid >> 4;
    const int b_tr = (lid & 7) + (lid >> 4) * 8;
    const int b_kq = (lid >> 3) & 1;

    float acc[2][8][4];
#pragma unroll
    for (int i = 0; i < 2; i++)
#pragma unroll
        for (int j = 0; j < 8; j++)
#pragma unroll
            for (int q = 0; q < 4; q++) acc[i][j][q] = 0.f;

    // cp.async loader: per stage, per array: 128 rows x 64B = 512 chunks
    auto issue = [&](int stg, int k0) {
        uint32_t base = sb + stg * MS_STAGE;
#pragma unroll
        for (int it = 0; it < 2; it++) {
            int ch = it * 256 + tid;
            int row = ch >> 2, c = ch & 3;
            uint32_t so = msw(row, c);
            size_t ga = (size_t)(m0 + row) * lda + k0 + c * 8;
            size_t gb = (size_t)(n0 + row) * ldb + k0 + c * 8;
            CP_ASYNC16(base + MS_AH + so, Ah + ga);
            CP_ASYNC16(base + MS_AL + so, Al + ga);
            CP_ASYNC16(base + MS_BH + so, Bh + gb);
            CP_ASYNC16(base + MS_BL + so, Bl + gb);
        }
        CP_COMMIT();
    };

    issue(0, 0);
    int st = 0;
    for (int k0 = 0; k0 < K; k0 += 32) {
        __syncthreads();   // all readers of stage st^1 (prev iter) done
        if (k0 + 32 < K) { issue(st ^ 1, k0 + 32); CP_WAIT(1); }
        else             { CP_WAIT(0); }
        __syncthreads();   // stage st visible to all

        uint32_t base = sb + st * MS_STAGE;
#pragma unroll
        for (int ks = 0; ks < 2; ks++) {
            uint32_t ah[2][4], al[2][4], bh[8][2], bl[8][2];
#pragma unroll
            for (int ma = 0; ma < 2; ma++) {
                int row = mw * 32 + ma * 16 + a_tr;
                int c = ks * 2 + a_kq;
                LDSM_X4(ah[ma][0], ah[ma][1], ah[ma][2], ah[ma][3], base + MS_AH + msw(row, c));
                LDSM_X4(al[ma][0], al[ma][1], al[ma][2], al[ma][3], base + MS_AL + msw(row, c));
            }
#pragma unroll
            for (int nb = 0; nb < 4; nb++) {
                int row = nw * 64 + nb * 16 + b_tr;
                int c = ks * 2 + b_kq;
                LDSM_X4(bh[nb*2][0], bh[nb*2][1], bh[nb*2+1][0], bh[nb*2+1][1], base + MS_BH + msw(row, c));
                LDSM_X4(bl[nb*2][0], bl[nb*2][1], bl[nb*2+1][0], bl[nb*2+1][1], base + MS_BL + msw(row, c));
            }
#pragma unroll
            for (int ma = 0; ma < 2; ma++)
#pragma unroll
                for (int na = 0; na < 8; na++) {
                    MMA16816(acc[ma][na], ah[ma], bh[na]);
                    MMA16816(acc[ma][na], ah[ma], bl[na]);
                    MMA16816(acc[ma][na], al[ma], bh[na]);
                }
        }
        st ^= 1;
    }

    // ----------------------- fused epilogues -------------------------------
    const int g = lid >> 2, t4 = lid & 3;

    if (MODE == 0) {
#pragma unroll
        for (int ma = 0; ma < 2; ma++) {
            int row0 = m0 + mw * 32 + ma * 16 + g;
#pragma unroll
            for (int na = 0; na < 8; na++) {
                int col = n0 + nw * 64 + na * 8 + t4 * 2;
                *(float2*)(Cf + (size_t)row0 * ldc + col) =
                    make_float2(acc[ma][na][0], acc[ma][na][1]);
                *(float2*)(Cf + (size_t)(row0 + 8) * ldc + col) =
                    make_float2(acc[ma][na][2], acc[ma][na][3]);
            }
        }
    } else if (MODE == 1) {
#pragma unroll
        for (int ma = 0; ma < 2; ma++) {
            int row0 = m0 + mw * 32 + ma * 16 + g;
#pragma unroll
            for (int na = 0; na < 8; na++) {
                int col = n0 + nw * 64 + na * 8 + t4 * 2;
                uint32_t h0, l0;
                split2(acc[ma][na][0], acc[ma][na][1], h0, l0);
                *(uint32_t*)(Ch + (size_t)row0 * ldc + col) = h0;
                *(uint32_t*)(Cl + (size_t)row0 * ldc + col) = l0;
                split2(acc[ma][na][2], acc[ma][na][3], h0, l0);
                *(uint32_t*)(Ch + (size_t)(row0 + 8) * ldc + col) = h0;
                *(uint32_t*)(Cl + (size_t)(row0 + 8) * ldc + col) = l0;
            }
        }
    } else if (MODE == 2) {
        const int hq = (n0 + nw * 64) >> 6;
#pragma unroll
        for (int ma = 0; ma < 2; ma++) {
            int r0 = m0 + mw * 32 + ma * 16 + g;
            int b = r0 >> 11;
            size_t bb = (size_t)((b << 4) + hq) * CS * CDQK;
#pragma unroll
            for (int rh = 0; rh < 2; rh++) {
                int s = (r0 + rh * 8) & (CS - 1);
                size_t base = bb + (size_t)s * CDQK;
                float fs = (float)s;
#pragma unroll
                for (int na = 0; na < 4; na++) {
                    int e = rh * 2;
                    int i0 = na * 8 + t4 * 2;
                    float x1a = acc[ma][na][e],     x1b = acc[ma][na][e+1];
                    float x2a = acc[ma][na+4][e],   x2b = acc[ma][na+4][e+1];
                    float sn0, cs0, sn1, cs1;
                    sincosf(fs * exp2f(-(float)i0 * ROPE_L), &sn0, &cs0);
                    sincosf(fs * exp2f(-(float)(i0+1) * ROPE_L), &sn1, &cs1);
                    float o1a = x1a*cs0 - x2a*sn0, o1b = x1b*cs1 - x2b*sn1;
                    float o2a = x2a*cs0 + x1a*sn0, o2b = x2b*cs1 + x1b*sn1;
                    uint32_t h0, l0;
                    split2(o1a, o1b, h0, l0);
                    *(uint32_t*)(Ch + base + i0) = h0;
                    *(uint32_t*)(Cl + base + i0) = l0;
                    split2(o2a, o2b, h0, l0);
                    *(uint32_t*)(Ch + base + 32 + i0) = h0;
                    *(uint32_t*)(Cl + base + 32 + i0) = l0;
                }
            }
        }
    } else if (MODE == 3) {
        const int hq = (n0 + nw * 64) >> 6;
#pragma unroll
        for (int ma = 0; ma < 2; ma++) {
            int r0 = m0 + mw * 32 + ma * 16 + g;
            int b = r0 >> 11;
            size_t bb = (size_t)((b << 4) + hq) * CS * CDQK;
#pragma unroll
            for (int rh = 0; rh < 2; rh++) {
                int s = (r0 + rh * 8) & (CS - 1);
                size_t base = bb + (size_t)s * CDQK + 64;
#pragma unroll
                for (int na = 0; na < 8; na++) {
                    int d0 = na * 8 + t4 * 2;
                    uint32_t h0, l0;
                    split2(acc[ma][na][rh*2], acc[ma][na][rh*2+1], h0, l0);
                    *(uint32_t*)(Ch + base + d0) = h0;
                    *(uint32_t*)(Cl + base + d0) = l0;
                }
            }
        }
    } else {
        const int hq = (n0 + nw * 64) >> 6;
#pragma unroll
        for (int ma = 0; ma < 2; ma++) {
            int r0 = m0 + mw * 32 + ma * 16 + g;
            int b = r0 >> 11;
            size_t bb = (size_t)((b << 4) + hq) * CHD;
#pragma unroll
            for (int rh = 0; rh < 2; rh++) {
                int s = (r0 + rh * 8) & (CS - 1);
#pragma unroll
                for (int na = 0; na < 8; na++) {
#pragma unroll
                    for (int j = 0; j < 2; j++) {
                        int d = na * 8 + t4 * 2 + j;
                        float v = acc[ma][na][rh*2 + j];
                        __nv_bfloat16 hv = __float2bfloat16(v);
                        size_t o = (bb + d) * CS + s;
                        Ch[o] = hv;
                        Cl[o] = __float2bfloat16(v - __bfloat162float(hv));
                    }
                }
            }
        }
    }
}

// =================== causal flash attention, cp.async K/V 2-stage ==========
// BQ=128, 256 threads; K/V tiles 64 wide, double-buffered.
#define FQH 0
#define FQL 32768
#define FKV0 65536
#define FKV_STAGE 49152
#define FO_KH 0
#define FO_KL 16384
#define FO_VH 32768
#define FO_VL 40960
#define FLASH_SMEM 163840

__device__ __forceinline__ uint32_t fsw(int row, int chunk) {
    return (uint32_t)(row * 256 + ((chunk >> 3) << 7) + (((chunk & 7) ^ (row & 7)) << 4));
}
__device__ __forceinline__ uint32_t vsw(int row, int chunk) {
    return (uint32_t)(row * 128 + ((chunk ^ (row & 7)) << 4));
}

__global__ __launch_bounds__(256) void flash_attn_mma(
    const __nv_bfloat16* __restrict__ Qh, const __nv_bfloat16* __restrict__ Ql,
    const __nv_bfloat16* __restrict__ Kh, const __nv_bfloat16* __restrict__ Kl,
    const __nv_bfloat16* __restrict__ Vh, const __nv_bfloat16* __restrict__ Vl,
    __nv_bfloat16* __restrict__ Yh, __nv_bfloat16* __restrict__ Yl)
{
    extern __shared__ char smem[];
    uint32_t sb = smem_to_u32(smem);
    const int tid = threadIdx.x, wid = tid >> 5, lid = tid & 31;
    const int qb = blockIdx.x, bh = blockIdx.y;
    const int q0 = qb * 128;
    const int g = lid >> 2, t = lid & 3;

    const __nv_bfloat16* Qhg = Qh + (size_t)bh * CS * CDQK;
    const __nv_bfloat16* Qlg = Ql + (size_t)bh * CS * CDQK;
    const __nv_bfloat16* Khg = Kh + (size_t)bh * CS * CDQK;
    const __nv_bfloat16* Klg = Kl + (size_t)bh * CS * CDQK;
    const __nv_bfloat16* Vhg = Vh + (size_t)bh * CHD * CS;
    const __nv_bfloat16* Vlg = Vl + (size_t)bh * CHD * CS;

    auto issue_kv = [&](int stg, int k0) {
        uint32_t base = sb + FKV0 + stg * FKV_STAGE;
#pragma unroll
        for (int it = 0; it < 4; it++) {
            int i = it * 256 + tid;
            int row = i >> 4, ch = i & 15;
            size_t off = (size_t)(k0 + row) * CDQK + ch * 8;
            uint32_t so = fsw(row, ch);
            CP_ASYNC16(base + FO_KH + so, Khg + off);
            CP_ASYNC16(base + FO_KL + so, Klg + off);
        }
#pragma unroll
        for (int it = 0; it < 2; it++) {
            int i = it * 256 + tid;
            int row = i >> 3, ch = i & 7;
            size_t off = (size_t)row * CS + k0 + ch * 8;
            uint32_t so = vsw(row, ch);
            CP_ASYNC16(base + FO_VH + so, Vhg + off);
            CP_ASYNC16(base + FO_VL + so, Vlg + off);
        }
        CP_COMMIT();
    };

    // kick off K/V tile 0 first, then fill Q (overlaps with cp.async in flight)
    issue_kv(0, 0);
#pragma unroll
    for (int it = 0; it < 8; it++) {
        int i = it * 256 + tid;
        int row = i >> 4, ch = i & 15;
        size_t off = (size_t)(q0 + row) * CDQK + ch * 8;
        *(uint4*)(smem + FQH + fsw(row, ch)) = *(const uint4*)(Qhg + off);
        *(uint4*)(smem + FQL + fsw(row, ch)) = *(const uint4*)(Qlg + off);
    }

    const int a_tr = (lid & 7) + ((lid >> 3) & 1) * 8;
    const int a_kq = lid >> 4;
    const int b_tr = (lid & 7) + (lid >> 4) * 8;
    const int b_kq = (lid >> 3) & 1;

    float O[8][4];
#pragma unroll
    for (int na = 0; na < 8; na++)
#pragma unroll
        for (int e = 0; e < 4; e++) O[na][e] = 0.f;
    float mI0 = -1e30f, mI1 = -1e30f, lI0 = 0.f, lI1 = 0.f;
    const float scale = 0.08838834764831845f;

    const int qw_last = q0 + wid * 16 + 15;
    const int nkb = 2 * qb + 2;
    int st = 0;

    for (int kb = 0; kb < nkb; kb++) {
        const int k0 = kb * 64;
        __syncthreads();   // stage st^1 readers from prev iter done
        if (kb + 1 < nkb) { issue_kv(st ^ 1, k0 + 64); CP_WAIT(1); }
        else              { CP_WAIT(0); }
        __syncthreads();   // stage st visible

        if (k0 <= qw_last) {
            uint32_t kvb = sb + FKV0 + st * FKV_STAGE;

            float sc[8][4];
#pragma unroll
            for (int na = 0; na < 8; na++)
#pragma unroll
                for (int e = 0; e < 4; e++) sc[na][e] = 0.f;

#pragma unroll
            for (int ks = 0; ks < 8; ks++) {
                uint32_t ah[4], al[4], khf[8][2], klf[8][2];
                LDSM_X4(ah[0], ah[1], ah[2], ah[3],
                        sb + FQH + fsw(wid * 16 + a_tr, ks * 2 + a_kq));
                LDSM_X4(al[0], al[1], al[2], al[3],
                        sb + FQL + fsw(wid * 16 + a_tr, ks * 2 + a_kq));
#pragma unroll
                for (int nb = 0; nb < 4; nb++) {
                    uint32_t so = fsw(nb * 16 + b_tr, ks * 2 + b_kq);
                    LDSM_X4(khf[nb*2][0], khf[nb*2][1], khf[nb*2+1][0], khf[nb*2+1][1], kvb + FO_KH + so);
                    LDSM_X4(klf[nb*2][0], klf[nb*2][1], klf[nb*2+1][0], klf[nb*2+1][1], kvb + FO_KL + so);
                }
#pragma unroll
                for (int na = 0; na < 8; na++) {
                    MMA16816(sc[na], ah, khf[na]);
                    MMA16816(sc[na], ah, klf[na]);
                    MMA16816(sc[na], al, khf[na]);
                }
            }

            if (k0 + 63 > qw_last - 15) {
#pragma unroll
                for (int na = 0; na < 8; na++)
#pragma unroll
                    for (int e = 0; e < 4; e++) {
                        int qr = q0 + wid * 16 + g + ((e >> 1) << 3);
                        int kc = k0 + na * 8 + 2 * t + (e & 1);
                        sc[na][e] = (kc > qr) ? -1e30f : sc[na][e] * scale;
                    }
            } else {
#pragma unroll
                for (int na = 0; na < 8; na++)
#pragma unroll
                    for (int e = 0; e < 4; e++) sc[na][e] *= scale;
            }

            float mx0 = -1e30f, mx1 = -1e30f;
#pragma unroll
            for (int na = 0; na < 8; na++) {
                mx0 = fmaxf(mx0, fmaxf(sc[na][0], sc[na][1]));
                mx1 = fmaxf(mx1, fmaxf(sc[na][2], sc[na][3]));
            }
            mx0 = fmaxf(mx0, __shfl_xor_sync(0xffffffffu, mx0, 1));
            mx0 = fmaxf(mx0, __shfl_xor_sync(0xffffffffu, mx0, 2));
            mx1 = fmaxf(mx1, __shfl_xor_sync(0xffffffffu, mx1, 1));
            mx1 = fmaxf(mx1, __shfl_xor_sync(0xffffffffu, mx1, 2));

            float mn0 = fmaxf(mI0, mx0), mn1 = fmaxf(mI1, mx1);
            float al0 = __expf(mI0 - mn0), al1 = __expf(mI1 - mn1);
            mI0 = mn0; mI1 = mn1;

            float rs0 = 0.f, rs1 = 0.f;
#pragma unroll
            for (int na = 0; na < 8; na++) {
                sc[na][0] = __expf(sc[na][0] - mn0); rs0 += sc[na][0];
                sc[na][1] = __expf(sc[na][1] - mn0); rs0 += sc[na][1];
                sc[na][2] = __expf(sc[na][2] - mn1); rs1 += sc[na][2];
                sc[na][3] = __expf(sc[na][3] - mn1); rs1 += sc[na][3];
            }
            rs0 += __shfl_xor_sync(0xffffffffu, rs0, 1);
            rs0 += __shfl_xor_sync(0xffffffffu, rs0, 2);
            rs1 += __shfl_xor_sync(0xffffffffu, rs1, 1);
            rs1 += __shfl_xor_sync(0xffffffffu, rs1, 2);
            lI0 = lI0 * al0 + rs0;
            lI1 = lI1 * al1 + rs1;

#pragma unroll
            for (int na = 0; na < 8; na++) {
                O[na][0] *= al0; O[na][1] *= al0;
                O[na][2] *= al1; O[na][3] *= al1;
            }

#pragma unroll
            for (int kk = 0; kk < 4; kk++) {
                uint32_t pah[4], pal[4];
                split2(sc[2*kk][0],   sc[2*kk][1],   pah[0], pal[0]);
                split2(sc[2*kk][2],   sc[2*kk][3],   pah[1], pal[1]);
                split2(sc[2*kk+1][0], sc[2*kk+1][1], pah[2], pal[2]);
                split2(sc[2*kk+1][2], sc[2*kk+1][3], pah[3], pal[3]);
                uint32_t vhf[8][2], vlf[8][2];
#pragma unroll
                for (int nb = 0; nb < 4; nb++) {
                    uint32_t so = vsw(nb * 16 + b_tr, kk * 2 + b_kq);
                    LDSM_X4(vhf[nb*2][0], vhf[nb*2][1], vhf[nb*2+1][0], vhf[nb*2+1][1], kvb + FO_VH + so);
                    LDSM_X4(vlf[nb*2][0], vlf[nb*2][1], vlf[nb*2+1][0], vlf[nb*2+1][1], kvb + FO_VL + so);
                }
#pragma unroll
                for (int na = 0; na < 8; na++) {
                    MMA16816(O[na], pah, vhf[na]);
                    MMA16816(O[na], pal, vhf[na]);
                    MMA16816(O[na], pah, vlf[na]);
                }
            }
        }
        st ^= 1;
    }

    // ---- epilogue: write Y directly as bf16 hi/lo -------------------------
    const int b = bh >> 4, h = bh & 15;
    const float inv0 = 1.f / lI0, inv1 = 1.f / lI1;
    const int qr0 = q0 + wid * 16 + g;
#pragma unroll
    for (int na = 0; na < 8; na++) {
        int col = h * CHD + na * 8 + 2 * t;
        uint32_t h0, l0;
        split2(O[na][0] * inv0, O[na][1] * inv0, h0, l0);
        *(uint32_t*)(Yh + (size_t)(b*CS + qr0) * CE + col) = h0;
        *(uint32_t*)(Yl + (size_t)(b*CS + qr0) * CE + col) = l0;
        split2(O[na][2] * inv1, O[na][3] * inv1, h0, l0);
        *(uint32_t*)(Yh + (size_t)(b*CS + qr0 + 8) * CE + col) = h0;
        *(uint32_t*)(Yl + (size_t)(b*CS + qr0 + 8) * CE + col) = l0;
    }
}

// ============================== launcher ===================================
static inline void launch_cvt(const float* s, __nv_bfloat16* h, __nv_bfloat16* l, int n) {
    cvt_split<<<(n + 255) / 256, 256>>>(s, h, l, n);
}

extern "C" void kernel_launch(void* const* d_in, const int* in_sizes, int n_in,
                              void* d_out, int out_size)
{
    const float* x        = (const float*)d_in[0];
    const float* wq_down  = (const float*)d_in[1];
    const float* wk_rope  = (const float*)d_in[2];
    const float* wkv_down = (const float*)d_in[3];
    const float* wq_rope  = (const float*)d_in[4];
    const float* wq_up    = (const float*)d_in[5];
    const float* wk_up    = (const float*)d_in[6];
    const float* wv_up    = (const float*)d_in[7];
    const float* wo       = (const float*)d_in[8];
    float* out = (float*)d_out;

    __nv_bfloat16 *xh,*xl,*lath,*latl,*Yh,*Yl,*wdh,*wdl;
    __nv_bfloat16 *w3h,*w3l,*w4h,*w4l,*w5h,*w5l,*w6h,*w6l,*w7h,*w7l;
    __nv_bfloat16 *Qbh,*Qbl,*Kbh,*Kbl,*Vbh,*Vbl;
    cudaGetSymbolAddress((void**)&xh,   g_xh);   cudaGetSymbolAddress((void**)&xl,   g_xl);
    cudaGetSymbolAddress((void**)&lath, g_lath); cudaGetSymbolAddress((void**)&latl, g_latl);
    cudaGetSymbolAddress((void**)&Yh,   g_Yh);   cudaGetSymbolAddress((void**)&Yl,   g_Yl);
    cudaGetSymbolAddress((void**)&wdh,  g_wdh);  cudaGetSymbolAddress((void**)&wdl,  g_wdl);
    cudaGetSymbolAddress((void**)&w3h,  g_w3h);  cudaGetSymbolAddress((void**)&w3l,  g_w3l);
    cudaGetSymbolAddress((void**)&w4h,  g_w4h);  cudaGetSymbolAddress((void**)&w4l,  g_w4l);
    cudaGetSymbolAddress((void**)&w5h,  g_w5h);  cudaGetSymbolAddress((void**)&w5l,  g_w5l);
    cudaGetSymbolAddress((void**)&w6h,  g_w6h);  cudaGetSymbolAddress((void**)&w6l,  g_w6l);
    cudaGetSymbolAddress((void**)&w7h,  g_w7h);  cudaGetSymbolAddress((void**)&w7l,  g_w7l);
    cudaGetSymbolAddress((void**)&Qbh,  g_Qbh);  cudaGetSymbolAddress((void**)&Qbl,  g_Qbl);
    cudaGetSymbolAddress((void**)&Kbh,  g_Kbh);  cudaGetSymbolAddress((void**)&Kbl,  g_Kbl);
    cudaGetSymbolAddress((void**)&Vbh,  g_Vbh);  cudaGetSymbolAddress((void**)&Vbl,  g_Vbl);

    cudaFuncSetAttribute(gemm_ms<0>, cudaFuncAttributeMaxDynamicSharedMemorySize, GEMM_SMEM);
    cudaFuncSetAttribute(gemm_ms<1>, cudaFuncAttributeMaxDynamicSharedMemorySize, GEMM_SMEM);
    cudaFuncSetAttribute(gemm_ms<2>, cudaFuncAttributeMaxDynamicSharedMemorySize, GEMM_SMEM);
    cudaFuncSetAttribute(gemm_ms<3>, cudaFuncAttributeMaxDynamicSharedMemorySize, GEMM_SMEM);
    cudaFuncSetAttribute(gemm_ms<4>, cudaFuncAttributeMaxDynamicSharedMemorySize, GEMM_SMEM);
    cudaFuncSetAttribute(flash_attn_mma, cudaFuncAttributeMaxDynamicSharedMemorySize, FLASH_SMEM);

    launch_cvt(x,        xh,  xl,  MTOK*CE);
    launch_cvt(wq_down,  wdh,             wdl,             CR*CE);
    launch_cvt(wk_rope,  wdh + CR*CE,     wdl + CR*CE,     CR*CE);
    launch_cvt(wkv_down, wdh + 2*CR*CE,   wdl + 2*CR*CE,   CR*CE);
    launch_cvt(wq_rope,  w3h, w3l, CE*CR);
    launch_cvt(wq_up,    w4h, w4l, CE*CR);
    launch_cvt(wk_up,    w5h, w5l, CE*CR);
    launch_cvt(wv_up,    w6h, w6l, CE*CR);
    launch_cvt(wo,       w7h, w7l, CE*CE);

    dim3 blk(256);
    // fused down projection
    gemm_ms<1><<<dim3(NLAT/128, MTOK/128), blk, GEMM_SMEM>>>(
        xh, xl, CE, wdh, wdl, CE, nullptr, lath, latl, NLAT, CE);
    // q rope
    gemm_ms<2><<<dim3(CE/128, MTOK/128), blk, GEMM_SMEM>>>(
        lath, latl, NLAT, w3h, w3l, CR, nullptr, Qbh, Qbl, 0, CR);
    // q nope
    gemm_ms<3><<<dim3(CE/128, MTOK/128), blk, GEMM_SMEM>>>(
        lath, latl, NLAT, w4h, w4l, CR, nullptr, Qbh, Qbl, 0, CR);
    // k rope
    gemm_ms<2><<<dim3(CE/128, MTOK/128), blk, GEMM_SMEM>>>(
        lath + CR, latl + CR, NLAT, w5h, w5l, CR, nullptr, Kbh, Kbl, 0, CR);
    // k nope
    gemm_ms<3><<<dim3(CE/128, MTOK/128), blk, GEMM_SMEM>>>(
        lath + 2*CR, latl + 2*CR, NLAT, w5h, w5l, CR, nullptr, Kbh, Kbl, 0, CR);
    // v (transposed)
    gemm_ms<4><<<dim3(CE/128, MTOK/128), blk, GEMM_SMEM>>>(
        lath + 2*CR, latl + 2*CR, NLAT, w6h, w6l, CR, nullptr, Vbh, Vbl, 0, CR);

    // causal flash attention -> Yh/Yl
    flash_attn_mma<<<dim3(CS/128, CB*CH), 256, FLASH_SMEM>>>(
        Qbh, Qbl, Kbh, Kbl, Vbh, Vbl, Yh, Yl);

    // output projection
    gemm_ms<0><<<dim3(CE/128, MTOK/128), blk, GEMM_SMEM>>>(
        Yh, Yl, CE, w7h, w7l, CE, out, nullptr, nullptr, CE, CE);
}

// round 10
// speedup vs baseline: 3.4699x; 1.1227x over previous
#include <cuda_runtime.h>
#include <cuda_bf16.h>
#include <cstdint>
#include <math.h>

#define CB   2
#define CS   2048
#define CE   1024
#define CR   256
#define CH   16
#define CHD  64
#define CDQK 128
#define MTOK (CB*CS)   // 4096
#define NLAT 768       // 3 x 256 concatenated latents
#define WSEG (CR*CE)   // 262144

// ---------------- scratch (no allocation allowed -> __device__ globals) ----
__device__ __nv_bfloat16 g_xh [MTOK*CE],  g_xl [MTOK*CE];
__device__ __nv_bfloat16 g_lath[MTOK*NLAT], g_latl[MTOK*NLAT];
__device__ __nv_bfloat16 g_Yh [MTOK*CE],  g_Yl [MTOK*CE];
__device__ __nv_bfloat16 g_wdh[NLAT*CE],  g_wdl[NLAT*CE];      // wq_down|wk_rope|wkv_down
__device__ __nv_bfloat16 g_wqh[2*CE*CR],  g_wql[2*CE*CR];      // wq_rope|wq_up
__device__ __nv_bfloat16 g_wkvh[2*CE*CR], g_wkvl[2*CE*CR];     // wk_up|wv_up
__device__ __nv_bfloat16 g_w7h[CE*CE],    g_w7l[CE*CE];        // wo

__device__ __nv_bfloat16 g_Qbh[CB*CH*CS*CDQK], g_Qbl[CB*CH*CS*CDQK];  // [b,h,s,128]
__device__ __nv_bfloat16 g_Kbh[CB*CH*CS*CDQK], g_Kbl[CB*CH*CS*CDQK];  // [b,h,s,128]
__device__ __nv_bfloat16 g_Vbh[CB*CH*CHD*CS],  g_Vbl[CB*CH*CHD*CS];   // [b,h,d,s]

// ===================== generic helpers =====================================
__device__ __forceinline__ uint32_t smem_to_u32(const void* p) {
    uint32_t a;
    asm("{ .reg .u64 t; cvta.to.shared.u64 t, %1; cvt.u32.u64 %0, t; }" : "=r"(a) : "l"(p));
    return a;
}

#define LDSM_X4(r0,r1,r2,r3, addr) \
    asm volatile("ldmatrix.sync.aligned.m8n8.x4.shared.b16 {%0,%1,%2,%3}, [%4];" \
        : "=r"(r0), "=r"(r1), "=r"(r2), "=r"(r3) : "r"(addr))

#define MMA16816(c, a, b) \
    asm volatile("mma.sync.aligned.m16n8k16.row.col.f32.bf16.bf16.f32 " \
        "{%0,%1,%2,%3}, {%4,%5,%6,%7}, {%8,%9}, {%0,%1,%2,%3};" \
        : "+f"((c)[0]), "+f"((c)[1]), "+f"((c)[2]), "+f"((c)[3]) \
        : "r"((a)[0]), "r"((a)[1]), "r"((a)[2]), "r"((a)[3]), "r"((b)[0]), "r"((b)[1]))

#define CP_ASYNC16(dst, src) \
    asm volatile("cp.async.cg.shared.global [%0], [%1], 16;" :: "r"(dst), "l"(src))
#define CP_COMMIT() asm volatile("cp.async.commit_group;" ::: "memory")
#define CP_WAIT(n)  asm volatile("cp.async.wait_group %0;" :: "n"(n) : "memory")

__device__ __forceinline__ void split2(float a, float b, uint32_t& hi, uint32_t& lo) {
    __nv_bfloat16 ha = __float2bfloat16(a), hb = __float2bfloat16(b);
    float ra = a - __bfloat162float(ha);
    float rb = b - __bfloat162float(hb);
    __nv_bfloat162 hh; hh.x = ha; hh.y = hb;
    hi = *(uint32_t*)&hh;
    __nv_bfloat162 ll = __floats2bfloat162_rn(ra, rb);
    lo = *(uint32_t*)&ll;
}

// ===================== split-fp32 converts =================================
__global__ void cvt_split(const float* __restrict__ src,
                          __nv_bfloat16* __restrict__ hi, __nv_bfloat16* __restrict__ lo, int n)
{
    int i = blockIdx.x * blockDim.x + threadIdx.x;
    if (i < n) {
        float v = src[i];
        __nv_bfloat16 h = __float2bfloat16(v);
        hi[i] = h;
        lo[i] = __float2bfloat16(v - __bfloat162float(h));
    }
}

// all 8 weight tensors in one launch, writing concatenated layouts
__global__ void cvt_weights(
    const float* __restrict__ wq_down, const float* __restrict__ wk_rope,
    const float* __restrict__ wkv_down, const float* __restrict__ wq_rope,
    const float* __restrict__ wq_up,   const float* __restrict__ wk_up,
    const float* __restrict__ wv_up,   const float* __restrict__ wo,
    __nv_bfloat16* __restrict__ wdh,  __nv_bfloat16* __restrict__ wdl,
    __nv_bfloat16* __restrict__ wqh,  __nv_bfloat16* __restrict__ wql,
    __nv_bfloat16* __restrict__ wkvh, __nv_bfloat16* __restrict__ wkvl,
    __nv_bfloat16* __restrict__ w7h,  __nv_bfloat16* __restrict__ w7l)
{
    int i = blockIdx.x * blockDim.x + threadIdx.x;
    const float* src;
    __nv_bfloat16 *dh, *dl;
    int off;
    if (i < 7 * WSEG) {
        int seg = i / WSEG;
        off = i - seg * WSEG;
        switch (seg) {
            case 0: src = wq_down;  dh = wdh;            dl = wdl;            break;
            case 1: src = wk_rope;  dh = wdh + WSEG;     dl = wdl + WSEG;     break;
            case 2: src = wkv_down; dh = wdh + 2*WSEG;   dl = wdl + 2*WSEG;   break;
            case 3: src = wq_rope;  dh = wqh;            dl = wql;            break;
            case 4: src = wq_up;    dh = wqh + WSEG;     dl = wql + WSEG;     break;
            case 5: src = wk_up;    dh = wkvh;           dl = wkvl;           break;
            default: src = wv_up;   dh = wkvh + WSEG;    dl = wkvl + WSEG;    break;
        }
    } else {
        off = i - 7 * WSEG;
        if (off >= CE * CE) return;
        src = wo; dh = w7h; dl = w7l;
    }
    float v = src[off];
    __nv_bfloat16 h = __float2bfloat16(v);
    dh[off] = h;
    dl[off] = __float2bfloat16(v - __bfloat162float(h));
}

// ============= tensor-core split-bf16 GEMM NT, cp.async 2-stage ============
// C[M,N] = A[M,K] * B[N,K]^T. CTA tile 128x128, 256 threads.
// MODE 0: fp32; 1: split hi/lo; 2: rope Q/K
// MODE 5: Q combined (cols<CE rope, else nope), both to Ch/Cl
// MODE 6: KV combined (cols<CE nope->Ch/Cl, else V-transposed->Dh/Dl)
#define GEMM_SMEM 65536
#define MS_AH 0
#define MS_AL 8192
#define MS_BH 16384
#define MS_BL 24576
#define MS_STAGE 32768
#define ROPE_L 0.41524101186109f

__device__ __forceinline__ uint32_t msw(int row, int c) {
    return (uint32_t)(row * 64 + ((c ^ ((row >> 1) & 3)) << 4));
}

template<int MODE>
__global__ __launch_bounds__(256) void gemm_ms(
    const __nv_bfloat16* __restrict__ Ah, const __nv_bfloat16* __restrict__ Al, int lda,
    const __nv_bfloat16* __restrict__ Bh, const __nv_bfloat16* __restrict__ Bl, int ldb,
    float* __restrict__ Cf, __nv_bfloat16* __restrict__ Ch, __nv_bfloat16* __restrict__ Cl,
    __nv_bfloat16* __restrict__ Dh, __nv_bfloat16* __restrict__ Dl,
    int ldc, int K)
{
    extern __shared__ char smem[];
    const int tid = threadIdx.x, wid = tid >> 5, lid = tid & 31;
    const int m0 = blockIdx.y * 128, n0 = blockIdx.x * 128;
    uint32_t sb = smem_to_u32(smem);

    const int mw = wid & 3, nw = wid >> 2;
    const int a_tr = (lid & 7) + ((lid >> 3) & 1) * 8;
    const int a_kq = lid >> 4;
    const int b_tr = (lid & 7) + (lid >> 4) * 8;
    const int b_kq = (lid >> 3) & 1;

    float acc[2][8][4];
#pragma unroll
    for (int i = 0; i < 2; i++)
#pragma unroll
        for (int j = 0; j < 8; j++)
#pragma unroll
            for (int q = 0; q < 4; q++) acc[i][j][q] = 0.f;

    auto issue = [&](int stg, int k0) {
        uint32_t base = sb + stg * MS_STAGE;
#pragma unroll
        for (int it = 0; it < 2; it++) {
            int ch = it * 256 + tid;
            int row = ch >> 2, c = ch & 3;
            uint32_t so = msw(row, c);
            size_t ga = (size_t)(m0 + row) * lda + k0 + c * 8;
            size_t gb = (size_t)(n0 + row) * ldb + k0 + c * 8;
            CP_ASYNC16(base + MS_AH + so, Ah + ga);
            CP_ASYNC16(base + MS_AL + so, Al + ga);
            CP_ASYNC16(base + MS_BH + so, Bh + gb);
            CP_ASYNC16(base + MS_BL + so, Bl + gb);
        }
        CP_COMMIT();
    };

    issue(0, 0);
    int st = 0;
    for (int k0 = 0; k0 < K; k0 += 32) {
        __syncthreads();
        if (k0 + 32 < K) { issue(st ^ 1, k0 + 32); CP_WAIT(1); }
        else             { CP_WAIT(0); }
        __syncthreads();

        uint32_t base = sb + st * MS_STAGE;
#pragma unroll
        for (int ks = 0; ks < 2; ks++) {
            uint32_t ah[2][4], al[2][4], bh[8][2], bl[8][2];
#pragma unroll
            for (int ma = 0; ma < 2; ma++) {
                int row = mw * 32 + ma * 16 + a_tr;
                int c = ks * 2 + a_kq;
                LDSM_X4(ah[ma][0], ah[ma][1], ah[ma][2], ah[ma][3], base + MS_AH + msw(row, c));
                LDSM_X4(al[ma][0], al[ma][1], al[ma][2], al[ma][3], base + MS_AL + msw(row, c));
            }
#pragma unroll
            for (int nb = 0; nb < 4; nb++) {
                int row = nw * 64 + nb * 16 + b_tr;
                int c = ks * 2 + b_kq;
                LDSM_X4(bh[nb*2][0], bh[nb*2][1], bh[nb*2+1][0], bh[nb*2+1][1], base + MS_BH + msw(row, c));
                LDSM_X4(bl[nb*2][0], bl[nb*2][1], bl[nb*2+1][0], bl[nb*2+1][1], base + MS_BL + msw(row, c));
            }
#pragma unroll
            for (int ma = 0; ma < 2; ma++)
#pragma unroll
                for (int na = 0; na < 8; na++) {
                    MMA16816(acc[ma][na], ah[ma], bh[na]);
                    MMA16816(acc[ma][na], ah[ma], bl[na]);
                    MMA16816(acc[ma][na], al[ma], bh[na]);
                }
        }
        st ^= 1;
    }

    // ----------------------- fused epilogues -------------------------------
    const int g = lid >> 2, t4 = lid & 3;
    const int ncol = n0 + nw * 64;   // warp-uniform column base

    if (MODE == 0) {
#pragma unroll
        for (int ma = 0; ma < 2; ma++) {
            int row0 = m0 + mw * 32 + ma * 16 + g;
#pragma unroll
            for (int na = 0; na < 8; na++) {
                int col = ncol + na * 8 + t4 * 2;
                *(float2*)(Cf + (size_t)row0 * ldc + col) =
                    make_float2(acc[ma][na][0], acc[ma][na][1]);
                *(float2*)(Cf + (size_t)(row0 + 8) * ldc + col) =
                    make_float2(acc[ma][na][2], acc[ma][na][3]);
            }
        }
    } else if (MODE == 1) {
#pragma unroll
        for (int ma = 0; ma < 2; ma++) {
            int row0 = m0 + mw * 32 + ma * 16 + g;
#pragma unroll
            for (int na = 0; na < 8; na++) {
                int col = ncol + na * 8 + t4 * 2;
                uint32_t h0, l0;
                split2(acc[ma][na][0], acc[ma][na][1], h0, l0);
                *(uint32_t*)(Ch + (size_t)row0 * ldc + col) = h0;
                *(uint32_t*)(Cl + (size_t)row0 * ldc + col) = l0;
                split2(acc[ma][na][2], acc[ma][na][3], h0, l0);
                *(uint32_t*)(Ch + (size_t)(row0 + 8) * ldc + col) = h0;
                *(uint32_t*)(Cl + (size_t)(row0 + 8) * ldc + col) = l0;
            }
        }
    } else {
        // rope / nope / vt dispatch (MODE 2, 5, 6)
        const bool first_half = (MODE == 2) || (ncol < CE);
        const int hq = (first_half ? ncol : (ncol - CE)) >> 6;

        if ((MODE == 2) || (MODE == 5 && first_half)) {
            // ---- rope epilogue -> Ch/Cl rope half [b,h,s,0:64] ----
#pragma unroll
            for (int ma = 0; ma < 2; ma++) {
                int r0 = m0 + mw * 32 + ma * 16 + g;
                int b = r0 >> 11;
                size_t bb = (size_t)((b << 4) + hq) * CS * CDQK;
#pragma unroll
                for (int rh = 0; rh < 2; rh++) {
                    int s = (r0 + rh * 8) & (CS - 1);
                    size_t base = bb + (size_t)s * CDQK;
                    float fs = (float)s;
#pragma unroll
                    for (int na = 0; na < 4; na++) {
                        int e = rh * 2;
                        int i0 = na * 8 + t4 * 2;
                        float x1a = acc[ma][na][e],   x1b = acc[ma][na][e+1];
                        float x2a = acc[ma][na+4][e], x2b = acc[ma][na+4][e+1];
                        float sn0, cs0, sn1, cs1;
                        sincosf(fs * exp2f(-(float)i0 * ROPE_L), &sn0, &cs0);
                        sincosf(fs * exp2f(-(float)(i0+1) * ROPE_L), &sn1, &cs1);
                        float o1a = x1a*cs0 - x2a*sn0, o1b = x1b*cs1 - x2b*sn1;
                        float o2a = x2a*cs0 + x1a*sn0, o2b = x2b*cs1 + x1b*sn1;
                        uint32_t h0, l0;
                        split2(o1a, o1b, h0, l0);
                        *(uint32_t*)(Ch + base + i0) = h0;
                        *(uint32_t*)(Cl + base + i0) = l0;
                        split2(o2a, o2b, h0, l0);
                        *(uint32_t*)(Ch + base + 32 + i0) = h0;
                        *(uint32_t*)(Cl + base + 32 + i0) = l0;
                    }
                }
            }
        } else if (MODE == 5 || (MODE == 6 && first_half)) {
            // ---- nope epilogue -> Ch/Cl [b,h,s,64:128] ----
#pragma unroll
            for (int ma = 0; ma < 2; ma++) {
                int r0 = m0 + mw * 32 + ma * 16 + g;
                int b = r0 >> 11;
                size_t bb = (size_t)((b << 4) + hq) * CS * CDQK;
#pragma unroll
                for (int rh = 0; rh < 2; rh++) {
                    int s = (r0 + rh * 8) & (CS - 1);
                    size_t base = bb + (size_t)s * CDQK + 64;
#pragma unroll
                    for (int na = 0; na < 8; na++) {
                        int d0 = na * 8 + t4 * 2;
                        uint32_t h0, l0;
                        split2(acc[ma][na][rh*2], acc[ma][na][rh*2+1], h0, l0);
                        *(uint32_t*)(Ch + base + d0) = h0;
                        *(uint32_t*)(Cl + base + d0) = l0;
                    }
                }
            }
        } else {
            // ---- vt epilogue -> Dh/Dl V [b,h,d,s] ----
#pragma unroll
            for (int ma = 0; ma < 2; ma++) {
                int r0 = m0 + mw * 32 + ma * 16 + g;
                int b = r0 >> 11;
                size_t bb = (size_t)((b << 4) + hq) * CHD;
#pragma unroll
                for (int rh = 0; rh < 2; rh++) {
                    int s = (r0 + rh * 8) & (CS - 1);
#pragma unroll
                    for (int na = 0; na < 8; na++) {
#pragma unroll
                        for (int j = 0; j < 2; j++) {
                            int d = na * 8 + t4 * 2 + j;
                            float v = acc[ma][na][rh*2 + j];
                            __nv_bfloat16 hv = __float2bfloat16(v);
                            size_t o = (bb + d) * CS + s;
                            Dh[o] = hv;
                            Dl[o] = __float2bfloat16(v - __bfloat162float(hv));
                        }
                    }
                }
            }
        }
    }
}

// =================== causal flash attention, cp.async K/V 2-stage ==========
// BQ=128, 256 threads; K/V tiles 64 wide, double-buffered.
// Grid (bh, qb') with qb = NQB-1-blockIdx.y => longest tiles scheduled first.
#define FQH 0
#define FQL 32768
#define FKV0 65536
#define FKV_STAGE 49152
#define FO_KH 0
#define FO_KL 16384
#define FO_VH 32768
#define FO_VL 40960
#define FLASH_SMEM 163840
#define NQB (CS/128)

__device__ __forceinline__ uint32_t fsw(int row, int chunk) {
    return (uint32_t)(row * 256 + ((chunk >> 3) << 7) + (((chunk & 7) ^ (row & 7)) << 4));
}
__device__ __forceinline__ uint32_t vsw(int row, int chunk) {
    return (uint32_t)(row * 128 + ((chunk ^ (row & 7)) << 4));
}

__global__ __launch_bounds__(256) void flash_attn_mma(
    const __nv_bfloat16* __restrict__ Qh, const __nv_bfloat16* __restrict__ Ql,
    const __nv_bfloat16* __restrict__ Kh, const __nv_bfloat16* __restrict__ Kl,
    const __nv_bfloat16* __restrict__ Vh, const __nv_bfloat16* __restrict__ Vl,
    __nv_bfloat16* __restrict__ Yh, __nv_bfloat16* __restrict__ Yl)
{
    extern __shared__ char smem[];
    uint32_t sb = smem_to_u32(smem);
    const int tid = threadIdx.x, wid = tid >> 5, lid = tid & 31;
    const int bh = blockIdx.x;
    const int qb = NQB - 1 - blockIdx.y;   // LPT: longest first
    const int q0 = qb * 128;
    const int g = lid >> 2, t = lid & 3;

    const __nv_bfloat16* Qhg = Qh + (size_t)bh * CS * CDQK;
    const __nv_bfloat16* Qlg = Ql + (size_t)bh * CS * CDQK;
    const __nv_bfloat16* Khg = Kh + (size_t)bh * CS * CDQK;
    const __nv_bfloat16* Klg = Kl + (size_t)bh * CS * CDQK;
    const __nv_bfloat16* Vhg = Vh + (size_t)bh * CHD * CS;
    const __nv_bfloat16* Vlg = Vl + (size_t)bh * CHD * CS;

    auto issue_kv = [&](int stg, int k0) {
        uint32_t base = sb + FKV0 + stg * FKV_STAGE;
#pragma unroll
        for (int it = 0; it < 4; it++) {
            int i = it * 256 + tid;
            int row = i >> 4, ch = i & 15;
            size_t off = (size_t)(k0 + row) * CDQK + ch * 8;
            uint32_t so = fsw(row, ch);
            CP_ASYNC16(base + FO_KH + so, Khg + off);
            CP_ASYNC16(base + FO_KL + so, Klg + off);
        }
#pragma unroll
        for (int it = 0; it < 2; it++) {
            int i = it * 256 + tid;
            int row = i >> 3, ch = i & 7;
            size_t off = (size_t)row * CS + k0 + ch * 8;
            uint32_t so = vsw(row, ch);
            CP_ASYNC16(base + FO_VH + so, Vhg + off);
            CP_ASYNC16(base + FO_VL + so, Vlg + off);
        }
        CP_COMMIT();
    };

    issue_kv(0, 0);
#pragma unroll
    for (int it = 0; it < 8; it++) {
        int i = it * 256 + tid;
        int row = i >> 4, ch = i & 15;
        size_t off = (size_t)(q0 + row) * CDQK + ch * 8;
        *(uint4*)(smem + FQH + fsw(row, ch)) = *(const uint4*)(Qhg + off);
        *(uint4*)(smem + FQL + fsw(row, ch)) = *(const uint4*)(Qlg + off);
    }

    const int a_tr = (lid & 7) + ((lid >> 3) & 1) * 8;
    const int a_kq = lid >> 4;
    const int b_tr = (lid & 7) + (lid >> 4) * 8;
    const int b_kq = (lid >> 3) & 1;

    float O[8][4];
#pragma unroll
    for (int na = 0; na < 8; na++)
#pragma unroll
        for (int e = 0; e < 4; e++) O[na][e] = 0.f;
    float mI0 = -1e30f, mI1 = -1e30f, lI0 = 0.f, lI1 = 0.f;
    const float scale = 0.08838834764831845f;

    const int qw_last = q0 + wid * 16 + 15;
    const int nkb = 2 * qb + 2;
    int st = 0;

    for (int kb = 0; kb < nkb; kb++) {
        const int k0 = kb * 64;
        __syncthreads();
        if (kb + 1 < nkb) { issue_kv(st ^ 1, k0 + 64); CP_WAIT(1); }
        else              { CP_WAIT(0); }
        __syncthreads();

        if (k0 <= qw_last) {
            uint32_t kvb = sb + FKV0 + st * FKV_STAGE;

            float sc[8][4];
#pragma unroll
            for (int na = 0; na < 8; na++)
#pragma unroll
                for (int e = 0; e < 4; e++) sc[na][e] = 0.f;

#pragma unroll
            for (int ks = 0; ks < 8; ks++) {
                uint32_t ah[4], al[4], khf[8][2], klf[8][2];
                LDSM_X4(ah[0], ah[1], ah[2], ah[3],
                        sb + FQH + fsw(wid * 16 + a_tr, ks * 2 + a_kq));
                LDSM_X4(al[0], al[1], al[2], al[3],
                        sb + FQL + fsw(wid * 16 + a_tr, ks * 2 + a_kq));
#pragma unroll
                for (int nb = 0; nb < 4; nb++) {
                    uint32_t so = fsw(nb * 16 + b_tr, ks * 2 + b_kq);
                    LDSM_X4(khf[nb*2][0], khf[nb*2][1], khf[nb*2+1][0], khf[nb*2+1][1], kvb + FO_KH + so);
                    LDSM_X4(klf[nb*2][0], klf[nb*2][1], klf[nb*2+1][0], klf[nb*2+1][1], kvb + FO_KL + so);
                }
#pragma unroll
                for (int na = 0; na < 8; na++) {
                    MMA16816(sc[na], ah, khf[na]);
                    MMA16816(sc[na], ah, klf[na]);
                    MMA16816(sc[na], al, khf[na]);
                }
            }

            if (k0 + 63 > qw_last - 15) {
#pragma unroll
                for (int na = 0; na < 8; na++)
#pragma unroll
                    for (int e = 0; e < 4; e++) {
                        int qr = q0 + wid * 16 + g + ((e >> 1) << 3);
                        int kc = k0 + na * 8 + 2 * t + (e & 1);
                        sc[na][e] = (kc > qr) ? -1e30f : sc[na][e] * scale;
                    }
            } else {
#pragma unroll
                for (int na = 0; na < 8; na++)
#pragma unroll
                    for (int e = 0; e < 4; e++) sc[na][e] *= scale;
            }

            float mx0 = -1e30f, mx1 = -1e30f;
#pragma unroll
            for (int na = 0; na < 8; na++) {
                mx0 = fmaxf(mx0, fmaxf(sc[na][0], sc[na][1]));
                mx1 = fmaxf(mx1, fmaxf(sc[na][2], sc[na][3]));
            }
            mx0 = fmaxf(mx0, __shfl_xor_sync(0xffffffffu, mx0, 1));
            mx0 = fmaxf(mx0, __shfl_xor_sync(0xffffffffu, mx0, 2));
            mx1 = fmaxf(mx1, __shfl_xor_sync(0xffffffffu, mx1, 1));
            mx1 = fmaxf(mx1, __shfl_xor_sync(0xffffffffu, mx1, 2));

            float mn0 = fmaxf(mI0, mx0), mn1 = fmaxf(mI1, mx1);
            float al0 = __expf(mI0 - mn0), al1 = __expf(mI1 - mn1);
            mI0 = mn0; mI1 = mn1;

            float rs0 = 0.f, rs1 = 0.f;
#pragma unroll
            for (int na = 0; na < 8; na++) {
                sc[na][0] = __expf(sc[na][0] - mn0); rs0 += sc[na][0];
                sc[na][1] = __expf(sc[na][1] - mn0); rs0 += sc[na][1];
                sc[na][2] = __expf(sc[na][2] - mn1); rs1 += sc[na][2];
                sc[na][3] = __expf(sc[na][3] - mn1); rs1 += sc[na][3];
            }
            rs0 += __shfl_xor_sync(0xffffffffu, rs0, 1);
            rs0 += __shfl_xor_sync(0xffffffffu, rs0, 2);
            rs1 += __shfl_xor_sync(0xffffffffu, rs1, 1);
            rs1 += __shfl_xor_sync(0xffffffffu, rs1, 2);
            lI0 = lI0 * al0 + rs0;
            lI1 = lI1 * al1 + rs1;

#pragma unroll
            for (int na = 0; na < 8; na++) {
                O[na][0] *= al0; O[na][1] *= al0;
                O[na][2] *= al1; O[na][3] *= al1;
            }

#pragma unroll
            for (int kk = 0; kk < 4; kk++) {
                uint32_t pah[4], pal[4];
                split2(sc[2*kk][0],   sc[2*kk][1],   pah[0], pal[0]);
                split2(sc[2*kk][2],   sc[2*kk][3],   pah[1], pal[1]);
                split2(sc[2*kk+1][0], sc[2*kk+1][1], pah[2], pal[2]);
                split2(sc[2*kk+1][2], sc[2*kk+1][3], pah[3], pal[3]);
                uint32_t vhf[8][2], vlf[8][2];
#pragma unroll
                for (int nb = 0; nb < 4; nb++) {
                    uint32_t so = vsw(nb * 16 + b_tr, kk * 2 + b_kq);
                    LDSM_X4(vhf[nb*2][0], vhf[nb*2][1], vhf[nb*2+1][0], vhf[nb*2+1][1], kvb + FO_VH + so);
                    LDSM_X4(vlf[nb*2][0], vlf[nb*2][1], vlf[nb*2+1][0], vlf[nb*2+1][1], kvb + FO_VL + so);
                }
#pragma unroll
                for (int na = 0; na < 8; na++) {
                    MMA16816(O[na], pah, vhf[na]);
                    MMA16816(O[na], pal, vhf[na]);
                    MMA16816(O[na], pah, vlf[na]);
                }
            }
        }
        st ^= 1;
    }

    // ---- epilogue: write Y directly as bf16 hi/lo -------------------------
    const int b = bh >> 4, h = bh & 15;
    const float inv0 = 1.f / lI0, inv1 = 1.f / lI1;
    const int qr0 = q0 + wid * 16 + g;
#pragma unroll
    for (int na = 0; na < 8; na++) {
        int col = h * CHD + na * 8 + 2 * t;
        uint32_t h0, l0;
        split2(O[na][0] * inv0, O[na][1] * inv0, h0, l0);
        *(uint32_t*)(Yh + (size_t)(b*CS + qr0) * CE + col) = h0;
        *(uint32_t*)(Yl + (size_t)(b*CS + qr0) * CE + col) = l0;
        split2(O[na][2] * inv1, O[na][3] * inv1, h0, l0);
        *(uint32_t*)(Yh + (size_t)(b*CS + qr0 + 8) * CE + col) = h0;
        *(uint32_t*)(Yl + (size_t)(b*CS + qr0 + 8) * CE + col) = l0;
    }
}

// ============================== launcher ===================================
extern "C" void kernel_launch(void* const* d_in, const int* in_sizes, int n_in,
                              void* d_out, int out_size)
{
    const float* x        = (const float*)d_in[0];
    const float* wq_down  = (const float*)d_in[1];
    const float* wk_rope  = (const float*)d_in[2];
    const float* wkv_down = (const float*)d_in[3];
    const float* wq_rope  = (const float*)d_in[4];
    const float* wq_up    = (const float*)d_in[5];
    const float* wk_up    = (const float*)d_in[6];
    const float* wv_up    = (const float*)d_in[7];
    const float* wo       = (const float*)d_in[8];
    float* out = (float*)d_out;

    __nv_bfloat16 *xh,*xl,*lath,*latl,*Yh,*Yl,*wdh,*wdl;
    __nv_bfloat16 *wqh,*wql,*wkvh,*wkvl,*w7h,*w7l;
    __nv_bfloat16 *Qbh,*Qbl,*Kbh,*Kbl,*Vbh,*Vbl;
    cudaGetSymbolAddress((void**)&xh,   g_xh);   cudaGetSymbolAddress((void**)&xl,   g_xl);
    cudaGetSymbolAddress((void**)&lath, g_lath); cudaGetSymbolAddress((void**)&latl, g_latl);
    cudaGetSymbolAddress((void**)&Yh,   g_Yh);   cudaGetSymbolAddress((void**)&Yl,   g_Yl);
    cudaGetSymbolAddress((void**)&wdh,  g_wdh);  cudaGetSymbolAddress((void**)&wdl,  g_wdl);
    cudaGetSymbolAddress((void**)&wqh,  g_wqh);  cudaGetSymbolAddress((void**)&wql,  g_wql);
    cudaGetSymbolAddress((void**)&wkvh, g_wkvh); cudaGetSymbolAddress((void**)&wkvl, g_wkvl);
    cudaGetSymbolAddress((void**)&w7h,  g_w7h);  cudaGetSymbolAddress((void**)&w7l,  g_w7l);
    cudaGetSymbolAddress((void**)&Qbh,  g_Qbh);  cudaGetSymbolAddress((void**)&Qbl,  g_Qbl);
    cudaGetSymbolAddress((void**)&Kbh,  g_Kbh);  cudaGetSymbolAddress((void**)&Kbl,  g_Kbl);
    cudaGetSymbolAddress((void**)&Vbh,  g_Vbh);  cudaGetSymbolAddress((void**)&Vbl,  g_Vbl);

    cudaFuncSetAttribute(gemm_ms<0>, cudaFuncAttributeMaxDynamicSharedMemorySize, GEMM_SMEM);
    cudaFuncSetAttribute(gemm_ms<1>, cudaFuncAttributeMaxDynamicSharedMemorySize, GEMM_SMEM);
    cudaFuncSetAttribute(gemm_ms<2>, cudaFuncAttributeMaxDynamicSharedMemorySize, GEMM_SMEM);
    cudaFuncSetAttribute(gemm_ms<5>, cudaFuncAttributeMaxDynamicSharedMemorySize, GEMM_SMEM);
    cudaFuncSetAttribute(gemm_ms<6>, cudaFuncAttributeMaxDynamicSharedMemorySize, GEMM_SMEM);
    cudaFuncSetAttribute(flash_attn_mma, cudaFuncAttributeMaxDynamicSharedMemorySize, FLASH_SMEM);

    // conversions: x + all weights (2 launches)
    cvt_split<<<(MTOK*CE + 255) / 256, 256>>>(x, xh, xl, MTOK*CE);
    cvt_weights<<<(7*WSEG + CE*CE + 255) / 256, 256>>>(
        wq_down, wk_rope, wkv_down, wq_rope, wq_up, wk_up, wv_up, wo,
        wdh, wdl, wqh, wql, wkvh, wkvl, w7h, w7l);

    dim3 blk(256);
    // fused down projection: lat[4096,768] = x @ [wq_down|wk_rope|wkv_down]^T
    gemm_ms<1><<<dim3(NLAT/128, MTOK/128), blk, GEMM_SMEM>>>(
        xh, xl, CE, wdh, wdl, CE, nullptr, lath, latl, nullptr, nullptr, NLAT, CE);

    // Q combined (rope | nope): qlat @ [wq_rope|wq_up]^T -> Qb
    gemm_ms<5><<<dim3(2*CE/128, MTOK/128), blk, GEMM_SMEM>>>(
        lath, latl, NLAT, wqh, wql, CR, nullptr, Qbh, Qbl, nullptr, nullptr, 0, CR);

    // K rope: krlat @ wk_up^T (rows 0..1023 of wkv) -> Kb rope half
    gemm_ms<2><<<dim3(CE/128, MTOK/128), blk, GEMM_SMEM>>>(
        lath + CR, latl + CR, NLAT, wkvh, wkvl, CR, nullptr, Kbh, Kbl, nullptr, nullptr, 0, CR);

    // KV combined (k nope | v): kvlat @ [wk_up|wv_up]^T -> Kb nope half / Vb
    gemm_ms<6><<<dim3(2*CE/128, MTOK/128), blk, GEMM_SMEM>>>(
        lath + 2*CR, latl + 2*CR, NLAT, wkvh, wkvl, CR, nullptr, Kbh, Kbl, Vbh, Vbl, 0, CR);

    // causal flash attention (LPT-ordered grid) -> Yh/Yl
    flash_attn_mma<<<dim3(CB*CH, NQB), 256, FLASH_SMEM>>>(
        Qbh, Qbl, Kbh, Kbl, Vbh, Vbl, Yh, Yl);

    // output projection: Y @ wo^T -> out (fp32)
    gemm_ms<0><<<dim3(CE/128, MTOK/128), blk, GEMM_SMEM>>>(
        Yh, Yl, CE, w7h, w7l, CE, out, nullptr, nullptr, nullptr, nullptr, CE, CE);
}

// round 11
// speedup vs baseline: 3.6762x; 1.0594x over previous
#include <cuda_runtime.h>
#include <cuda_bf16.h>
#include <cstdint>
#include <math.h>

#define CB   2
#define CS   2048
#define CE   1024
#define CR   256
#define CH   16
#define CHD  64
#define CDQK 128
#define MTOK (CB*CS)   // 4096
#define NLAT 768       // 3 x 256 concatenated latents
#define WSEG (CR*CE)   // 262144

// ---------------- scratch (no allocation allowed -> __device__ globals) ----
__device__ __nv_bfloat16 g_xh [MTOK*CE],  g_xl [MTOK*CE];
__device__ __nv_bfloat16 g_lath[MTOK*NLAT], g_latl[MTOK*NLAT];
__device__ __nv_bfloat16 g_Yh [MTOK*CE],  g_Yl [MTOK*CE];
__device__ __nv_bfloat16 g_wdh[NLAT*CE],  g_wdl[NLAT*CE];      // wq_down|wk_rope|wkv_down
__device__ __nv_bfloat16 g_wuh[5*WSEG],   g_wul[5*WSEG];       // wq_rope|wq_up|wk_up|wk_up|wv_up
__device__ __nv_bfloat16 g_w7h[CE*CE],    g_w7l[CE*CE];        // wo

__device__ __nv_bfloat16 g_Qbh[CB*CH*CS*CDQK], g_Qbl[CB*CH*CS*CDQK];  // [b,h,s,128]
__device__ __nv_bfloat16 g_Kbh[CB*CH*CS*CDQK], g_Kbl[CB*CH*CS*CDQK];  // [b,h,s,128]
__device__ __nv_bfloat16 g_Vbh[CB*CH*CHD*CS],  g_Vbl[CB*CH*CHD*CS];   // [b,h,d,s]

// ===================== generic helpers =====================================
__device__ __forceinline__ uint32_t smem_to_u32(const void* p) {
    uint32_t a;
    asm("{ .reg .u64 t; cvta.to.shared.u64 t, %1; cvt.u32.u64 %0, t; }" : "=r"(a) : "l"(p));
    return a;
}

#define LDSM_X4(r0,r1,r2,r3, addr) \
    asm volatile("ldmatrix.sync.aligned.m8n8.x4.shared.b16 {%0,%1,%2,%3}, [%4];" \
        : "=r"(r0), "=r"(r1), "=r"(r2), "=r"(r3) : "r"(addr))

#define MMA16816(c, a, b) \
    asm volatile("mma.sync.aligned.m16n8k16.row.col.f32.bf16.bf16.f32 " \
        "{%0,%1,%2,%3}, {%4,%5,%6,%7}, {%8,%9}, {%0,%1,%2,%3};" \
        : "+f"((c)[0]), "+f"((c)[1]), "+f"((c)[2]), "+f"((c)[3]) \
        : "r"((a)[0]), "r"((a)[1]), "r"((a)[2]), "r"((a)[3]), "r"((b)[0]), "r"((b)[1]))

#define CP_ASYNC16(dst, src) \
    asm volatile("cp.async.cg.shared.global [%0], [%1], 16;" :: "r"(dst), "l"(src))
#define CP_COMMIT() asm volatile("cp.async.commit_group;" ::: "memory")
#define CP_WAIT(n)  asm volatile("cp.async.wait_group %0;" :: "n"(n) : "memory")

__device__ __forceinline__ void split2(float a, float b, uint32_t& hi, uint32_t& lo) {
    __nv_bfloat16 ha = __float2bfloat16(a), hb = __float2bfloat16(b);
    float ra = a - __bfloat162float(ha);
    float rb = b - __bfloat162float(hb);
    __nv_bfloat162 hh; hh.x = ha; hh.y = hb;
    hi = *(uint32_t*)&hh;
    __nv_bfloat162 ll = __floats2bfloat162_rn(ra, rb);
    lo = *(uint32_t*)&ll;
}

// ===================== split-fp32 converts =================================
__global__ void cvt_split(const float* __restrict__ src,
                          __nv_bfloat16* __restrict__ hi, __nv_bfloat16* __restrict__ lo, int n)
{
    int i = blockIdx.x * blockDim.x + threadIdx.x;
    if (i < n) {
        float v = src[i];
        __nv_bfloat16 h = __float2bfloat16(v);
        hi[i] = h;
        lo[i] = __float2bfloat16(v - __bfloat162float(h));
    }
}

// all weight tensors in one launch (wk_up written twice into the up buffer)
__global__ void cvt_weights(
    const float* __restrict__ wq_down, const float* __restrict__ wk_rope,
    const float* __restrict__ wkv_down, const float* __restrict__ wq_rope,
    const float* __restrict__ wq_up,   const float* __restrict__ wk_up,
    const float* __restrict__ wv_up,   const float* __restrict__ wo,
    __nv_bfloat16* __restrict__ wdh,  __nv_bfloat16* __restrict__ wdl,
    __nv_bfloat16* __restrict__ wuh,  __nv_bfloat16* __restrict__ wul,
    __nv_bfloat16* __restrict__ w7h,  __nv_bfloat16* __restrict__ w7l)
{
    int i = blockIdx.x * blockDim.x + threadIdx.x;
    const float* src;
    __nv_bfloat16 *dh, *dl;
    int off;
    if (i < 8 * WSEG) {
        int seg = i / WSEG;
        off = i - seg * WSEG;
        switch (seg) {
            case 0: src = wq_down;  dh = wdh;          dl = wdl;          break;
            case 1: src = wk_rope;  dh = wdh + WSEG;   dl = wdl + WSEG;   break;
            case 2: src = wkv_down; dh = wdh + 2*WSEG; dl = wdl + 2*WSEG; break;
            case 3: src = wq_rope;  dh = wuh;          dl = wul;          break;
            case 4: src = wq_up;    dh = wuh + WSEG;   dl = wul + WSEG;   break;
            case 5: src = wk_up;    dh = wuh + 2*WSEG; dl = wul + 2*WSEG; break;
            case 6: src = wk_up;    dh = wuh + 3*WSEG; dl = wul + 3*WSEG; break;
            default: src = wv_up;   dh = wuh + 4*WSEG; dl = wul + 4*WSEG; break;
        }
    } else {
        off = i - 8 * WSEG;
        if (off >= CE * CE) return;
        src = wo; dh = w7h; dl = w7l;
    }
    float v = src[off];
    __nv_bfloat16 h = __float2bfloat16(v);
    dh[off] = h;
    dl[off] = __float2bfloat16(v - __bfloat162float(h));
}

// ============= tensor-core split-bf16 GEMM NT, cp.async 2-stage ============
// C[M,N] = A[M,K] * B[N,K]^T. CTA tile 128x128, 256 threads, 2 CTAs/SM.
// MODE 0: fp32; 1: split hi/lo
// MODE 7: mega up-projection. blockIdx.x ranges over 40 tiles:
//   [0,16):  A=qlat,  cols 0..2047:    <1024 rope->Q else nope->Q
//   [16,24): A=krlat, cols 2048..3071: rope->K
//   [24,40): A=kvlat, cols 3072..5119: <4096 nope->K else vt->V
#define GEMM_SMEM 65536
#define MS_AH 0
#define MS_AL 8192
#define MS_BH 16384
#define MS_BL 24576
#define MS_STAGE 32768
#define ROPE_L 0.41524101186109f

__device__ __forceinline__ uint32_t msw(int row, int c) {
    return (uint32_t)(row * 64 + ((c ^ ((row >> 1) & 3)) << 4));
}

template<int MODE>
__global__ __launch_bounds__(256, 2) void gemm_ms(
    const __nv_bfloat16* __restrict__ Ah, const __nv_bfloat16* __restrict__ Al, int lda,
    const __nv_bfloat16* __restrict__ Bh, const __nv_bfloat16* __restrict__ Bl, int ldb,
    float* __restrict__ Cf, __nv_bfloat16* __restrict__ Ch, __nv_bfloat16* __restrict__ Cl,
    __nv_bfloat16* __restrict__ Dh, __nv_bfloat16* __restrict__ Dl,
    __nv_bfloat16* __restrict__ Eh, __nv_bfloat16* __restrict__ El,
    int ldc, int K)
{
    extern __shared__ char smem[];
    const int tid = threadIdx.x, wid = tid >> 5, lid = tid & 31;
    const int m0 = blockIdx.y * 128, n0 = blockIdx.x * 128;
    uint32_t sb = smem_to_u32(smem);

    if (MODE == 7) {
        int nb = blockIdx.x;
        int aoff = (nb < 16) ? 0 : ((nb < 24) ? CR : 2 * CR);
        Ah += aoff; Al += aoff;
    }

    const int mw = wid & 3, nw = wid >> 2;
    const int a_tr = (lid & 7) + ((lid >> 3) & 1) * 8;
    const int a_kq = lid >> 4;
    const int b_tr = (lid & 7) + (lid >> 4) * 8;
    const int b_kq = (lid >> 3) & 1;

    float acc[2][8][4];
#pragma unroll
    for (int i = 0; i < 2; i++)
#pragma unroll
        for (int j = 0; j < 8; j++)
#pragma unroll
            for (int q = 0; q < 4; q++) acc[i][j][q] = 0.f;

    auto issue = [&](int stg, int k0) {
        uint32_t base = sb + stg * MS_STAGE;
#pragma unroll
        for (int it = 0; it < 2; it++) {
            int ch = it * 256 + tid;
            int row = ch >> 2, c = ch & 3;
            uint32_t so = msw(row, c);
            size_t ga = (size_t)(m0 + row) * lda + k0 + c * 8;
            size_t gb = (size_t)(n0 + row) * ldb + k0 + c * 8;
            CP_ASYNC16(base + MS_AH + so, Ah + ga);
            CP_ASYNC16(base + MS_AL + so, Al + ga);
            CP_ASYNC16(base + MS_BH + so, Bh + gb);
            CP_ASYNC16(base + MS_BL + so, Bl + gb);
        }
        CP_COMMIT();
    };

    issue(0, 0);
    int st = 0;
    for (int k0 = 0; k0 < K; k0 += 32) {
        __syncthreads();
        if (k0 + 32 < K) { issue(st ^ 1, k0 + 32); CP_WAIT(1); }
        else             { CP_WAIT(0); }
        __syncthreads();

        uint32_t base = sb + st * MS_STAGE;
#pragma unroll
        for (int ks = 0; ks < 2; ks++) {
            uint32_t ah[2][4], al[2][4], bh[8][2], bl[8][2];
#pragma unroll
            for (int ma = 0; ma < 2; ma++) {
                int row = mw * 32 + ma * 16 + a_tr;
                int c = ks * 2 + a_kq;
                LDSM_X4(ah[ma][0], ah[ma][1], ah[ma][2], ah[ma][3], base + MS_AH + msw(row, c));
                LDSM_X4(al[ma][0], al[ma][1], al[ma][2], al[ma][3], base + MS_AL + msw(row, c));
            }
#pragma unroll
            for (int nb = 0; nb < 4; nb++) {
                int row = nw * 64 + nb * 16 + b_tr;
                int c = ks * 2 + b_kq;
                LDSM_X4(bh[nb*2][0], bh[nb*2][1], bh[nb*2+1][0], bh[nb*2+1][1], base + MS_BH + msw(row, c));
                LDSM_X4(bl[nb*2][0], bl[nb*2][1], bl[nb*2+1][0], bl[nb*2+1][1], base + MS_BL + msw(row, c));
            }
#pragma unroll
            for (int ma = 0; ma < 2; ma++)
#pragma unroll
                for (int na = 0; na < 8; na++) {
                    MMA16816(acc[ma][na], ah[ma], bh[na]);
                    MMA16816(acc[ma][na], ah[ma], bl[na]);
                    MMA16816(acc[ma][na], al[ma], bh[na]);
                }
        }
        st ^= 1;
    }

    // ----------------------- fused epilogues -------------------------------
    const int g = lid >> 2, t4 = lid & 3;
    const int ncol = n0 + nw * 64;   // warp-uniform column base

    if (MODE == 0) {
#pragma unroll
        for (int ma = 0; ma < 2; ma++) {
            int row0 = m0 + mw * 32 + ma * 16 + g;
#pragma unroll
            for (int na = 0; na < 8; na++) {
                int col = ncol + na * 8 + t4 * 2;
                *(float2*)(Cf + (size_t)row0 * ldc + col) =
                    make_float2(acc[ma][na][0], acc[ma][na][1]);
                *(float2*)(Cf + (size_t)(row0 + 8) * ldc + col) =
                    make_float2(acc[ma][na][2], acc[ma][na][3]);
            }
        }
    } else if (MODE == 1) {
#pragma unroll
        for (int ma = 0; ma < 2; ma++) {
            int row0 = m0 + mw * 32 + ma * 16 + g;
#pragma unroll
            for (int na = 0; na < 8; na++) {
                int col = ncol + na * 8 + t4 * 2;
                uint32_t h0, l0;
                split2(acc[ma][na][0], acc[ma][na][1], h0, l0);
                *(uint32_t*)(Ch + (size_t)row0 * ldc + col) = h0;
                *(uint32_t*)(Cl + (size_t)row0 * ldc + col) = l0;
                split2(acc[ma][na][2], acc[ma][na][3], h0, l0);
                *(uint32_t*)(Ch + (size_t)(row0 + 8) * ldc + col) = h0;
                *(uint32_t*)(Cl + (size_t)(row0 + 8) * ldc + col) = l0;
            }
        }
    } else {
        // MODE 7 dispatch (warp-uniform by ncol)
        const bool is_rope = (ncol < CE) || (ncol >= 2*CE && ncol < 3*CE);
        const bool is_v    = (ncol >= 4*CE);
        __nv_bfloat16 *Oh, *Ol;
        int hq;
        if (ncol < CE)           { Oh = Ch; Ol = Cl; hq = ncol >> 6; }            // rope->Q
        else if (ncol < 2*CE)    { Oh = Ch; Ol = Cl; hq = (ncol - CE) >> 6; }     // nope->Q
        else if (ncol < 3*CE)    { Oh = Dh; Ol = Dl; hq = (ncol - 2*CE) >> 6; }   // rope->K
        else if (ncol < 4*CE)    { Oh = Dh; Ol = Dl; hq = (ncol - 3*CE) >> 6; }   // nope->K
        else                     { Oh = Eh; Ol = El; hq = (ncol - 4*CE) >> 6; }   // vt->V

        if (is_rope) {
#pragma unroll
            for (int ma = 0; ma < 2; ma++) {
                int r0 = m0 + mw * 32 + ma * 16 + g;
                int b = r0 >> 11;
                size_t bb = (size_t)((b << 4) + hq) * CS * CDQK;
#pragma unroll
                for (int rh = 0; rh < 2; rh++) {
                    int s = (r0 + rh * 8) & (CS - 1);
                    size_t base = bb + (size_t)s * CDQK;
                    float fs = (float)s;
#pragma unroll
                    for (int na = 0; na < 4; na++) {
                        int e = rh * 2;
                        int i0 = na * 8 + t4 * 2;
                        float x1a = acc[ma][na][e],   x1b = acc[ma][na][e+1];
                        float x2a = acc[ma][na+4][e], x2b = acc[ma][na+4][e+1];
                        float sn0, cs0, sn1, cs1;
                        sincosf(fs * exp2f(-(float)i0 * ROPE_L), &sn0, &cs0);
                        sincosf(fs * exp2f(-(float)(i0+1) * ROPE_L), &sn1, &cs1);
                        float o1a = x1a*cs0 - x2a*sn0, o1b = x1b*cs1 - x2b*sn1;
                        float o2a = x2a*cs0 + x1a*sn0, o2b = x2b*cs1 + x1b*sn1;
                        uint32_t h0, l0;
                        split2(o1a, o1b, h0, l0);
                        *(uint32_t*)(Oh + base + i0) = h0;
                        *(uint32_t*)(Ol + base + i0) = l0;
                        split2(o2a, o2b, h0, l0);
                        *(uint32_t*)(Oh + base + 32 + i0) = h0;
                        *(uint32_t*)(Ol + base + 32 + i0) = l0;
                    }
                }
            }
        } else if (!is_v) {
            // nope -> [b,h,s,64:128]
#pragma unroll
            for (int ma = 0; ma < 2; ma++) {
                int r0 = m0 + mw * 32 + ma * 16 + g;
                int b = r0 >> 11;
                size_t bb = (size_t)((b << 4) + hq) * CS * CDQK;
#pragma unroll
                for (int rh = 0; rh < 2; rh++) {
                    int s = (r0 + rh * 8) & (CS - 1);
                    size_t base = bb + (size_t)s * CDQK + 64;
#pragma unroll
                    for (int na = 0; na < 8; na++) {
                        int d0 = na * 8 + t4 * 2;
                        uint32_t h0, l0;
                        split2(acc[ma][na][rh*2], acc[ma][na][rh*2+1], h0, l0);
                        *(uint32_t*)(Oh + base + d0) = h0;
                        *(uint32_t*)(Ol + base + d0) = l0;
                    }
                }
            }
        } else {
            // vt -> V [b,h,d,s]
#pragma unroll
            for (int ma = 0; ma < 2; ma++) {
                int r0 = m0 + mw * 32 + ma * 16 + g;
                int b = r0 >> 11;
                size_t bb = (size_t)((b << 4) + hq) * CHD;
#pragma unroll
                for (int rh = 0; rh < 2; rh++) {
                    int s = (r0 + rh * 8) & (CS - 1);
#pragma unroll
                    for (int na = 0; na < 8; na++) {
#pragma unroll
                        for (int j = 0; j < 2; j++) {
                            int d = na * 8 + t4 * 2 + j;
                            float v = acc[ma][na][rh*2 + j];
                            __nv_bfloat16 hv = __float2bfloat16(v);
                            size_t o = (bb + d) * CS + s;
                            Oh[o] = hv;
                            Ol[o] = __float2bfloat16(v - __bfloat162float(hv));
                        }
                    }
                }
            }
        }
    }
}

// =================== causal flash attention, cp.async K/V 2-stage ==========
// BQ=128, 256 threads; K/V tiles 64 wide, double-buffered. LPT grid order.
#define FQH 0
#define FQL 32768
#define FKV0 65536
#define FKV_STAGE 49152
#define FO_KH 0
#define FO_KL 16384
#define FO_VH 32768
#define FO_VL 40960
#define FLASH_SMEM 163840
#define NQB (CS/128)

__device__ __forceinline__ uint32_t fsw(int row, int chunk) {
    return (uint32_t)(row * 256 + ((chunk >> 3) << 7) + (((chunk & 7) ^ (row & 7)) << 4));
}
__device__ __forceinline__ uint32_t vsw(int row, int chunk) {
    return (uint32_t)(row * 128 + ((chunk ^ (row & 7)) << 4));
}

__global__ __launch_bounds__(256) void flash_attn_mma(
    const __nv_bfloat16* __restrict__ Qh, const __nv_bfloat16* __restrict__ Ql,
    const __nv_bfloat16* __restrict__ Kh, const __nv_bfloat16* __restrict__ Kl,
    const __nv_bfloat16* __restrict__ Vh, const __nv_bfloat16* __restrict__ Vl,
    __nv_bfloat16* __restrict__ Yh, __nv_bfloat16* __restrict__ Yl)
{
    extern __shared__ char smem[];
    uint32_t sb = smem_to_u32(smem);
    const int tid = threadIdx.x, wid = tid >> 5, lid = tid & 31;
    const int bh = blockIdx.x;
    const int qb = NQB - 1 - blockIdx.y;   // LPT: longest first
    const int q0 = qb * 128;
    const int g = lid >> 2, t = lid & 3;

    const __nv_bfloat16* Qhg = Qh + (size_t)bh * CS * CDQK;
    const __nv_bfloat16* Qlg = Ql + (size_t)bh * CS * CDQK;
    const __nv_bfloat16* Khg = Kh + (size_t)bh * CS * CDQK;
    const __nv_bfloat16* Klg = Kl + (size_t)bh * CS * CDQK;
    const __nv_bfloat16* Vhg = Vh + (size_t)bh * CHD * CS;
    const __nv_bfloat16* Vlg = Vl + (size_t)bh * CHD * CS;

    auto issue_kv = [&](int stg, int k0) {
        uint32_t base = sb + FKV0 + stg * FKV_STAGE;
#pragma unroll
        for (int it = 0; it < 4; it++) {
            int i = it * 256 + tid;
            int row = i >> 4, ch = i & 15;
            size_t off = (size_t)(k0 + row) * CDQK + ch * 8;
            uint32_t so = fsw(row, ch);
            CP_ASYNC16(base + FO_KH + so, Khg + off);
            CP_ASYNC16(base + FO_KL + so, Klg + off);
        }
#pragma unroll
        for (int it = 0; it < 2; it++) {
            int i = it * 256 + tid;
            int row = i >> 3, ch = i & 7;
            size_t off = (size_t)row * CS + k0 + ch * 8;
            uint32_t so = vsw(row, ch);
            CP_ASYNC16(base + FO_VH + so, Vhg + off);
            CP_ASYNC16(base + FO_VL + so, Vlg + off);
        }
        CP_COMMIT();
    };

    issue_kv(0, 0);
#pragma unroll
    for (int it = 0; it < 8; it++) {
        int i = it * 256 + tid;
        int row = i >> 4, ch = i & 15;
        size_t off = (size_t)(q0 + row) * CDQK + ch * 8;
        *(uint4*)(smem + FQH + fsw(row, ch)) = *(const uint4*)(Qhg + off);
        *(uint4*)(smem + FQL + fsw(row, ch)) = *(const uint4*)(Qlg + off);
    }

    const int a_tr = (lid & 7) + ((lid >> 3) & 1) * 8;
    const int a_kq = lid >> 4;
    const int b_tr = (lid & 7) + (lid >> 4) * 8;
    const int b_kq = (lid >> 3) & 1;

    float O[8][4];
#pragma unroll
    for (int na = 0; na < 8; na++)
#pragma unroll
        for (int e = 0; e < 4; e++) O[na][e] = 0.f;
    float mI0 = -1e30f, mI1 = -1e30f, lI0 = 0.f, lI1 = 0.f;
    const float scale = 0.08838834764831845f;

    const int qw_last = q0 + wid * 16 + 15;
    const int nkb = 2 * qb + 2;
    int st = 0;

    for (int kb = 0; kb < nkb; kb++) {
        const int k0 = kb * 64;
        __syncthreads();
        if (kb + 1 < nkb) { issue_kv(st ^ 1, k0 + 64); CP_WAIT(1); }
        else              { CP_WAIT(0); }
        __syncthreads();

        if (k0 <= qw_last) {
            uint32_t kvb = sb + FKV0 + st * FKV_STAGE;

            float sc[8][4];
#pragma unroll
            for (int na = 0; na < 8; na++)
#pragma unroll
                for (int e = 0; e < 4; e++) sc[na][e] = 0.f;

#pragma unroll
            for (int ks = 0; ks < 8; ks++) {
                uint32_t ah[4], al[4], khf[8][2], klf[8][2];
                LDSM_X4(ah[0], ah[1], ah[2], ah[3],
                        sb + FQH + fsw(wid * 16 + a_tr, ks * 2 + a_kq));
                LDSM_X4(al[0], al[1], al[2], al[3],
                        sb + FQL + fsw(wid * 16 + a_tr, ks * 2 + a_kq));
#pragma unroll
                for (int nb = 0; nb < 4; nb++) {
                    uint32_t so = fsw(nb * 16 + b_tr, ks * 2 + b_kq);
                    LDSM_X4(khf[nb*2][0], khf[nb*2][1], khf[nb*2+1][0], khf[nb*2+1][1], kvb + FO_KH + so);
                    LDSM_X4(klf[nb*2][0], klf[nb*2][1], klf[nb*2+1][0], klf[nb*2+1][1], kvb + FO_KL + so);
                }
#pragma unroll
                for (int na = 0; na < 8; na++) {
                    MMA16816(sc[na], ah, khf[na]);
                    MMA16816(sc[na], ah, klf[na]);
                    MMA16816(sc[na], al, khf[na]);
                }
            }

            if (k0 + 63 > qw_last - 15) {
#pragma unroll
                for (int na = 0; na < 8; na++)
#pragma unroll
                    for (int e = 0; e < 4; e++) {
                        int qr = q0 + wid * 16 + g + ((e >> 1) << 3);
                        int kc = k0 + na * 8 + 2 * t + (e & 1);
                        sc[na][e] = (kc > qr) ? -1e30f : sc[na][e] * scale;
                    }
            } else {
#pragma unroll
                for (int na = 0; na < 8; na++)
#pragma unroll
                    for (int e = 0; e < 4; e++) sc[na][e] *= scale;
            }

            float mx0 = -1e30f, mx1 = -1e30f;
#pragma unroll
            for (int na = 0; na < 8; na++) {
                mx0 = fmaxf(mx0, fmaxf(sc[na][0], sc[na][1]));
                mx1 = fmaxf(mx1, fmaxf(sc[na][2], sc[na][3]));
            }
            mx0 = fmaxf(mx0, __shfl_xor_sync(0xffffffffu, mx0, 1));
            mx0 = fmaxf(mx0, __shfl_xor_sync(0xffffffffu, mx0, 2));
            mx1 = fmaxf(mx1, __shfl_xor_sync(0xffffffffu, mx1, 1));
            mx1 = fmaxf(mx1, __shfl_xor_sync(0xffffffffu, mx1, 2));

            float mn0 = fmaxf(mI0, mx0), mn1 = fmaxf(mI1, mx1);
            float al0 = __expf(mI0 - mn0), al1 = __expf(mI1 - mn1);
            mI0 = mn0; mI1 = mn1;

            float rs0 = 0.f, rs1 = 0.f;
#pragma unroll
            for (int na = 0; na < 8; na++) {
                sc[na][0] = __expf(sc[na][0] - mn0); rs0 += sc[na][0];
                sc[na][1] = __expf(sc[na][1] - mn0); rs0 += sc[na][1];
                sc[na][2] = __expf(sc[na][2] - mn1); rs1 += sc[na][2];
                sc[na][3] = __expf(sc[na][3] - mn1); rs1 += sc[na][3];
            }
            rs0 += __shfl_xor_sync(0xffffffffu, rs0, 1);
            rs0 += __shfl_xor_sync(0xffffffffu, rs0, 2);
            rs1 += __shfl_xor_sync(0xffffffffu, rs1, 1);
            rs1 += __shfl_xor_sync(0xffffffffu, rs1, 2);
            lI0 = lI0 * al0 + rs0;
            lI1 = lI1 * al1 + rs1;

#pragma unroll
            for (int na = 0; na < 8; na++) {
                O[na][0] *= al0; O[na][1] *= al0;
                O[na][2] *= al1; O[na][3] *= al1;
            }

#pragma unroll
            for (int kk = 0; kk < 4; kk++) {
                uint32_t pah[4], pal[4];
                split2(sc[2*kk][0],   sc[2*kk][1],   pah[0], pal[0]);
                split2(sc[2*kk][2],   sc[2*kk][3],   pah[1], pal[1]);
                split2(sc[2*kk+1][0], sc[2*kk+1][1], pah[2], pal[2]);
                split2(sc[2*kk+1][2], sc[2*kk+1][3], pah[3], pal[3]);
                uint32_t vhf[8][2], vlf[8][2];
#pragma unroll
                for (int nb = 0; nb < 4; nb++) {
                    uint32_t so = vsw(nb * 16 + b_tr, kk * 2 + b_kq);
                    LDSM_X4(vhf[nb*2][0], vhf[nb*2][1], vhf[nb*2+1][0], vhf[nb*2+1][1], kvb + FO_VH + so);
                    LDSM_X4(vlf[nb*2][0], vlf[nb*2][1], vlf[nb*2+1][0], vlf[nb*2+1][1], kvb + FO_VL + so);
                }
#pragma unroll
                for (int na = 0; na < 8; na++) {
                    MMA16816(O[na], pah, vhf[na]);
                    MMA16816(O[na], pal, vhf[na]);
                    MMA16816(O[na], pah, vlf[na]);
                }
            }
        }
        st ^= 1;
    }

    // ---- epilogue -----------------------------------------------------
    const int b = bh >> 4, h = bh & 15;
    const float inv0 = 1.f / lI0, inv1 = 1.f / lI1;
    const int qr0 = q0 + wid * 16 + g;
#pragma unroll
    for (int na = 0; na < 8; na++) {
        int col = h * CHD + na * 8 + 2 * t;
        uint32_t h0, l0;
        split2(O[na][0] * inv0, O[na][1] * inv0, h0, l0);
        *(uint32_t*)(Yh + (size_t)(b*CS + qr0) * CE + col) = h0;
        *(uint32_t*)(Yl + (size_t)(b*CS + qr0) * CE + col) = l0;
        split2(O[na][2] * inv1, O[na][3] * inv1, h0, l0);
        *(uint32_t*)(Yh + (size_t)(b*CS + qr0 + 8) * CE + col) = h0;
        *(uint32_t*)(Yl + (size_t)(b*CS + qr0 + 8) * CE + col) = l0;
    }
}

// ============================== launcher ===================================
extern "C" void kernel_launch(void* const* d_in, const int* in_sizes, int n_in,
                              void* d_out, int out_size)
{
    const float* x        = (const float*)d_in[0];
    const float* wq_down  = (const float*)d_in[1];
    const float* wk_rope  = (const float*)d_in[2];
    const float* wkv_down = (const float*)d_in[3];
    const float* wq_rope  = (const float*)d_in[4];
    const float* wq_up    = (const float*)d_in[5];
    const float* wk_up    = (const float*)d_in[6];
    const float* wv_up    = (const float*)d_in[7];
    const float* wo       = (const float*)d_in[8];
    float* out = (float*)d_out;

    __nv_bfloat16 *xh,*xl,*lath,*latl,*Yh,*Yl,*wdh,*wdl,*wuh,*wul,*w7h,*w7l;
    __nv_bfloat16 *Qbh,*Qbl,*Kbh,*Kbl,*Vbh,*Vbl;
    cudaGetSymbolAddress((void**)&xh,   g_xh);   cudaGetSymbolAddress((void**)&xl,   g_xl);
    cudaGetSymbolAddress((void**)&lath, g_lath); cudaGetSymbolAddress((void**)&latl, g_latl);
    cudaGetSymbolAddress((void**)&Yh,   g_Yh);   cudaGetSymbolAddress((void**)&Yl,   g_Yl);
    cudaGetSymbolAddress((void**)&wdh,  g_wdh);  cudaGetSymbolAddress((void**)&wdl,  g_wdl);
    cudaGetSymbolAddress((void**)&wuh,  g_wuh);  cudaGetSymbolAddress((void**)&wul,  g_wul);
    cudaGetSymbolAddress((void**)&w7h,  g_w7h);  cudaGetSymbolAddress((void**)&w7l,  g_w7l);
    cudaGetSymbolAddress((void**)&Qbh,  g_Qbh);  cudaGetSymbolAddress((void**)&Qbl,  g_Qbl);
    cudaGetSymbolAddress((void**)&Kbh,  g_Kbh);  cudaGetSymbolAddress((void**)&Kbl,  g_Kbl);
    cudaGetSymbolAddress((void**)&Vbh,  g_Vbh);  cudaGetSymbolAddress((void**)&Vbl,  g_Vbl);

    cudaFuncSetAttribute(gemm_ms<0>, cudaFuncAttributeMaxDynamicSharedMemorySize, GEMM_SMEM);
    cudaFuncSetAttribute(gemm_ms<1>, cudaFuncAttributeMaxDynamicSharedMemorySize, GEMM_SMEM);
    cudaFuncSetAttribute(gemm_ms<7>, cudaFuncAttributeMaxDynamicSharedMemorySize, GEMM_SMEM);
    cudaFuncSetAttribute(flash_attn_mma, cudaFuncAttributeMaxDynamicSharedMemorySize, FLASH_SMEM);

    // conversions (2 launches)
    cvt_split<<<(MTOK*CE + 255) / 256, 256>>>(x, xh, xl, MTOK*CE);
    cvt_weights<<<(8*WSEG + CE*CE + 255) / 256, 256>>>(
        wq_down, wk_rope, wkv_down, wq_rope, wq_up, wk_up, wv_up, wo,
        wdh, wdl, wuh, wul, w7h, w7l);

    dim3 blk(256);
    // fused down projection: lat[4096,768] = x @ [wq_down|wk_rope|wkv_down]^T
    gemm_ms<1><<<dim3(NLAT/128, MTOK/128), blk, GEMM_SMEM>>>(
        xh, xl, CE, wdh, wdl, CE, nullptr, lath, latl, nullptr, nullptr,
        nullptr, nullptr, NLAT, CE);

    // mega up-projection: all 5 up-GEMMs in one launch -> Q, K, V
    gemm_ms<7><<<dim3(40, MTOK/128), blk, GEMM_SMEM>>>(
        lath, latl, NLAT, wuh, wul, CR, nullptr, Qbh, Qbl, Kbh, Kbl,
        Vbh, Vbl, 0, CR);

    // causal flash attention (LPT-ordered grid) -> Yh/Yl
    flash_attn_mma<<<dim3(CB*CH, NQB), 256, FLASH_SMEM>>>(
        Qbh, Qbl, Kbh, Kbl, Vbh, Vbl, Yh, Yl);

    // output projection: Y @ wo^T -> out (fp32)
    gemm_ms<0><<<dim3(CE/128, MTOK/128), blk, GEMM_SMEM>>>(
        Yh, Yl, CE, w7h, w7l, CE, out, nullptr, nullptr, nullptr, nullptr,
        nullptr, nullptr, CE, CE);
}

// round 12
// speedup vs baseline: 3.6965x; 1.0055x over previous
#include <cuda_runtime.h>
#include <cuda_bf16.h>
#include <cstdint>
#include <math.h>

#define CB   2
#define CS   2048
#define CE   1024
#define CR   256
#define CH   16
#define CHD  64
#define CDQK 128
#define MTOK (CB*CS)   // 4096
#define NLAT 768       // 3 x 256 concatenated latents
#define WSEG (CR*CE)   // 262144

// ---------------- scratch (no allocation allowed -> __device__ globals) ----
__device__ __nv_bfloat16 g_xh [MTOK*CE],  g_xl [MTOK*CE];
__device__ __nv_bfloat16 g_lath[MTOK*NLAT], g_latl[MTOK*NLAT];
__device__ __nv_bfloat16 g_Yh [MTOK*CE],  g_Yl [MTOK*CE];
__device__ __nv_bfloat16 g_wdh[NLAT*CE],  g_wdl[NLAT*CE];      // wq_down|wk_rope|wkv_down
__device__ __nv_bfloat16 g_wuh[5*WSEG],   g_wul[5*WSEG];       // wq_rope|wq_up|wk_up|wk_up|wv_up
__device__ __nv_bfloat16 g_w7h[CE*CE],    g_w7l[CE*CE];        // wo

__device__ __nv_bfloat16 g_Qbh[CB*CH*CS*CDQK], g_Qbl[CB*CH*CS*CDQK];  // [b,h,s,128]
__device__ __nv_bfloat16 g_Kbh[CB*CH*CS*CDQK], g_Kbl[CB*CH*CS*CDQK];  // [b,h,s,128]
__device__ __nv_bfloat16 g_Vbh[CB*CH*CHD*CS],  g_Vbl[CB*CH*CHD*CS];   // [b,h,d,s]

// ===================== generic helpers =====================================
__device__ __forceinline__ uint32_t smem_to_u32(const void* p) {
    uint32_t a;
    asm("{ .reg .u64 t; cvta.to.shared.u64 t, %1; cvt.u32.u64 %0, t; }" : "=r"(a) : "l"(p));
    return a;
}

#define LDSM_X4(r0,r1,r2,r3, addr) \
    asm volatile("ldmatrix.sync.aligned.m8n8.x4.shared.b16 {%0,%1,%2,%3}, [%4];" \
        : "=r"(r0), "=r"(r1), "=r"(r2), "=r"(r3) : "r"(addr))

#define MMA16816(c, a, b) \
    asm volatile("mma.sync.aligned.m16n8k16.row.col.f32.bf16.bf16.f32 " \
        "{%0,%1,%2,%3}, {%4,%5,%6,%7}, {%8,%9}, {%0,%1,%2,%3};" \
        : "+f"((c)[0]), "+f"((c)[1]), "+f"((c)[2]), "+f"((c)[3]) \
        : "r"((a)[0]), "r"((a)[1]), "r"((a)[2]), "r"((a)[3]), "r"((b)[0]), "r"((b)[1]))

#define CP_ASYNC16(dst, src) \
    asm volatile("cp.async.cg.shared.global [%0], [%1], 16;" :: "r"(dst), "l"(src))
#define CP_COMMIT() asm volatile("cp.async.commit_group;" ::: "memory")
#define CP_WAIT(n)  asm volatile("cp.async.wait_group %0;" :: "n"(n) : "memory")

__device__ __forceinline__ void split2(float a, float b, uint32_t& hi, uint32_t& lo) {
    __nv_bfloat16 ha = __float2bfloat16(a), hb = __float2bfloat16(b);
    float ra = a - __bfloat162float(ha);
    float rb = b - __bfloat162float(hb);
    __nv_bfloat162 hh; hh.x = ha; hh.y = hb;
    hi = *(uint32_t*)&hh;
    __nv_bfloat162 ll = __floats2bfloat162_rn(ra, rb);
    lo = *(uint32_t*)&ll;
}

// ===================== split-fp32 converts =================================
__global__ void cvt_split(const float* __restrict__ src,
                          __nv_bfloat16* __restrict__ hi, __nv_bfloat16* __restrict__ lo, int n)
{
    int i = blockIdx.x * blockDim.x + threadIdx.x;
    if (i < n) {
        float v = src[i];
        __nv_bfloat16 h = __float2bfloat16(v);
        hi[i] = h;
        lo[i] = __float2bfloat16(v - __bfloat162float(h));
    }
}

// all weight tensors in one launch (wk_up written twice into the up buffer)
__global__ void cvt_weights(
    const float* __restrict__ wq_down, const float* __restrict__ wk_rope,
    const float* __restrict__ wkv_down, const float* __restrict__ wq_rope,
    const float* __restrict__ wq_up,   const float* __restrict__ wk_up,
    const float* __restrict__ wv_up,   const float* __restrict__ wo,
    __nv_bfloat16* __restrict__ wdh,  __nv_bfloat16* __restrict__ wdl,
    __nv_bfloat16* __restrict__ wuh,  __nv_bfloat16* __restrict__ wul,
    __nv_bfloat16* __restrict__ w7h,  __nv_bfloat16* __restrict__ w7l)
{
    int i = blockIdx.x * blockDim.x + threadIdx.x;
    const float* src;
    __nv_bfloat16 *dh, *dl;
    int off;
    if (i < 8 * WSEG) {
        int seg = i / WSEG;
        off = i - seg * WSEG;
        switch (seg) {
            case 0: src = wq_down;  dh = wdh;          dl = wdl;          break;
            case 1: src = wk_rope;  dh = wdh + WSEG;   dl = wdl + WSEG;   break;
            case 2: src = wkv_down; dh = wdh + 2*WSEG; dl = wdl + 2*WSEG; break;
            case 3: src = wq_rope;  dh = wuh;          dl = wul;          break;
            case 4: src = wq_up;    dh = wuh + WSEG;   dl = wul + WSEG;   break;
            case 5: src = wk_up;    dh = wuh + 2*WSEG; dl = wul + 2*WSEG; break;
            case 6: src = wk_up;    dh = wuh + 3*WSEG; dl = wul + 3*WSEG; break;
            default: src = wv_up;   dh = wuh + 4*WSEG; dl = wul + 4*WSEG; break;
        }
    } else {
        off = i - 8 * WSEG;
        if (off >= CE * CE) return;
        src = wo; dh = w7h; dl = w7l;
    }
    float v = src[off];
    __nv_bfloat16 h = __float2bfloat16(v);
    dh[off] = h;
    dl[off] = __float2bfloat16(v - __bfloat162float(h));
}

// ============= tensor-core split-bf16 GEMM NT, cp.async 3-stage ============
// C[M,N] = A[M,K] * B[N,K]^T. CTA tile 128x128, 256 threads, 2 CTAs/SM.
// One __syncthreads per K-chunk; issue chunk i+2 right after the barrier.
// MODE 0: fp32; 1: split hi/lo
// MODE 7: mega up-projection (see dispatch below)
#define GEMM_SMEM (3*32768)
#define MS_AH 0
#define MS_AL 8192
#define MS_BH 16384
#define MS_BL 24576
#define MS_STAGE 32768
#define ROPE_L 0.41524101186109f

__device__ __forceinline__ uint32_t msw(int row, int c) {
    return (uint32_t)(row * 64 + ((c ^ ((row >> 1) & 3)) << 4));
}

template<int MODE>
__global__ __launch_bounds__(256, 2) void gemm_ms(
    const __nv_bfloat16* __restrict__ Ah, const __nv_bfloat16* __restrict__ Al, int lda,
    const __nv_bfloat16* __restrict__ Bh, const __nv_bfloat16* __restrict__ Bl, int ldb,
    float* __restrict__ Cf, __nv_bfloat16* __restrict__ Ch, __nv_bfloat16* __restrict__ Cl,
    __nv_bfloat16* __restrict__ Dh, __nv_bfloat16* __restrict__ Dl,
    __nv_bfloat16* __restrict__ Eh, __nv_bfloat16* __restrict__ El,
    int ldc, int K)
{
    extern __shared__ char smem[];
    const int tid = threadIdx.x, wid = tid >> 5, lid = tid & 31;
    const int m0 = blockIdx.y * 128, n0 = blockIdx.x * 128;
    uint32_t sb = smem_to_u32(smem);

    if (MODE == 7) {
        int nb = blockIdx.x;
        int aoff = (nb < 16) ? 0 : ((nb < 24) ? CR : 2 * CR);
        Ah += aoff; Al += aoff;
    }

    const int mw = wid & 3, nw = wid >> 2;
    const int a_tr = (lid & 7) + ((lid >> 3) & 1) * 8;
    const int a_kq = lid >> 4;
    const int b_tr = (lid & 7) + (lid >> 4) * 8;
    const int b_kq = (lid >> 3) & 1;

    float acc[2][8][4];
#pragma unroll
    for (int i = 0; i < 2; i++)
#pragma unroll
        for (int j = 0; j < 8; j++)
#pragma unroll
            for (int q = 0; q < 4; q++) acc[i][j][q] = 0.f;

    auto issue = [&](int stg, int k0) {
        uint32_t base = sb + stg * MS_STAGE;
#pragma unroll
        for (int it = 0; it < 2; it++) {
            int ch = it * 256 + tid;
            int row = ch >> 2, c = ch & 3;
            uint32_t so = msw(row, c);
            size_t ga = (size_t)(m0 + row) * lda + k0 + c * 8;
            size_t gb = (size_t)(n0 + row) * ldb + k0 + c * 8;
            CP_ASYNC16(base + MS_AH + so, Ah + ga);
            CP_ASYNC16(base + MS_AL + so, Al + ga);
            CP_ASYNC16(base + MS_BH + so, Bh + gb);
            CP_ASYNC16(base + MS_BL + so, Bl + gb);
        }
        CP_COMMIT();
    };

    const int niter = K >> 5;
    issue(0, 0);
    if (niter > 1) issue(1, 32);

    for (int it = 0; it < niter; it++) {
        if (it + 1 < niter) { CP_WAIT(1); } else { CP_WAIT(0); }
        __syncthreads();
        if (it + 2 < niter) issue((it + 2) % 3, (it + 2) * 32);

        uint32_t base = sb + (it % 3) * MS_STAGE;
#pragma unroll
        for (int ks = 0; ks < 2; ks++) {
            uint32_t ah[2][4], al[2][4], bh[8][2], bl[8][2];
#pragma unroll
            for (int ma = 0; ma < 2; ma++) {
                int row = mw * 32 + ma * 16 + a_tr;
                int c = ks * 2 + a_kq;
                LDSM_X4(ah[ma][0], ah[ma][1], ah[ma][2], ah[ma][3], base + MS_AH + msw(row, c));
                LDSM_X4(al[ma][0], al[ma][1], al[ma][2], al[ma][3], base + MS_AL + msw(row, c));
            }
#pragma unroll
            for (int nb = 0; nb < 4; nb++) {
                int row = nw * 64 + nb * 16 + b_tr;
                int c = ks * 2 + b_kq;
                LDSM_X4(bh[nb*2][0], bh[nb*2][1], bh[nb*2+1][0], bh[nb*2+1][1], base + MS_BH + msw(row, c));
                LDSM_X4(bl[nb*2][0], bl[nb*2][1], bl[nb*2+1][0], bl[nb*2+1][1], base + MS_BL + msw(row, c));
            }
#pragma unroll
            for (int ma = 0; ma < 2; ma++)
#pragma unroll
                for (int na = 0; na < 8; na++) {
                    MMA16816(acc[ma][na], ah[ma], bh[na]);
                    MMA16816(acc[ma][na], ah[ma], bl[na]);
                    MMA16816(acc[ma][na], al[ma], bh[na]);
                }
        }
    }

    // ----------------------- fused epilogues -------------------------------
    const int g = lid >> 2, t4 = lid & 3;
    const int ncol = n0 + nw * 64;   // warp-uniform column base

    if (MODE == 0) {
#pragma unroll
        for (int ma = 0; ma < 2; ma++) {
            int row0 = m0 + mw * 32 + ma * 16 + g;
#pragma unroll
            for (int na = 0; na < 8; na++) {
                int col = ncol + na * 8 + t4 * 2;
                *(float2*)(Cf + (size_t)row0 * ldc + col) =
                    make_float2(acc[ma][na][0], acc[ma][na][1]);
                *(float2*)(Cf + (size_t)(row0 + 8) * ldc + col) =
                    make_float2(acc[ma][na][2], acc[ma][na][3]);
            }
        }
    } else if (MODE == 1) {
#pragma unroll
        for (int ma = 0; ma < 2; ma++) {
            int row0 = m0 + mw * 32 + ma * 16 + g;
#pragma unroll
            for (int na = 0; na < 8; na++) {
                int col = ncol + na * 8 + t4 * 2;
                uint32_t h0, l0;
                split2(acc[ma][na][0], acc[ma][na][1], h0, l0);
                *(uint32_t*)(Ch + (size_t)row0 * ldc + col) = h0;
                *(uint32_t*)(Cl + (size_t)row0 * ldc + col) = l0;
                split2(acc[ma][na][2], acc[ma][na][3], h0, l0);
                *(uint32_t*)(Ch + (size_t)(row0 + 8) * ldc + col) = h0;
                *(uint32_t*)(Cl + (size_t)(row0 + 8) * ldc + col) = l0;
            }
        }
    } else {
        // MODE 7 dispatch (warp-uniform by ncol)
        const bool is_rope = (ncol < CE) || (ncol >= 2*CE && ncol < 3*CE);
        const bool is_v    = (ncol >= 4*CE);
        __nv_bfloat16 *Oh, *Ol;
        int hq;
        if (ncol < CE)           { Oh = Ch; Ol = Cl; hq = ncol >> 6; }            // rope->Q
        else if (ncol < 2*CE)    { Oh = Ch; Ol = Cl; hq = (ncol - CE) >> 6; }     // nope->Q
        else if (ncol < 3*CE)    { Oh = Dh; Ol = Dl; hq = (ncol - 2*CE) >> 6; }   // rope->K
        else if (ncol < 4*CE)    { Oh = Dh; Ol = Dl; hq = (ncol - 3*CE) >> 6; }   // nope->K
        else                     { Oh = Eh; Ol = El; hq = (ncol - 4*CE) >> 6; }   // vt->V

        if (is_rope) {
#pragma unroll
            for (int ma = 0; ma < 2; ma++) {
                int r0 = m0 + mw * 32 + ma * 16 + g;
                int b = r0 >> 11;
                size_t bb = (size_t)((b << 4) + hq) * CS * CDQK;
#pragma unroll
                for (int rh = 0; rh < 2; rh++) {
                    int s = (r0 + rh * 8) & (CS - 1);
                    size_t base = bb + (size_t)s * CDQK;
                    float fs = (float)s;
#pragma unroll
                    for (int na = 0; na < 4; na++) {
                        int e = rh * 2;
                        int i0 = na * 8 + t4 * 2;
                        float x1a = acc[ma][na][e],   x1b = acc[ma][na][e+1];
                        float x2a = acc[ma][na+4][e], x2b = acc[ma][na+4][e+1];
                        float sn0, cs0, sn1, cs1;
                        sincosf(fs * exp2f(-(float)i0 * ROPE_L), &sn0, &cs0);
                        sincosf(fs * exp2f(-(float)(i0+1) * ROPE_L), &sn1, &cs1);
                        float o1a = x1a*cs0 - x2a*sn0, o1b = x1b*cs1 - x2b*sn1;
                        float o2a = x2a*cs0 + x1a*sn0, o2b = x2b*cs1 + x1b*sn1;
                        uint32_t h0, l0;
                        split2(o1a, o1b, h0, l0);
                        *(uint32_t*)(Oh + base + i0) = h0;
                        *(uint32_t*)(Ol + base + i0) = l0;
                        split2(o2a, o2b, h0, l0);
                        *(uint32_t*)(Oh + base + 32 + i0) = h0;
                        *(uint32_t*)(Ol + base + 32 + i0) = l0;
                    }
                }
            }
        } else if (!is_v) {
            // nope -> [b,h,s,64:128]
#pragma unroll
            for (int ma = 0; ma < 2; ma++) {
                int r0 = m0 + mw * 32 + ma * 16 + g;
                int b = r0 >> 11;
                size_t bb = (size_t)((b << 4) + hq) * CS * CDQK;
#pragma unroll
                for (int rh = 0; rh < 2; rh++) {
                    int s = (r0 + rh * 8) & (CS - 1);
                    size_t base = bb + (size_t)s * CDQK + 64;
#pragma unroll
                    for (int na = 0; na < 8; na++) {
                        int d0 = na * 8 + t4 * 2;
                        uint32_t h0, l0;
                        split2(acc[ma][na][rh*2], acc[ma][na][rh*2+1], h0, l0);
                        *(uint32_t*)(Oh + base + d0) = h0;
                        *(uint32_t*)(Ol + base + d0) = l0;
                    }
                }
            }
        } else {
            // vt -> V [b,h,d,s]
#pragma unroll
            for (int ma = 0; ma < 2; ma++) {
                int r0 = m0 + mw * 32 + ma * 16 + g;
                int b = r0 >> 11;
                size_t bb = (size_t)((b << 4) + hq) * CHD;
#pragma unroll
                for (int rh = 0; rh < 2; rh++) {
                    int s = (r0 + rh * 8) & (CS - 1);
#pragma unroll
                    for (int na = 0; na < 8; na++) {
#pragma unroll
                        for (int j = 0; j < 2; j++) {
                            int d = na * 8 + t4 * 2 + j;
                            float v = acc[ma][na][rh*2 + j];
                            __nv_bfloat16 hv = __float2bfloat16(v);
                            size_t o = (bb + d) * CS + s;
                            Oh[o] = hv;
                            Ol[o] = __float2bfloat16(v - __bfloat162float(hv));
                        }
                    }
                }
            }
        }
    }
}

// =================== causal flash attention, cp.async K/V 3-stage ==========
// BQ=128, 256 threads; K/V tiles 64 wide, triple-buffered, 1 sync/tile.
#define FQH 0
#define FQL 32768
#define FKV0 65536
#define FKV_STAGE 49152
#define FO_KH 0
#define FO_KL 16384
#define FO_VH 32768
#define FO_VL 40960
#define FLASH_SMEM (65536 + 3*49152)   // 212992
#define NQB (CS/128)

__device__ __forceinline__ uint32_t fsw(int row, int chunk) {
    return (uint32_t)(row * 256 + ((chunk >> 3) << 7) + (((chunk & 7) ^ (row & 7)) << 4));
}
__device__ __forceinline__ uint32_t vsw(int row, int chunk) {
    return (uint32_t)(row * 128 + ((chunk ^ (row & 7)) << 4));
}

__global__ __launch_bounds__(256) void flash_attn_mma(
    const __nv_bfloat16* __restrict__ Qh, const __nv_bfloat16* __restrict__ Ql,
    const __nv_bfloat16* __restrict__ Kh, const __nv_bfloat16* __restrict__ Kl,
    const __nv_bfloat16* __restrict__ Vh, const __nv_bfloat16* __restrict__ Vl,
    __nv_bfloat16* __restrict__ Yh, __nv_bfloat16* __restrict__ Yl)
{
    extern __shared__ char smem[];
    uint32_t sb = smem_to_u32(smem);
    const int tid = threadIdx.x, wid = tid >> 5, lid = tid & 31;
    const int bh = blockIdx.x;
    const int qb = NQB - 1 - blockIdx.y;   // LPT: longest first
    const int q0 = qb * 128;
    const int g = lid >> 2, t = lid & 3;

    const __nv_bfloat16* Qhg = Qh + (size_t)bh * CS * CDQK;
    const __nv_bfloat16* Qlg = Ql + (size_t)bh * CS * CDQK;
    const __nv_bfloat16* Khg = Kh + (size_t)bh * CS * CDQK;
    const __nv_bfloat16* Klg = Kl + (size_t)bh * CS * CDQK;
    const __nv_bfloat16* Vhg = Vh + (size_t)bh * CHD * CS;
    const __nv_bfloat16* Vlg = Vl + (size_t)bh * CHD * CS;

    auto issue_kv = [&](int stg, int k0) {
        uint32_t base = sb + FKV0 + stg * FKV_STAGE;
#pragma unroll
        for (int it = 0; it < 4; it++) {
            int i = it * 256 + tid;
            int row = i >> 4, ch = i & 15;
            size_t off = (size_t)(k0 + row) * CDQK + ch * 8;
            uint32_t so = fsw(row, ch);
            CP_ASYNC16(base + FO_KH + so, Khg + off);
            CP_ASYNC16(base + FO_KL + so, Klg + off);
        }
#pragma unroll
        for (int it = 0; it < 2; it++) {
            int i = it * 256 + tid;
            int row = i >> 3, ch = i & 7;
            size_t off = (size_t)row * CS + k0 + ch * 8;
            uint32_t so = vsw(row, ch);
            CP_ASYNC16(base + FO_VH + so, Vhg + off);
            CP_ASYNC16(base + FO_VL + so, Vlg + off);
        }
        CP_COMMIT();
    };

    const int nkb = 2 * qb + 2;
    issue_kv(0, 0);
    if (nkb > 1) issue_kv(1, 64);

    // Q tile load (plain loads; visibility covered by the loop's first barrier)
#pragma unroll
    for (int it = 0; it < 8; it++) {
        int i = it * 256 + tid;
        int row = i >> 4, ch = i & 15;
        size_t off = (size_t)(q0 + row) * CDQK + ch * 8;
        *(uint4*)(smem + FQH + fsw(row, ch)) = *(const uint4*)(Qhg + off);
        *(uint4*)(smem + FQL + fsw(row, ch)) = *(const uint4*)(Qlg + off);
    }

    const int a_tr = (lid & 7) + ((lid >> 3) & 1) * 8;
    const int a_kq = lid >> 4;
    const int b_tr = (lid & 7) + (lid >> 4) * 8;
    const int b_kq = (lid >> 3) & 1;

    float O[8][4];
#pragma unroll
    for (int na = 0; na < 8; na++)
#pragma unroll
        for (int e = 0; e < 4; e++) O[na][e] = 0.f;
    float mI0 = -1e30f, mI1 = -1e30f, lI0 = 0.f, lI1 = 0.f;
    const float scale = 0.08838834764831845f;

    const int qw_last = q0 + wid * 16 + 15;

    for (int kb = 0; kb < nkb; kb++) {
        const int k0 = kb * 64;
        if (kb + 1 < nkb) { CP_WAIT(1); } else { CP_WAIT(0); }
        __syncthreads();
        if (kb + 2 < nkb) issue_kv((kb + 2) % 3, (kb + 2) * 64);

        if (k0 <= qw_last) {
            uint32_t kvb = sb + FKV0 + (kb % 3) * FKV_STAGE;

            float sc[8][4];
#pragma unroll
            for (int na = 0; na < 8; na++)
#pragma unroll
                for (int e = 0; e < 4; e++) sc[na][e] = 0.f;

#pragma unroll
            for (int ks = 0; ks < 8; ks++) {
                uint32_t ah[4], al[4], khf[8][2], klf[8][2];
                LDSM_X4(ah[0], ah[1], ah[2], ah[3],
                        sb + FQH + fsw(wid * 16 + a_tr, ks * 2 + a_kq));
                LDSM_X4(al[0], al[1], al[2], al[3],
                        sb + FQL + fsw(wid * 16 + a_tr, ks * 2 + a_kq));
#pragma unroll
                for (int nb = 0; nb < 4; nb++) {
                    uint32_t so = fsw(nb * 16 + b_tr, ks * 2 + b_kq);
                    LDSM_X4(khf[nb*2][0], khf[nb*2][1], khf[nb*2+1][0], khf[nb*2+1][1], kvb + FO_KH + so);
                    LDSM_X4(klf[nb*2][0], klf[nb*2][1], klf[nb*2+1][0], klf[nb*2+1][1], kvb + FO_KL + so);
                }
#pragma unroll
                for (int na = 0; na < 8; na++) {
                    MMA16816(sc[na], ah, khf[na]);
                    MMA16816(sc[na], ah, klf[na]);
                    MMA16816(sc[na], al, khf[na]);
                }
            }

            if (k0 + 63 > qw_last - 15) {
#pragma unroll
                for (int na = 0; na < 8; na++)
#pragma unroll
                    for (int e = 0; e < 4; e++) {
                        int qr = q0 + wid * 16 + g + ((e >> 1) << 3);
                        int kc = k0 + na * 8 + 2 * t + (e & 1);
                        sc[na][e] = (kc > qr) ? -1e30f : sc[na][e] * scale;
                    }
            } else {
#pragma unroll
                for (int na = 0; na < 8; na++)
#pragma unroll
                    for (int e = 0; e < 4; e++) sc[na][e] *= scale;
            }

            float mx0 = -1e30f, mx1 = -1e30f;
#pragma unroll
            for (int na = 0; na < 8; na++) {
                mx0 = fmaxf(mx0, fmaxf(sc[na][0], sc[na][1]));
                mx1 = fmaxf(mx1, fmaxf(sc[na][2], sc[na][3]));
            }
            mx0 = fmaxf(mx0, __shfl_xor_sync(0xffffffffu, mx0, 1));
            mx0 = fmaxf(mx0, __shfl_xor_sync(0xffffffffu, mx0, 2));
            mx1 = fmaxf(mx1, __shfl_xor_sync(0xffffffffu, mx1, 1));
            mx1 = fmaxf(mx1, __shfl_xor_sync(0xffffffffu, mx1, 2));

            float mn0 = fmaxf(mI0, mx0), mn1 = fmaxf(mI1, mx1);
            float al0 = __expf(mI0 - mn0), al1 = __expf(mI1 - mn1);
            mI0 = mn0; mI1 = mn1;

            float rs0 = 0.f, rs1 = 0.f;
#pragma unroll
            for (int na = 0; na < 8; na++) {
                sc[na][0] = __expf(sc[na][0] - mn0); rs0 += sc[na][0];
                sc[na][1] = __expf(sc[na][1] - mn0); rs0 += sc[na][1];
                sc[na][2] = __expf(sc[na][2] - mn1); rs1 += sc[na][2];
                sc[na][3] = __expf(sc[na][3] - mn1); rs1 += sc[na][3];
            }
            rs0 += __shfl_xor_sync(0xffffffffu, rs0, 1);
            rs0 += __shfl_xor_sync(0xffffffffu, rs0, 2);
            rs1 += __shfl_xor_sync(0xffffffffu, rs1, 1);
            rs1 += __shfl_xor_sync(0xffffffffu, rs1, 2);
            lI0 = lI0 * al0 + rs0;
            lI1 = lI1 * al1 + rs1;

#pragma unroll
            for (int na = 0; na < 8; na++) {
                O[na][0] *= al0; O[na][1] *= al0;
                O[na][2] *= al1; O[na][3] *= al1;
            }

#pragma unroll
            for (int kk = 0; kk < 4; kk++) {
                uint32_t pah[4], pal[4];
                split2(sc[2*kk][0],   sc[2*kk][1],   pah[0], pal[0]);
                split2(sc[2*kk][2],   sc[2*kk][3],   pah[1], pal[1]);
                split2(sc[2*kk+1][0], sc[2*kk+1][1], pah[2], pal[2]);
                split2(sc[2*kk+1][2], sc[2*kk+1][3], pah[3], pal[3]);
                uint32_t vhf[8][2], vlf[8][2];
#pragma unroll
                for (int nb = 0; nb < 4; nb++) {
                    uint32_t so = vsw(nb * 16 + b_tr, kk * 2 + b_kq);
                    LDSM_X4(vhf[nb*2][0], vhf[nb*2][1], vhf[nb*2+1][0], vhf[nb*2+1][1], kvb + FO_VH + so);
                    LDSM_X4(vlf[nb*2][0], vlf[nb*2][1], vlf[nb*2+1][0], vlf[nb*2+1][1], kvb + FO_VL + so);
                }
#pragma unroll
                for (int na = 0; na < 8; na++) {
                    MMA16816(O[na], pah, vhf[na]);
                    MMA16816(O[na], pal, vhf[na]);
                    MMA16816(O[na], pah, vlf[na]);
                }
            }
        }
    }

    // ---- epilogue -----------------------------------------------------
    const int b = bh >> 4, h = bh & 15;
    const float inv0 = 1.f / lI0, inv1 = 1.f / lI1;
    const int qr0 = q0 + wid * 16 + g;
#pragma unroll
    for (int na = 0; na < 8; na++) {
        int col = h * CHD + na * 8 + 2 * t;
        uint32_t h0, l0;
        split2(O[na][0] * inv0, O[na][1] * inv0, h0, l0);
        *(uint32_t*)(Yh + (size_t)(b*CS + qr0) * CE + col) = h0;
        *(uint32_t*)(Yl + (size_t)(b*CS + qr0) * CE + col) = l0;
        split2(O[na][2] * inv1, O[na][3] * inv1, h0, l0);
        *(uint32_t*)(Yh + (size_t)(b*CS + qr0 + 8) * CE + col) = h0;
        *(uint32_t*)(Yl + (size_t)(b*CS + qr0 + 8) * CE + col) = l0;
    }
}

// ============================== launcher ===================================
extern "C" void kernel_launch(void* const* d_in, const int* in_sizes, int n_in,
                              void* d_out, int out_size)
{
    const float* x        = (const float*)d_in[0];
    const float* wq_down  = (const float*)d_in[1];
    const float* wk_rope  = (const float*)d_in[2];
    const float* wkv_down = (const float*)d_in[3];
    const float* wq_rope  = (const float*)d_in[4];
    const float* wq_up    = (const float*)d_in[5];
    const float* wk_up    = (const float*)d_in[6];
    const float* wv_up    = (const float*)d_in[7];
    const float* wo       = (const float*)d_in[8];
    float* out = (float*)d_out;

    __nv_bfloat16 *xh,*xl,*lath,*latl,*Yh,*Yl,*wdh,*wdl,*wuh,*wul,*w7h,*w7l;
    __nv_bfloat16 *Qbh,*Qbl,*Kbh,*Kbl,*Vbh,*Vbl;
    cudaGetSymbolAddress((void**)&xh,   g_xh);   cudaGetSymbolAddress((void**)&xl,   g_xl);
    cudaGetSymbolAddress((void**)&lath, g_lath); cudaGetSymbolAddress((void**)&latl, g_latl);
    cudaGetSymbolAddress((void**)&Yh,   g_Yh);   cudaGetSymbolAddress((void**)&Yl,   g_Yl);
    cudaGetSymbolAddress((void**)&wdh,  g_wdh);  cudaGetSymbolAddress((void**)&wdl,  g_wdl);
    cudaGetSymbolAddress((void**)&wuh,  g_wuh);  cudaGetSymbolAddress((void**)&wul,  g_wul);
    cudaGetSymbolAddress((void**)&w7h,  g_w7h);  cudaGetSymbolAddress((void**)&w7l,  g_w7l);
    cudaGetSymbolAddress((void**)&Qbh,  g_Qbh);  cudaGetSymbolAddress((void**)&Qbl,  g_Qbl);
    cudaGetSymbolAddress((void**)&Kbh,  g_Kbh);  cudaGetSymbolAddress((void**)&Kbl,  g_Kbl);
    cudaGetSymbolAddress((void**)&Vbh,  g_Vbh);  cudaGetSymbolAddress((void**)&Vbl,  g_Vbl);

    cudaFuncSetAttribute(gemm_ms<0>, cudaFuncAttributeMaxDynamicSharedMemorySize, GEMM_SMEM);
    cudaFuncSetAttribute(gemm_ms<1>, cudaFuncAttributeMaxDynamicSharedMemorySize, GEMM_SMEM);
    cudaFuncSetAttribute(gemm_ms<7>, cudaFuncAttributeMaxDynamicSharedMemorySize, GEMM_SMEM);
    cudaFuncSetAttribute(flash_attn_mma, cudaFuncAttributeMaxDynamicSharedMemorySize, FLASH_SMEM);

    // conversions (2 launches)
    cvt_split<<<(MTOK*CE + 255) / 256, 256>>>(x, xh, xl, MTOK*CE);
    cvt_weights<<<(8*WSEG + CE*CE + 255) / 256, 256>>>(
        wq_down, wk_rope, wkv_down, wq_rope, wq_up, wk_up, wv_up, wo,
        wdh, wdl, wuh, wul, w7h, w7l);

    dim3 blk(256);
    // fused down projection: lat[4096,768] = x @ [wq_down|wk_rope|wkv_down]^T
    gemm_ms<1><<<dim3(NLAT/128, MTOK/128), blk, GEMM_SMEM>>>(
        xh, xl, CE, wdh, wdl, CE, nullptr, lath, latl, nullptr, nullptr,
        nullptr, nullptr, NLAT, CE);

    // mega up-projection: all 5 up-GEMMs in one launch -> Q, K, V
    gemm_ms<7><<<dim3(40, MTOK/128), blk, GEMM_SMEM>>>(
        lath, latl, NLAT, wuh, wul, CR, nullptr, Qbh, Qbl, Kbh, Kbl,
        Vbh, Vbl, 0, CR);

    // causal flash attention (LPT-ordered grid) -> Yh/Yl
    flash_attn_mma<<<dim3(CB*CH, NQB), 256, FLASH_SMEM>>>(
        Qbh, Qbl, Kbh, Kbl, Vbh, Vbl, Yh, Yl);

    // output projection: Y @ wo^T -> out (fp32)
    gemm_ms<0><<<dim3(CE/128, MTOK/128), blk, GEMM_SMEM>>>(
        Yh, Yl, CE, w7h, w7l, CE, out, nullptr, nullptr, nullptr, nullptr,
        nullptr, nullptr, CE, CE);
}

// round 13
// speedup vs baseline: 3.7060x; 1.0026x over previous
#include <cuda_runtime.h>
#include <cuda_bf16.h>
#include <cstdint>
#include <math.h>

#define CB   2
#define CS   2048
#define CE   1024
#define CR   256
#define CH   16
#define CHD  64
#define CDQK 128
#define MTOK (CB*CS)   // 4096
#define NLAT 768       // 3 x 256 concatenated latents
#define WSEG (CR*CE)   // 262144

// ---------------- scratch (no allocation allowed -> __device__ globals) ----
__device__ __nv_bfloat16 g_xh [MTOK*CE],  g_xl [MTOK*CE];
__device__ __nv_bfloat16 g_lath[MTOK*NLAT], g_latl[MTOK*NLAT];
__device__ __nv_bfloat16 g_Yh [MTOK*CE],  g_Yl [MTOK*CE];
__device__ __nv_bfloat16 g_wdh[NLAT*CE],  g_wdl[NLAT*CE];      // wq_down|wk_rope|wkv_down
__device__ __nv_bfloat16 g_wuh[5*WSEG],   g_wul[5*WSEG];       // wq_rope|wq_up|wk_up|wk_up|wv_up
__device__ __nv_bfloat16 g_w7h[CE*CE],    g_w7l[CE*CE];        // wo
__device__ float g_ropetab[CS*64];                             // [s][i] -> cos,sin pairs

__device__ __nv_bfloat16 g_Qbh[CB*CH*CS*CDQK], g_Qbl[CB*CH*CS*CDQK];  // [b,h,s,128]
__device__ __nv_bfloat16 g_Kbh[CB*CH*CS*CDQK], g_Kbl[CB*CH*CS*CDQK];  // [b,h,s,128]
__device__ __nv_bfloat16 g_Vbh[CB*CH*CHD*CS],  g_Vbl[CB*CH*CHD*CS];   // [b,h,d,s]

// ===================== generic helpers =====================================
__device__ __forceinline__ uint32_t smem_to_u32(const void* p) {
    uint32_t a;
    asm("{ .reg .u64 t; cvta.to.shared.u64 t, %1; cvt.u32.u64 %0, t; }" : "=r"(a) : "l"(p));
    return a;
}

#define LDSM_X4(r0,r1,r2,r3, addr) \
    asm volatile("ldmatrix.sync.aligned.m8n8.x4.shared.b16 {%0,%1,%2,%3}, [%4];" \
        : "=r"(r0), "=r"(r1), "=r"(r2), "=r"(r3) : "r"(addr))

#define MMA16816(c, a, b) \
    asm volatile("mma.sync.aligned.m16n8k16.row.col.f32.bf16.bf16.f32 " \
        "{%0,%1,%2,%3}, {%4,%5,%6,%7}, {%8,%9}, {%0,%1,%2,%3};" \
        : "+f"((c)[0]), "+f"((c)[1]), "+f"((c)[2]), "+f"((c)[3]) \
        : "r"((a)[0]), "r"((a)[1]), "r"((a)[2]), "r"((a)[3]), "r"((b)[0]), "r"((b)[1]))

#define CP_ASYNC16(dst, src) \
    asm volatile("cp.async.cg.shared.global [%0], [%1], 16;" :: "r"(dst), "l"(src))
#define CP_COMMIT() asm volatile("cp.async.commit_group;" ::: "memory")
#define CP_WAIT(n)  asm volatile("cp.async.wait_group %0;" :: "n"(n) : "memory")

__device__ __forceinline__ void split2(float a, float b, uint32_t& hi, uint32_t& lo) {
    __nv_bfloat16 ha = __float2bfloat16(a), hb = __float2bfloat16(b);
    float ra = a - __bfloat162float(ha);
    float rb = b - __bfloat162float(hb);
    __nv_bfloat162 hh; hh.x = ha; hh.y = hb;
    hi = *(uint32_t*)&hh;
    __nv_bfloat162 ll = __floats2bfloat162_rn(ra, rb);
    lo = *(uint32_t*)&ll;
}

#define ROPE_L 0.41524101186109f

// ===================== small prep kernels ==================================
__global__ void cvt_split(const float* __restrict__ src,
                          __nv_bfloat16* __restrict__ hi, __nv_bfloat16* __restrict__ lo, int n)
{
    int i = blockIdx.x * blockDim.x + threadIdx.x;
    if (i < n) {
        float v = src[i];
        __nv_bfloat16 h = __float2bfloat16(v);
        hi[i] = h;
        lo[i] = __float2bfloat16(v - __bfloat162float(h));
    }
}

// rope cos/sin LUT: tab[s*64 + i*2] = cos, +1 = sin  (bitwise-identical math)
__global__ void build_rope_tab(float* __restrict__ tab)
{
    int idx = blockIdx.x * blockDim.x + threadIdx.x;   // CS*32
    int s = idx >> 5, i = idx & 31;
    float ang = (float)s * exp2f(-(float)i * ROPE_L);
    float sn, cs;
    sincosf(ang, &sn, &cs);
    tab[(idx << 1)]     = cs;
    tab[(idx << 1) + 1] = sn;
}

// all weight tensors in one launch (wk_up written twice into the up buffer)
__global__ void cvt_weights(
    const float* __restrict__ wq_down, const float* __restrict__ wk_rope,
    const float* __restrict__ wkv_down, const float* __restrict__ wq_rope,
    const float* __restrict__ wq_up,   const float* __restrict__ wk_up,
    const float* __restrict__ wv_up,   const float* __restrict__ wo,
    __nv_bfloat16* __restrict__ wdh,  __nv_bfloat16* __restrict__ wdl,
    __nv_bfloat16* __restrict__ wuh,  __nv_bfloat16* __restrict__ wul,
    __nv_bfloat16* __restrict__ w7h,  __nv_bfloat16* __restrict__ w7l)
{
    int i = blockIdx.x * blockDim.x + threadIdx.x;
    const float* src;
    __nv_bfloat16 *dh, *dl;
    int off;
    if (i < 8 * WSEG) {
        int seg = i / WSEG;
        off = i - seg * WSEG;
        switch (seg) {
            case 0: src = wq_down;  dh = wdh;          dl = wdl;          break;
            case 1: src = wk_rope;  dh = wdh + WSEG;   dl = wdl + WSEG;   break;
            case 2: src = wkv_down; dh = wdh + 2*WSEG; dl = wdl + 2*WSEG; break;
            case 3: src = wq_rope;  dh = wuh;          dl = wul;          break;
            case 4: src = wq_up;    dh = wuh + WSEG;   dl = wul + WSEG;   break;
            case 5: src = wk_up;    dh = wuh + 2*WSEG; dl = wul + 2*WSEG; break;
            case 6: src = wk_up;    dh = wuh + 3*WSEG; dl = wul + 3*WSEG; break;
            default: src = wv_up;   dh = wuh + 4*WSEG; dl = wul + 4*WSEG; break;
        }
    } else {
        off = i - 8 * WSEG;
        if (off >= CE * CE) return;
        src = wo; dh = w7h; dl = w7l;
    }
    float v = src[off];
    __nv_bfloat16 h = __float2bfloat16(v);
    dh[off] = h;
    dl[off] = __float2bfloat16(v - __bfloat162float(h));
}

// ============= tensor-core split-bf16 GEMM NT, cp.async 3-stage ============
// C[M,N] = A[M,K] * B[N,K]^T. CTA tile 128x128, 256 threads, 2 CTAs/SM.
// MODE 0: fp32; 1: split hi/lo; MODE 7: mega up-projection
#define GEMM_SMEM (3*32768)
#define MS_AH 0
#define MS_AL 8192
#define MS_BH 16384
#define MS_BL 24576
#define MS_STAGE 32768

__device__ __forceinline__ uint32_t msw(int row, int c) {
    return (uint32_t)(row * 64 + ((c ^ ((row >> 1) & 3)) << 4));
}

template<int MODE>
__global__ __launch_bounds__(256, 2) void gemm_ms(
    const __nv_bfloat16* __restrict__ Ah, const __nv_bfloat16* __restrict__ Al, int lda,
    const __nv_bfloat16* __restrict__ Bh, const __nv_bfloat16* __restrict__ Bl, int ldb,
    float* __restrict__ Cf, __nv_bfloat16* __restrict__ Ch, __nv_bfloat16* __restrict__ Cl,
    __nv_bfloat16* __restrict__ Dh, __nv_bfloat16* __restrict__ Dl,
    __nv_bfloat16* __restrict__ Eh, __nv_bfloat16* __restrict__ El,
    const float* __restrict__ Rt,
    int ldc, int K)
{
    extern __shared__ char smem[];
    const int tid = threadIdx.x, wid = tid >> 5, lid = tid & 31;
    const int m0 = blockIdx.y * 128, n0 = blockIdx.x * 128;
    uint32_t sb = smem_to_u32(smem);

    if (MODE == 7) {
        int nb = blockIdx.x;
        int aoff = (nb < 16) ? 0 : ((nb < 24) ? CR : 2 * CR);
        Ah += aoff; Al += aoff;
    }

    const int mw = wid & 3, nw = wid >> 2;
    const int a_tr = (lid & 7) + ((lid >> 3) & 1) * 8;
    const int a_kq = lid >> 4;
    const int b_tr = (lid & 7) + (lid >> 4) * 8;
    const int b_kq = (lid >> 3) & 1;

    float acc[2][8][4];
#pragma unroll
    for (int i = 0; i < 2; i++)
#pragma unroll
        for (int j = 0; j < 8; j++)
#pragma unroll
            for (int q = 0; q < 4; q++) acc[i][j][q] = 0.f;

    auto issue = [&](int stg, int k0) {
        uint32_t base = sb + stg * MS_STAGE;
#pragma unroll
        for (int it = 0; it < 2; it++) {
            int ch = it * 256 + tid;
            int row = ch >> 2, c = ch & 3;
            uint32_t so = msw(row, c);
            size_t ga = (size_t)(m0 + row) * lda + k0 + c * 8;
            size_t gb = (size_t)(n0 + row) * ldb + k0 + c * 8;
            CP_ASYNC16(base + MS_AH + so, Ah + ga);
            CP_ASYNC16(base + MS_AL + so, Al + ga);
            CP_ASYNC16(base + MS_BH + so, Bh + gb);
            CP_ASYNC16(base + MS_BL + so, Bl + gb);
        }
        CP_COMMIT();
    };

    const int niter = K >> 5;
    issue(0, 0);
    if (niter > 1) issue(1, 32);

    for (int it = 0; it < niter; it++) {
        if (it + 1 < niter) { CP_WAIT(1); } else { CP_WAIT(0); }
        __syncthreads();
        if (it + 2 < niter) issue((it + 2) % 3, (it + 2) * 32);

        uint32_t base = sb + (it % 3) * MS_STAGE;
#pragma unroll
        for (int ks = 0; ks < 2; ks++) {
            uint32_t ah[2][4], al[2][4], bh[8][2], bl[8][2];
#pragma unroll
            for (int ma = 0; ma < 2; ma++) {
                int row = mw * 32 + ma * 16 + a_tr;
                int c = ks * 2 + a_kq;
                LDSM_X4(ah[ma][0], ah[ma][1], ah[ma][2], ah[ma][3], base + MS_AH + msw(row, c));
                LDSM_X4(al[ma][0], al[ma][1], al[ma][2], al[ma][3], base + MS_AL + msw(row, c));
            }
#pragma unroll
            for (int nb = 0; nb < 4; nb++) {
                int row = nw * 64 + nb * 16 + b_tr;
                int c = ks * 2 + b_kq;
                LDSM_X4(bh[nb*2][0], bh[nb*2][1], bh[nb*2+1][0], bh[nb*2+1][1], base + MS_BH + msw(row, c));
                LDSM_X4(bl[nb*2][0], bl[nb*2][1], bl[nb*2+1][0], bl[nb*2+1][1], base + MS_BL + msw(row, c));
            }
#pragma unroll
            for (int ma = 0; ma < 2; ma++)
#pragma unroll
                for (int na = 0; na < 8; na++) {
                    MMA16816(acc[ma][na], ah[ma], bh[na]);
                    MMA16816(acc[ma][na], ah[ma], bl[na]);
                    MMA16816(acc[ma][na], al[ma], bh[na]);
                }
        }
    }

    // ----------------------- fused epilogues -------------------------------
    const int g = lid >> 2, t4 = lid & 3;
    const int ncol = n0 + nw * 64;   // warp-uniform column base

    if (MODE == 0) {
#pragma unroll
        for (int ma = 0; ma < 2; ma++) {
            int row0 = m0 + mw * 32 + ma * 16 + g;
#pragma unroll
            for (int na = 0; na < 8; na++) {
                int col = ncol + na * 8 + t4 * 2;
                *(float2*)(Cf + (size_t)row0 * ldc + col) =
                    make_float2(acc[ma][na][0], acc[ma][na][1]);
                *(float2*)(Cf + (size_t)(row0 + 8) * ldc + col) =
                    make_float2(acc[ma][na][2], acc[ma][na][3]);
            }
        }
    } else if (MODE == 1) {
#pragma unroll
        for (int ma = 0; ma < 2; ma++) {
            int row0 = m0 + mw * 32 + ma * 16 + g;
#pragma unroll
            for (int na = 0; na < 8; na++) {
                int col = ncol + na * 8 + t4 * 2;
                uint32_t h0, l0;
                split2(acc[ma][na][0], acc[ma][na][1], h0, l0);
                *(uint32_t*)(Ch + (size_t)row0 * ldc + col) = h0;
                *(uint32_t*)(Cl + (size_t)row0 * ldc + col) = l0;
                split2(acc[ma][na][2], acc[ma][na][3], h0, l0);
                *(uint32_t*)(Ch + (size_t)(row0 + 8) * ldc + col) = h0;
                *(uint32_t*)(Cl + (size_t)(row0 + 8) * ldc + col) = l0;
            }
        }
    } else {
        // MODE 7 dispatch (warp-uniform by ncol)
        const bool is_rope = (ncol < CE) || (ncol >= 2*CE && ncol < 3*CE);
        const bool is_v    = (ncol >= 4*CE);
        __nv_bfloat16 *Oh, *Ol;
        int hq;
        if (ncol < CE)           { Oh = Ch; Ol = Cl; hq = ncol >> 6; }            // rope->Q
        else if (ncol < 2*CE)    { Oh = Ch; Ol = Cl; hq = (ncol - CE) >> 6; }     // nope->Q
        else if (ncol < 3*CE)    { Oh = Dh; Ol = Dl; hq = (ncol - 2*CE) >> 6; }   // rope->K
        else if (ncol < 4*CE)    { Oh = Dh; Ol = Dl; hq = (ncol - 3*CE) >> 6; }   // nope->K
        else                     { Oh = Eh; Ol = El; hq = (ncol - 4*CE) >> 6; }   // vt->V

        if (is_rope) {
#pragma unroll
            for (int ma = 0; ma < 2; ma++) {
                int r0 = m0 + mw * 32 + ma * 16 + g;
                int b = r0 >> 11;
                size_t bb = (size_t)((b << 4) + hq) * CS * CDQK;
#pragma unroll
                for (int rh = 0; rh < 2; rh++) {
                    int s = (r0 + rh * 8) & (CS - 1);
                    size_t base = bb + (size_t)s * CDQK;
                    const float* rt = Rt + s * 64;
#pragma unroll
                    for (int na = 0; na < 4; na++) {
                        int e = rh * 2;
                        int i0 = na * 8 + t4 * 2;
                        float x1a = acc[ma][na][e],   x1b = acc[ma][na][e+1];
                        float x2a = acc[ma][na+4][e], x2b = acc[ma][na+4][e+1];
                        float4 cs4 = *(const float4*)(rt + i0 * 2);  // cos0,sin0,cos1,sin1
                        float o1a = x1a*cs4.x - x2a*cs4.y, o1b = x1b*cs4.z - x2b*cs4.w;
                        float o2a = x2a*cs4.x + x1a*cs4.y, o2b = x2b*cs4.z + x1b*cs4.w;
                        uint32_t h0, l0;
                        split2(o1a, o1b, h0, l0);
                        *(uint32_t*)(Oh + base + i0) = h0;
                        *(uint32_t*)(Ol + base + i0) = l0;
                        split2(o2a, o2b, h0, l0);
                        *(uint32_t*)(Oh + base + 32 + i0) = h0;
                        *(uint32_t*)(Ol + base + 32 + i0) = l0;
                    }
                }
            }
        } else if (!is_v) {
            // nope -> [b,h,s,64:128]
#pragma unroll
            for (int ma = 0; ma < 2; ma++) {
                int r0 = m0 + mw * 32 + ma * 16 + g;
                int b = r0 >> 11;
                size_t bb = (size_t)((b << 4) + hq) * CS * CDQK;
#pragma unroll
                for (int rh = 0; rh < 2; rh++) {
                    int s = (r0 + rh * 8) & (CS - 1);
                    size_t base = bb + (size_t)s * CDQK + 64;
#pragma unroll
                    for (int na = 0; na < 8; na++) {
                        int d0 = na * 8 + t4 * 2;
                        uint32_t h0, l0;
                        split2(acc[ma][na][rh*2], acc[ma][na][rh*2+1], h0, l0);
                        *(uint32_t*)(Oh + base + d0) = h0;
                        *(uint32_t*)(Ol + base + d0) = l0;
                    }
                }
            }
        } else {
            // vt -> V [b,h,d,s]
#pragma unroll
            for (int ma = 0; ma < 2; ma++) {
                int r0 = m0 + mw * 32 + ma * 16 + g;
                int b = r0 >> 11;
                size_t bb = (size_t)((b << 4) + hq) * CHD;
#pragma unroll
                for (int rh = 0; rh < 2; rh++) {
                    int s = (r0 + rh * 8) & (CS - 1);
#pragma unroll
                    for (int na = 0; na < 8; na++) {
#pragma unroll
                        for (int j = 0; j < 2; j++) {
                            int d = na * 8 + t4 * 2 + j;
                            float v = acc[ma][na][rh*2 + j];
                            __nv_bfloat16 hv = __float2bfloat16(v);
                            size_t o = (bb + d) * CS + s;
                            Oh[o] = hv;
                            Ol[o] = __float2bfloat16(v - __bfloat162float(hv));
                        }
                    }
                }
            }
        }
    }
}

// =================== causal flash attention, cp.async K/V 3-stage ==========
// BQ=128, 256 threads; K/V tiles 64 wide, triple-buffered, 1 sync/tile.
// Q fragments hoisted into registers (loop-invariant; 1 CTA/SM anyway).
#define FQH 0
#define FQL 32768
#define FKV0 65536
#define FKV_STAGE 49152
#define FO_KH 0
#define FO_KL 16384
#define FO_VH 32768
#define FO_VL 40960
#define FLASH_SMEM (65536 + 3*49152)   // 212992
#define NQB (CS/128)

__device__ __forceinline__ uint32_t fsw(int row, int chunk) {
    return (uint32_t)(row * 256 + ((chunk >> 3) << 7) + (((chunk & 7) ^ (row & 7)) << 4));
}
__device__ __forceinline__ uint32_t vsw(int row, int chunk) {
    return (uint32_t)(row * 128 + ((chunk ^ (row & 7)) << 4));
}

__global__ __launch_bounds__(256) void flash_attn_mma(
    const __nv_bfloat16* __restrict__ Qh, const __nv_bfloat16* __restrict__ Ql,
    const __nv_bfloat16* __restrict__ Kh, const __nv_bfloat16* __restrict__ Kl,
    const __nv_bfloat16* __restrict__ Vh, const __nv_bfloat16* __restrict__ Vl,
    __nv_bfloat16* __restrict__ Yh, __nv_bfloat16* __restrict__ Yl)
{
    extern __shared__ char smem[];
    uint32_t sb = smem_to_u32(smem);
    const int tid = threadIdx.x, wid = tid >> 5, lid = tid & 31;
    const int bh = blockIdx.x;
    const int qb = NQB - 1 - blockIdx.y;   // LPT: longest first
    const int q0 = qb * 128;
    const int g = lid >> 2, t = lid & 3;

    const __nv_bfloat16* Qhg = Qh + (size_t)bh * CS * CDQK;
    const __nv_bfloat16* Qlg = Ql + (size_t)bh * CS * CDQK;
    const __nv_bfloat16* Khg = Kh + (size_t)bh * CS * CDQK;
    const __nv_bfloat16* Klg = Kl + (size_t)bh * CS * CDQK;
    const __nv_bfloat16* Vhg = Vh + (size_t)bh * CHD * CS;
    const __nv_bfloat16* Vlg = Vl + (size_t)bh * CHD * CS;

    auto issue_kv = [&](int stg, int k0) {
        uint32_t base = sb + FKV0 + stg * FKV_STAGE;
#pragma unroll
        for (int it = 0; it < 4; it++) {
            int i = it * 256 + tid;
            int row = i >> 4, ch = i & 15;
            size_t off = (size_t)(k0 + row) * CDQK + ch * 8;
            uint32_t so = fsw(row, ch);
            CP_ASYNC16(base + FO_KH + so, Khg + off);
            CP_ASYNC16(base + FO_KL + so, Klg + off);
        }
#pragma unroll
        for (int it = 0; it < 2; it++) {
            int i = it * 256 + tid;
            int row = i >> 3, ch = i & 7;
            size_t off = (size_t)row * CS + k0 + ch * 8;
            uint32_t so = vsw(row, ch);
            CP_ASYNC16(base + FO_VH + so, Vhg + off);
            CP_ASYNC16(base + FO_VL + so, Vlg + off);
        }
        CP_COMMIT();
    };

    const int nkb = 2 * qb + 2;
    issue_kv(0, 0);
    if (nkb > 1) issue_kv(1, 64);

    // Q tile into smem, then hoist this warp's fragments into registers
#pragma unroll
    for (int it = 0; it < 8; it++) {
        int i = it * 256 + tid;
        int row = i >> 4, ch = i & 15;
        size_t off = (size_t)(q0 + row) * CDQK + ch * 8;
        *(uint4*)(smem + FQH + fsw(row, ch)) = *(const uint4*)(Qhg + off);
        *(uint4*)(smem + FQL + fsw(row, ch)) = *(const uint4*)(Qlg + off);
    }
    __syncthreads();

    const int a_tr = (lid & 7) + ((lid >> 3) & 1) * 8;
    const int a_kq = lid >> 4;
    const int b_tr = (lid & 7) + (lid >> 4) * 8;
    const int b_kq = (lid >> 3) & 1;

    uint32_t qhf[8][4], qlf[8][4];
#pragma unroll
    for (int ks = 0; ks < 8; ks++) {
        LDSM_X4(qhf[ks][0], qhf[ks][1], qhf[ks][2], qhf[ks][3],
                sb + FQH + fsw(wid * 16 + a_tr, ks * 2 + a_kq));
        LDSM_X4(qlf[ks][0], qlf[ks][1], qlf[ks][2], qlf[ks][3],
                sb + FQL + fsw(wid * 16 + a_tr, ks * 2 + a_kq));
    }

    float O[8][4];
#pragma unroll
    for (int na = 0; na < 8; na++)
#pragma unroll
        for (int e = 0; e < 4; e++) O[na][e] = 0.f;
    float mI0 = -1e30f, mI1 = -1e30f, lI0 = 0.f, lI1 = 0.f;
    const float scale = 0.08838834764831845f;

    const int qw_last = q0 + wid * 16 + 15;

    for (int kb = 0; kb < nkb; kb++) {
        const int k0 = kb * 64;
        if (kb + 1 < nkb) { CP_WAIT(1); } else { CP_WAIT(0); }
        __syncthreads();
        if (kb + 2 < nkb) issue_kv((kb + 2) % 3, (kb + 2) * 64);

        if (k0 <= qw_last) {
            uint32_t kvb = sb + FKV0 + (kb % 3) * FKV_STAGE;

            float sc[8][4];
#pragma unroll
            for (int na = 0; na < 8; na++)
#pragma unroll
                for (int e = 0; e < 4; e++) sc[na][e] = 0.f;

#pragma unroll
            for (int ks = 0; ks < 8; ks++) {
                uint32_t khf[8][2], klf[8][2];
#pragma unroll
                for (int nb = 0; nb < 4; nb++) {
                    uint32_t so = fsw(nb * 16 + b_tr, ks * 2 + b_kq);
                    LDSM_X4(khf[nb*2][0], khf[nb*2][1], khf[nb*2+1][0], khf[nb*2+1][1], kvb + FO_KH + so);
                    LDSM_X4(klf[nb*2][0], klf[nb*2][1], klf[nb*2+1][0], klf[nb*2+1][1], kvb + FO_KL + so);
                }
#pragma unroll
                for (int na = 0; na < 8; na++) {
                    MMA16816(sc[na], qhf[ks], khf[na]);
                    MMA16816(sc[na], qhf[ks], klf[na]);
                    MMA16816(sc[na], qlf[ks], khf[na]);
                }
            }

            if (k0 + 63 > qw_last - 15) {
#pragma unroll
                for (int na = 0; na < 8; na++)
#pragma unroll
                    for (int e = 0; e < 4; e++) {
                        int qr = q0 + wid * 16 + g + ((e >> 1) << 3);
                        int kc = k0 + na * 8 + 2 * t + (e & 1);
                        sc[na][e] = (kc > qr) ? -1e30f : sc[na][e] * scale;
                    }
            } else {
#pragma unroll
                for (int na = 0; na < 8; na++)
#pragma unroll
                    for (int e = 0; e < 4; e++) sc[na][e] *= scale;
            }

            float mx0 = -1e30f, mx1 = -1e30f;
#pragma unroll
            for (int na = 0; na < 8; na++) {
                mx0 = fmaxf(mx0, fmaxf(sc[na][0], sc[na][1]));
                mx1 = fmaxf(mx1, fmaxf(sc[na][2], sc[na][3]));
            }
            mx0 = fmaxf(mx0, __shfl_xor_sync(0xffffffffu, mx0, 1));
            mx0 = fmaxf(mx0, __shfl_xor_sync(0xffffffffu, mx0, 2));
            mx1 = fmaxf(mx1, __shfl_xor_sync(0xffffffffu, mx1, 1));
            mx1 = fmaxf(mx1, __shfl_xor_sync(0xffffffffu, mx1, 2));

            float mn0 = fmaxf(mI0, mx0), mn1 = fmaxf(mI1, mx1);
            float al0 = __expf(mI0 - mn0), al1 = __expf(mI1 - mn1);
            mI0 = mn0; mI1 = mn1;

            float rs0 = 0.f, rs1 = 0.f;
#pragma unroll
            for (int na = 0; na < 8; na++) {
                sc[na][0] = __expf(sc[na][0] - mn0); rs0 += sc[na][0];
                sc[na][1] = __expf(sc[na][1] - mn0); rs0 += sc[na][1];
                sc[na][2] = __expf(sc[na][2] - mn1); rs1 += sc[na][2];
                sc[na][3] = __expf(sc[na][3] - mn1); rs1 += sc[na][3];
            }
            rs0 += __shfl_xor_sync(0xffffffffu, rs0, 1);
            rs0 += __shfl_xor_sync(0xffffffffu, rs0, 2);
            rs1 += __shfl_xor_sync(0xffffffffu, rs1, 1);
            rs1 += __shfl_xor_sync(0xffffffffu, rs1, 2);
            lI0 = lI0 * al0 + rs0;
            lI1 = lI1 * al1 + rs1;

#pragma unroll
            for (int na = 0; na < 8; na++) {
                O[na][0] *= al0; O[na][1] *= al0;
                O[na][2] *= al1; O[na][3] *= al1;
            }

#pragma unroll
            for (int kk = 0; kk < 4; kk++) {
                uint32_t pah[4], pal[4];
                split2(sc[2*kk][0],   sc[2*kk][1],   pah[0], pal[0]);
                split2(sc[2*kk][2],   sc[2*kk][3],   pah[1], pal[1]);
                split2(sc[2*kk+1][0], sc[2*kk+1][1], pah[2], pal[2]);
                split2(sc[2*kk+1][2], sc[2*kk+1][3], pah[3], pal[3]);
                uint32_t vhf[8][2], vlf[8][2];
#pragma unroll
                for (int nb = 0; nb < 4; nb++) {
                    uint32_t so = vsw(nb * 16 + b_tr, kk * 2 + b_kq);
                    LDSM_X4(vhf[nb*2][0], vhf[nb*2][1], vhf[nb*2+1][0], vhf[nb*2+1][1], kvb + FO_VH + so);
                    LDSM_X4(vlf[nb*2][0], vlf[nb*2][1], vlf[nb*2+1][0], vlf[nb*2+1][1], kvb + FO_VL + so);
                }
#pragma unroll
                for (int na = 0; na < 8; na++) {
                    MMA16816(O[na], pah, vhf[na]);
                    MMA16816(O[na], pal, vhf[na]);
                    MMA16816(O[na], pah, vlf[na]);
                }
            }
        }
    }

    // ---- epilogue -----------------------------------------------------
    const int b = bh >> 4, h = bh & 15;
    const float inv0 = 1.f / lI0, inv1 = 1.f / lI1;
    const int qr0 = q0 + wid * 16 + g;
#pragma unroll
    for (int na = 0; na < 8; na++) {
        int col = h * CHD + na * 8 + 2 * t;
        uint32_t h0, l0;
        split2(O[na][0] * inv0, O[na][1] * inv0, h0, l0);
        *(uint32_t*)(Yh + (size_t)(b*CS + qr0) * CE + col) = h0;
        *(uint32_t*)(Yl + (size_t)(b*CS + qr0) * CE + col) = l0;
        split2(O[na][2] * inv1, O[na][3] * inv1, h0, l0);
        *(uint32_t*)(Yh + (size_t)(b*CS + qr0 + 8) * CE + col) = h0;
        *(uint32_t*)(Yl + (size_t)(b*CS + qr0 + 8) * CE + col) = l0;
    }
}

// ============================== launcher ===================================
extern "C" void kernel_launch(void* const* d_in, const int* in_sizes, int n_in,
                              void* d_out, int out_size)
{
    const float* x        = (const float*)d_in[0];
    const float* wq_down  = (const float*)d_in[1];
    const float* wk_rope  = (const float*)d_in[2];
    const float* wkv_down = (const float*)d_in[3];
    const float* wq_rope  = (const float*)d_in[4];
    const float* wq_up    = (const float*)d_in[5];
    const float* wk_up    = (const float*)d_in[6];
    const float* wv_up    = (const float*)d_in[7];
    const float* wo       = (const float*)d_in[8];
    float* out = (float*)d_out;

    __nv_bfloat16 *xh,*xl,*lath,*latl,*Yh,*Yl,*wdh,*wdl,*wuh,*wul,*w7h,*w7l;
    __nv_bfloat16 *Qbh,*Qbl,*Kbh,*Kbl,*Vbh,*Vbl;
    float* rtab;
    cudaGetSymbolAddress((void**)&xh,   g_xh);   cudaGetSymbolAddress((void**)&xl,   g_xl);
    cudaGetSymbolAddress((void**)&lath, g_lath); cudaGetSymbolAddress((void**)&latl, g_latl);
    cudaGetSymbolAddress((void**)&Yh,   g_Yh);   cudaGetSymbolAddress((void**)&Yl,   g_Yl);
    cudaGetSymbolAddress((void**)&wdh,  g_wdh);  cudaGetSymbolAddress((void**)&wdl,  g_wdl);
    cudaGetSymbolAddress((void**)&wuh,  g_wuh);  cudaGetSymbolAddress((void**)&wul,  g_wul);
    cudaGetSymbolAddress((void**)&w7h,  g_w7h);  cudaGetSymbolAddress((void**)&w7l,  g_w7l);
    cudaGetSymbolAddress((void**)&Qbh,  g_Qbh);  cudaGetSymbolAddress((void**)&Qbl,  g_Qbl);
    cudaGetSymbolAddress((void**)&Kbh,  g_Kbh);  cudaGetSymbolAddress((void**)&Kbl,  g_Kbl);
    cudaGetSymbolAddress((void**)&Vbh,  g_Vbh);  cudaGetSymbolAddress((void**)&Vbl,  g_Vbl);
    cudaGetSymbolAddress((void**)&rtab, g_ropetab);

    cudaFuncSetAttribute(gemm_ms<0>, cudaFuncAttributeMaxDynamicSharedMemorySize, GEMM_SMEM);
    cudaFuncSetAttribute(gemm_ms<1>, cudaFuncAttributeMaxDynamicSharedMemorySize, GEMM_SMEM);
    cudaFuncSetAttribute(gemm_ms<7>, cudaFuncAttributeMaxDynamicSharedMemorySize, GEMM_SMEM);
    cudaFuncSetAttribute(flash_attn_mma, cudaFuncAttributeMaxDynamicSharedMemorySize, FLASH_SMEM);

    // prep (3 launches)
    build_rope_tab<<<(CS*32) / 256, 256>>>(rtab);
    cvt_split<<<(MTOK*CE + 255) / 256, 256>>>(x, xh, xl, MTOK*CE);
    cvt_weights<<<(8*WSEG + CE*CE + 255) / 256, 256>>>(
        wq_down, wk_rope, wkv_down, wq_rope, wq_up, wk_up, wv_up, wo,
        wdh, wdl, wuh, wul, w7h, w7l);

    dim3 blk(256);
    // fused down projection: lat[4096,768] = x @ [wq_down|wk_rope|wkv_down]^T
    gemm_ms<1><<<dim3(NLAT/128, MTOK/128), blk, GEMM_SMEM>>>(
        xh, xl, CE, wdh, wdl, CE, nullptr, lath, latl, nullptr, nullptr,
        nullptr, nullptr, nullptr, NLAT, CE);

    // mega up-projection: all 5 up-GEMMs in one launch -> Q, K, V
    gemm_ms<7><<<dim3(40, MTOK/128), blk, GEMM_SMEM>>>(
        lath, latl, NLAT, wuh, wul, CR, nullptr, Qbh, Qbl, Kbh, Kbl,
        Vbh, Vbl, rtab, 0, CR);

    // causal flash attention (LPT-ordered grid) -> Yh/Yl
    flash_attn_mma<<<dim3(CB*CH, NQB), 256, FLASH_SMEM>>>(
        Qbh, Qbl, Kbh, Kbl, Vbh, Vbl, Yh, Yl);

    // output projection: Y @ wo^T -> out (fp32)
    gemm_ms<0><<<dim3(CE/128, MTOK/128), blk, GEMM_SMEM>>>(
        Yh, Yl, CE, w7h, w7l, CE, out, nullptr, nullptr, nullptr, nullptr,
        nullptr, nullptr, nullptr, CE, CE);
}

// round 16
// speedup vs baseline: 3.8142x; 1.0292x over previous
#include <cuda_runtime.h>
#include <cuda_bf16.h>
#include <cstdint>
#include <math.h>

#define CB   2
#define CS   2048
#define CE   1024
#define CR   256
#define CH   16
#define CHD  64
#define CDQK 128
#define MTOK (CB*CS)   // 4096
#define NLAT 768
#define WSEG (CR*CE)   // 262144

// ---------------- scratch -------------------------------------------------
__device__ __nv_bfloat16 g_xh [MTOK*CE],  g_xl [MTOK*CE];
__device__ __nv_bfloat16 g_lath[MTOK*NLAT], g_latl[MTOK*NLAT];
__device__ __nv_bfloat16 g_Yh [MTOK*CE],  g_Yl [MTOK*CE];
__device__ __nv_bfloat16 g_wdh[NLAT*CE],  g_wdl[NLAT*CE];      // wq_down|wk_rope|wkv_down
__device__ __nv_bfloat16 g_wuh[5*WSEG],   g_wul[5*WSEG];       // wq_rope|wq_up|wk_up|wk_up|wv_up
__device__ __nv_bfloat16 g_w7h[CE*CE],    g_w7l[CE*CE];        // wo
__device__ float g_ropetab[CS*64];

__device__ __nv_bfloat16 g_Qbh[CB*CH*CS*CDQK], g_Qbl[CB*CH*CS*CDQK];
__device__ __nv_bfloat16 g_Kbh[CB*CH*CS*CDQK], g_Kbl[CB*CH*CS*CDQK];
__device__ __nv_bfloat16 g_Vbh[CB*CH*CHD*CS],  g_Vbl[CB*CH*CHD*CS];

// ===================== generic helpers =====================================
__device__ __forceinline__ uint32_t smem_to_u32(const void* p) {
    uint32_t a;
    asm("{ .reg .u64 t; cvta.to.shared.u64 t, %1; cvt.u32.u64 %0, t; }" : "=r"(a) : "l"(p));
    return a;
}

#define LDSM_X4(r0,r1,r2,r3, addr) \
    asm volatile("ldmatrix.sync.aligned.m8n8.x4.shared.b16 {%0,%1,%2,%3}, [%4];" \
        : "=r"(r0), "=r"(r1), "=r"(r2), "=r"(r3) : "r"(addr))

#define MMA16816(c, a, b) \
    asm volatile("mma.sync.aligned.m16n8k16.row.col.f32.bf16.bf16.f32 " \
        "{%0,%1,%2,%3}, {%4,%5,%6,%7}, {%8,%9}, {%0,%1,%2,%3};" \
        : "+f"((c)[0]), "+f"((c)[1]), "+f"((c)[2]), "+f"((c)[3]) \
        : "r"((a)[0]), "r"((a)[1]), "r"((a)[2]), "r"((a)[3]), "r"((b)[0]), "r"((b)[1]))

#define CP_ASYNC16(dst, src) \
    asm volatile("cp.async.cg.shared.global [%0], [%1], 16;" :: "r"(dst), "l"(src))
#define CP_COMMIT() asm volatile("cp.async.commit_group;" ::: "memory")
#define CP_WAIT(n)  asm volatile("cp.async.wait_group %0;" :: "n"(n) : "memory")

__device__ __forceinline__ void split2(float a, float b, uint32_t& hi, uint32_t& lo) {
    __nv_bfloat16 ha = __float2bfloat16(a), hb = __float2bfloat16(b);
    float ra = a - __bfloat162float(ha);
    float rb = b - __bfloat162float(hb);
    __nv_bfloat162 hh; hh.x = ha; hh.y = hb;
    hi = *(uint32_t*)&hh;
    __nv_bfloat162 ll = __floats2bfloat162_rn(ra, rb);
    lo = *(uint32_t*)&ll;
}

#define ROPE_L 0.41524101186109f

// ===================== small prep kernels ==================================
__global__ void cvt_split(const float* __restrict__ src,
                          __nv_bfloat16* __restrict__ hi, __nv_bfloat16* __restrict__ lo, int n)
{
    int i = blockIdx.x * blockDim.x + threadIdx.x;
    if (i < n) {
        float v = src[i];
        __nv_bfloat16 h = __float2bfloat16(v);
        hi[i] = h;
        lo[i] = __float2bfloat16(v - __bfloat162float(h));
    }
}

__global__ void build_rope_tab(float* __restrict__ tab)
{
    int idx = blockIdx.x * blockDim.x + threadIdx.x;   // CS*32
    int s = idx >> 5, i = idx & 31;
    float ang = (float)s * exp2f(-(float)i * ROPE_L);
    float sn, cs;
    sincosf(ang, &sn, &cs);
    tab[(idx << 1)]     = cs;
    tab[(idx << 1) + 1] = sn;
}

__global__ void cvt_weights(
    const float* __restrict__ wq_down, const float* __restrict__ wk_rope,
    const float* __restrict__ wkv_down, const float* __restrict__ wq_rope,
    const float* __restrict__ wq_up,   const float* __restrict__ wk_up,
    const float* __restrict__ wv_up,   const float* __restrict__ wo,
    __nv_bfloat16* __restrict__ wdh,  __nv_bfloat16* __restrict__ wdl,
    __nv_bfloat16* __restrict__ wuh,  __nv_bfloat16* __restrict__ wul,
    __nv_bfloat16* __restrict__ w7h,  __nv_bfloat16* __restrict__ w7l)
{
    int i = blockIdx.x * blockDim.x + threadIdx.x;
    const float* src;
    __nv_bfloat16 *dh, *dl;
    int off;
    if (i < 8 * WSEG) {
        int seg = i / WSEG;
        off = i - seg * WSEG;
        switch (seg) {
            case 0: src = wq_down;  dh = wdh;          dl = wdl;          break;
            case 1: src = wk_rope;  dh = wdh + WSEG;   dl = wdl + WSEG;   break;
            case 2: src = wkv_down; dh = wdh + 2*WSEG; dl = wdl + 2*WSEG; break;
            case 3: src = wq_rope;  dh = wuh;          dl = wul;          break;
            case 4: src = wq_up;    dh = wuh + WSEG;   dl = wul + WSEG;   break;
            case 5: src = wk_up;    dh = wuh + 2*WSEG; dl = wul + 2*WSEG; break;
            case 6: src = wk_up;    dh = wuh + 3*WSEG; dl = wul + 3*WSEG; break;
            default: src = wv_up;   dh = wuh + 4*WSEG; dl = wul + 4*WSEG; break;
        }
    } else {
        off = i - 8 * WSEG;
        if (off >= CE * CE) return;
        src = wo; dh = w7h; dl = w7l;
    }
    float v = src[off];
    __nv_bfloat16 h = __float2bfloat16(v);
    dh[off] = h;
    dl[off] = __float2bfloat16(v - __bfloat162float(h));
}

__device__ __forceinline__ uint32_t msw(int row, int c) {
    return (uint32_t)(row * 64 + ((c ^ ((row >> 1) & 3)) << 4));
}

// ======= GEMM-64: 64x128 CTA tile, 128 threads, 3 CTAs/SM (K=1024 GEMMs) ===
// Warp tile 32x64 (identical fragment code). MODE 0: fp32 store; 1: split.
#define G64_AH 0
#define G64_AL 4096
#define G64_BH 8192
#define G64_BL 16384
#define G64_STAGE 24576
#define G64_SMEM (3*24576)

template<int MODE>
__global__ __launch_bounds__(128, 3) void gemm64(
    const __nv_bfloat16* __restrict__ Ah, const __nv_bfloat16* __restrict__ Al, int lda,
    const __nv_bfloat16* __restrict__ Bh, const __nv_bfloat16* __restrict__ Bl, int ldb,
    float* __restrict__ Cf, __nv_bfloat16* __restrict__ Ch, __nv_bfloat16* __restrict__ Cl,
    int ldc, int K)
{
    extern __shared__ char smem[];
    const int tid = threadIdx.x, wid = tid >> 5, lid = tid & 31;
    const int m0 = blockIdx.y * 64, n0 = blockIdx.x * 128;
    uint32_t sb = smem_to_u32(smem);

    const int mw = wid & 1, nw = wid >> 1;   // 2 M-warps x 2 N-warps
    const int a_tr = (lid & 7) + ((lid >> 3) & 1) * 8;
    const int a_kq = lid >> 4;
    const int b_tr = (lid & 7) + (lid >> 4) * 8;
    const int b_kq = (lid >> 3) & 1;

    float acc[2][8][4];
#pragma unroll
    for (int i = 0; i < 2; i++)
#pragma unroll
        for (int j = 0; j < 8; j++)
#pragma unroll
            for (int q = 0; q < 4; q++) acc[i][j][q] = 0.f;

    auto issue = [&](int stg, int k0) {
        uint32_t base = sb + stg * G64_STAGE;
#pragma unroll
        for (int it = 0; it < 2; it++) {
            int ch = it * 128 + tid;
            int row = ch >> 2, c = ch & 3;
            uint32_t so = msw(row, c);
            size_t ga = (size_t)(m0 + row) * lda + k0 + c * 8;
            CP_ASYNC16(base + G64_AH + so, Ah + ga);
            CP_ASYNC16(base + G64_AL + so, Al + ga);
        }
#pragma unroll
        for (int it = 0; it < 4; it++) {
            int ch = it * 128 + tid;
            int row = ch >> 2, c = ch & 3;
            uint32_t so = msw(row, c);
            size_t gb = (size_t)(n0 + row) * ldb + k0 + c * 8;
            CP_ASYNC16(base + G64_BH + so, Bh + gb);
            CP_ASYNC16(base + G64_BL + so, Bl + gb);
        }
        CP_COMMIT();
    };

    const int niter = K >> 5;
    issue(0, 0);
    if (niter > 1) issue(1, 32);

    for (int it = 0; it < niter; it++) {
        if (it + 1 < niter) { CP_WAIT(1); } else { CP_WAIT(0); }
        __syncthreads();
        if (it + 2 < niter) issue((it + 2) % 3, (it + 2) * 32);

        uint32_t base = sb + (it % 3) * G64_STAGE;
#pragma unroll
        for (int ks = 0; ks < 2; ks++) {
            uint32_t ah[2][4], al[2][4], bh[8][2], bl[8][2];
#pragma unroll
            for (int ma = 0; ma < 2; ma++) {
                int row = mw * 32 + ma * 16 + a_tr;
                int c = ks * 2 + a_kq;
                LDSM_X4(ah[ma][0], ah[ma][1], ah[ma][2], ah[ma][3], base + G64_AH + msw(row, c));
                LDSM_X4(al[ma][0], al[ma][1], al[ma][2], al[ma][3], base + G64_AL + msw(row, c));
            }
#pragma unroll
            for (int nb = 0; nb < 4; nb++) {
                int row = nw * 64 + nb * 16 + b_tr;
                int c = ks * 2 + b_kq;
                LDSM_X4(bh[nb*2][0], bh[nb*2][1], bh[nb*2+1][0], bh[nb*2+1][1], base + G64_BH + msw(row, c));
                LDSM_X4(bl[nb*2][0], bl[nb*2][1], bl[nb*2+1][0], bl[nb*2+1][1], base + G64_BL + msw(row, c));
            }
#pragma unroll
            for (int ma = 0; ma < 2; ma++)
#pragma unroll
                for (int na = 0; na < 8; na++) {
                    MMA16816(acc[ma][na], ah[ma], bh[na]);
                    MMA16816(acc[ma][na], ah[ma], bl[na]);
                    MMA16816(acc[ma][na], al[ma], bh[na]);
                }
        }
    }

    const int g = lid >> 2, t4 = lid & 3;
    const int ncol = n0 + nw * 64;

    if (MODE == 0) {
#pragma unroll
        for (int ma = 0; ma < 2; ma++) {
            int row0 = m0 + mw * 32 + ma * 16 + g;
#pragma unroll
            for (int na = 0; na < 8; na++) {
                int col = ncol + na * 8 + t4 * 2;
                *(float2*)(Cf + (size_t)row0 * ldc + col) =
                    make_float2(acc[ma][na][0], acc[ma][na][1]);
                *(float2*)(Cf + (size_t)(row0 + 8) * ldc + col) =
                    make_float2(acc[ma][na][2], acc[ma][na][3]);
            }
        }
    } else {
#pragma unroll
        for (int ma = 0; ma < 2; ma++) {
            int row0 = m0 + mw * 32 + ma * 16 + g;
#pragma unroll
            for (int na = 0; na < 8; na++) {
                int col = ncol + na * 8 + t4 * 2;
                uint32_t h0, l0;
                split2(acc[ma][na][0], acc[ma][na][1], h0, l0);
                *(uint32_t*)(Ch + (size_t)row0 * ldc + col) = h0;
                *(uint32_t*)(Cl + (size_t)row0 * ldc + col) = l0;
                split2(acc[ma][na][2], acc[ma][na][3], h0, l0);
                *(uint32_t*)(Ch + (size_t)(row0 + 8) * ldc + col) = h0;
                *(uint32_t*)(Cl + (size_t)(row0 + 8) * ldc + col) = l0;
            }
        }
    }
}

// ======= mega up-projection GEMM: 128x128 tile, 256 threads, 2 CTAs/SM =====
#define GEMM_SMEM (3*32768)
#define MS_AH 0
#define MS_AL 8192
#define MS_BH 16384
#define MS_BL 24576
#define MS_STAGE 32768

__global__ __launch_bounds__(256, 2) void gemm_up(
    const __nv_bfloat16* __restrict__ Ah, const __nv_bfloat16* __restrict__ Al, int lda,
    const __nv_bfloat16* __restrict__ Bh, const __nv_bfloat16* __restrict__ Bl, int ldb,
    __nv_bfloat16* __restrict__ Ch, __nv_bfloat16* __restrict__ Cl,
    __nv_bfloat16* __restrict__ Dh, __nv_bfloat16* __restrict__ Dl,
    __nv_bfloat16* __restrict__ Eh, __nv_bfloat16* __restrict__ El,
    const float* __restrict__ Rt, int K)
{
    extern __shared__ char smem[];
    const int tid = threadIdx.x, wid = tid >> 5, lid = tid & 31;
    const int m0 = blockIdx.y * 128, n0 = blockIdx.x * 128;
    uint32_t sb = smem_to_u32(smem);

    {
        int nb = blockIdx.x;
        int aoff = (nb < 16) ? 0 : ((nb < 24) ? CR : 2 * CR);
        Ah += aoff; Al += aoff;
    }

    const int mw = wid & 3, nw = wid >> 2;
    const int a_tr = (lid & 7) + ((lid >> 3) & 1) * 8;
    const int a_kq = lid >> 4;
    const int b_tr = (lid & 7) + (lid >> 4) * 8;
    const int b_kq = (lid >> 3) & 1;

    float acc[2][8][4];
#pragma unroll
    for (int i = 0; i < 2; i++)
#pragma unroll
        for (int j = 0; j < 8; j++)
#pragma unroll
            for (int q = 0; q < 4; q++) acc[i][j][q] = 0.f;

    auto issue = [&](int stg, int k0) {
        uint32_t base = sb + stg * MS_STAGE;
#pragma unroll
        for (int it = 0; it < 2; it++) {
            int ch = it * 256 + tid;
            int row = ch >> 2, c = ch & 3;
            uint32_t so = msw(row, c);
            size_t ga = (size_t)(m0 + row) * lda + k0 + c * 8;
            size_t gb = (size_t)(n0 + row) * ldb + k0 + c * 8;
            CP_ASYNC16(base + MS_AH + so, Ah + ga);
            CP_ASYNC16(base + MS_AL + so, Al + ga);
            CP_ASYNC16(base + MS_BH + so, Bh + gb);
            CP_ASYNC16(base + MS_BL + so, Bl + gb);
        }
        CP_COMMIT();
    };

    const int niter = K >> 5;
    issue(0, 0);
    if (niter > 1) issue(1, 32);

    for (int it = 0; it < niter; it++) {
        if (it + 1 < niter) { CP_WAIT(1); } else { CP_WAIT(0); }
        __syncthreads();
        if (it + 2 < niter) issue((it + 2) % 3, (it + 2) * 32);

        uint32_t base = sb + (it % 3) * MS_STAGE;
#pragma unroll
        for (int ks = 0; ks < 2; ks++) {
            uint32_t ah[2][4], al[2][4], bh[8][2], bl[8][2];
#pragma unroll
            for (int ma = 0; ma < 2; ma++) {
                int row = mw * 32 + ma * 16 + a_tr;
                int c = ks * 2 + a_kq;
                LDSM_X4(ah[ma][0], ah[ma][1], ah[ma][2], ah[ma][3], base + MS_AH + msw(row, c));
                LDSM_X4(al[ma][0], al[ma][1], al[ma][2], al[ma][3], base + MS_AL + msw(row, c));
            }
#pragma unroll
            for (int nb = 0; nb < 4; nb++) {
                int row = nw * 64 + nb * 16 + b_tr;
                int c = ks * 2 + b_kq;
                LDSM_X4(bh[nb*2][0], bh[nb*2][1], bh[nb*2+1][0], bh[nb*2+1][1], base + MS_BH + msw(row, c));
                LDSM_X4(bl[nb*2][0], bl[nb*2][1], bl[nb*2+1][0], bl[nb*2+1][1], base + MS_BL + msw(row, c));
            }
#pragma unroll
            for (int ma = 0; ma < 2; ma++)
#pragma unroll
                for (int na = 0; na < 8; na++) {
                    MMA16816(acc[ma][na], ah[ma], bh[na]);
                    MMA16816(acc[ma][na], ah[ma], bl[na]);
                    MMA16816(acc[ma][na], al[ma], bh[na]);
                }
        }
    }

    const int g = lid >> 2, t4 = lid & 3;
    const int ncol = n0 + nw * 64;

    const bool is_rope = (ncol < CE) || (ncol >= 2*CE && ncol < 3*CE);
    const bool is_v    = (ncol >= 4*CE);
    __nv_bfloat16 *Oh, *Ol;
    int hq;
    if (ncol < CE)           { Oh = Ch; Ol = Cl; hq = ncol >> 6; }
    else if (ncol < 2*CE)    { Oh = Ch; Ol = Cl; hq = (ncol - CE) >> 6; }
    else if (ncol < 3*CE)    { Oh = Dh; Ol = Dl; hq = (ncol - 2*CE) >> 6; }
    else if (ncol < 4*CE)    { Oh = Dh; Ol = Dl; hq = (ncol - 3*CE) >> 6; }
    else                     { Oh = Eh; Ol = El; hq = (ncol - 4*CE) >> 6; }

    if (is_rope) {
#pragma unroll
        for (int ma = 0; ma < 2; ma++) {
            int r0 = m0 + mw * 32 + ma * 16 + g;
            int b = r0 >> 11;
            size_t bb = (size_t)((b << 4) + hq) * CS * CDQK;
#pragma unroll
            for (int rh = 0; rh < 2; rh++) {
                int s = (r0 + rh * 8) & (CS - 1);
                size_t base = bb + (size_t)s * CDQK;
                const float* rt = Rt + s * 64;
#pragma unroll
                for (int na = 0; na < 4; na++) {
                    int e = rh * 2;
                    int i0 = na * 8 + t4 * 2;
                    float x1a = acc[ma][na][e],   x1b = acc[ma][na][e+1];
                    float x2a = acc[ma][na+4][e], x2b = acc[ma][na+4][e+1];
                    float4 cs4 = *(const float4*)(rt + i0 * 2);
                    float o1a = x1a*cs4.x - x2a*cs4.y, o1b = x1b*cs4.z - x2b*cs4.w;
                    float o2a = x2a*cs4.x + x1a*cs4.y, o2b = x2b*cs4.z + x1b*cs4.w;
                    uint32_t h0, l0;
                    split2(o1a, o1b, h0, l0);
                    *(uint32_t*)(Oh + base + i0) = h0;
                    *(uint32_t*)(Ol + base + i0) = l0;
                    split2(o2a, o2b, h0, l0);
                    *(uint32_t*)(Oh + base + 32 + i0) = h0;
                    *(uint32_t*)(Ol + base + 32 + i0) = l0;
                }
            }
        }
    } else if (!is_v) {
#pragma unroll
        for (int ma = 0; ma < 2; ma++) {
            int r0 = m0 + mw * 32 + ma * 16 + g;
            int b = r0 >> 11;
            size_t bb = (size_t)((b << 4) + hq) * CS * CDQK;
#pragma unroll
            for (int rh = 0; rh < 2; rh++) {
                int s = (r0 + rh * 8) & (CS - 1);
                size_t base = bb + (size_t)s * CDQK + 64;
#pragma unroll
                for (int na = 0; na < 8; na++) {
                    int d0 = na * 8 + t4 * 2;
                    uint32_t h0, l0;
                    split2(acc[ma][na][rh*2], acc[ma][na][rh*2+1], h0, l0);
                    *(uint32_t*)(Oh + base + d0) = h0;
                    *(uint32_t*)(Ol + base + d0) = l0;
                }
            }
        }
    } else {
#pragma unroll
        for (int ma = 0; ma < 2; ma++) {
            int r0 = m0 + mw * 32 + ma * 16 + g;
            int b = r0 >> 11;
            size_t bb = (size_t)((b << 4) + hq) * CHD;
#pragma unroll
            for (int rh = 0; rh < 2; rh++) {
                int s = (r0 + rh * 8) & (CS - 1);
#pragma unroll
                for (int na = 0; na < 8; na++) {
#pragma unroll
                    for (int j = 0; j < 2; j++) {
                        int d = na * 8 + t4 * 2 + j;
                        float v = acc[ma][na][rh*2 + j];
                        __nv_bfloat16 hv = __float2bfloat16(v);
                        size_t o = (bb + d) * CS + s;
                        Oh[o] = hv;
                        Ol[o] = __float2bfloat16(v - __bfloat162float(hv));
                    }
                }
            }
        }
    }
}

// =================== causal flash attention ================================
#define FQH 0
#define FQL 32768
#define FKV0 65536
#define FKV_STAGE 49152
#define FO_KH 0
#define FO_KL 16384
#define FO_VH 32768
#define FO_VL 40960
#define FLASH_SMEM (65536 + 3*49152)
#define NQB (CS/128)

__device__ __forceinline__ uint32_t fsw(int row, int chunk) {
    return (uint32_t)(row * 256 + ((chunk >> 3) << 7) + (((chunk & 7) ^ (row & 7)) << 4));
}
__device__ __forceinline__ uint32_t vsw(int row, int chunk) {
    return (uint32_t)(row * 128 + ((chunk ^ (row & 7)) << 4));
}

__global__ __launch_bounds__(256) void flash_attn_mma(
    const __nv_bfloat16* __restrict__ Qh, const __nv_bfloat16* __restrict__ Ql,
    const __nv_bfloat16* __restrict__ Kh, const __nv_bfloat16* __restrict__ Kl,
    const __nv_bfloat16* __restrict__ Vh, const __nv_bfloat16* __restrict__ Vl,
    __nv_bfloat16* __restrict__ Yh, __nv_bfloat16* __restrict__ Yl)
{
    extern __shared__ char smem[];
    uint32_t sb = smem_to_u32(smem);
    const int tid = threadIdx.x, wid = tid >> 5, lid = tid & 31;
    const int bh = blockIdx.x;
    const int qb = NQB - 1 - blockIdx.y;
    const int q0 = qb * 128;
    const int g = lid >> 2, t = lid & 3;

    const __nv_bfloat16* Qhg = Qh + (size_t)bh * CS * CDQK;
    const __nv_bfloat16* Qlg = Ql + (size_t)bh * CS * CDQK;
    const __nv_bfloat16* Khg = Kh + (size_t)bh * CS * CDQK;
    const __nv_bfloat16* Klg = Kl + (size_t)bh * CS * CDQK;
    const __nv_bfloat16* Vhg = Vh + (size_t)bh * CHD * CS;
    const __nv_bfloat16* Vlg = Vl + (size_t)bh * CHD * CS;

    auto issue_kv = [&](int stg, int k0) {
        uint32_t base = sb + FKV0 + stg * FKV_STAGE;
#pragma unroll
        for (int it = 0; it < 4; it++) {
            int i = it * 256 + tid;
            int row = i >> 4, ch = i & 15;
            size_t off = (size_t)(k0 + row) * CDQK + ch * 8;
            uint32_t so = fsw(row, ch);
            CP_ASYNC16(base + FO_KH + so, Khg + off);
            CP_ASYNC16(base + FO_KL + so, Klg + off);
        }
#pragma unroll
        for (int it = 0; it < 2; it++) {
            int i = it * 256 + tid;
            int row = i >> 3, ch = i & 7;
            size_t off = (size_t)row * CS + k0 + ch * 8;
            uint32_t so = vsw(row, ch);
            CP_ASYNC16(base + FO_VH + so, Vhg + off);
            CP_ASYNC16(base + FO_VL + so, Vlg + off);
        }
        CP_COMMIT();
    };

    const int nkb = 2 * qb + 2;
    issue_kv(0, 0);
    if (nkb > 1) issue_kv(1, 64);

#pragma unroll
    for (int it = 0; it < 8; it++) {
        int i = it * 256 + tid;
        int row = i >> 4, ch = i & 15;
        size_t off = (size_t)(q0 + row) * CDQK + ch * 8;
        *(uint4*)(smem + FQH + fsw(row, ch)) = *(const uint4*)(Qhg + off);
        *(uint4*)(smem + FQL + fsw(row, ch)) = *(const uint4*)(Qlg + off);
    }
    __syncthreads();

    const int a_tr = (lid & 7) + ((lid >> 3) & 1) * 8;
    const int a_kq = lid >> 4;
    const int b_tr = (lid & 7) + (lid >> 4) * 8;
    const int b_kq = (lid >> 3) & 1;

    uint32_t qhf[8][4], qlf[8][4];
#pragma unroll
    for (int ks = 0; ks < 8; ks++) {
        LDSM_X4(qhf[ks][0], qhf[ks][1], qhf[ks][2], qhf[ks][3],
                sb + FQH + fsw(wid * 16 + a_tr, ks * 2 + a_kq));
        LDSM_X4(qlf[ks][0], qlf[ks][1], qlf[ks][2], qlf[ks][3],
                sb + FQL + fsw(wid * 16 + a_tr, ks * 2 + a_kq));
    }

    float O[8][4];
#pragma unroll
    for (int na = 0; na < 8; na++)
#pragma unroll
        for (int e = 0; e < 4; e++) O[na][e] = 0.f;
    float mI0 = -1e30f, mI1 = -1e30f, lI0 = 0.f, lI1 = 0.f;
    const float scale = 0.08838834764831845f;

    const int qw_last = q0 + wid * 16 + 15;

    for (int kb = 0; kb < nkb; kb++) {
        const int k0 = kb * 64;
        if (kb + 1 < nkb) { CP_WAIT(1); } else { CP_WAIT(0); }
        __syncthreads();
        if (kb + 2 < nkb) issue_kv((kb + 2) % 3, (kb + 2) * 64);

        if (k0 <= qw_last) {
            uint32_t kvb = sb + FKV0 + (kb % 3) * FKV_STAGE;

            float sc[8][4];
#pragma unroll
            for (int na = 0; na < 8; na++)
#pragma unroll
                for (int e = 0; e < 4; e++) sc[na][e] = 0.f;

#pragma unroll
            for (int ks = 0; ks < 8; ks++) {
                uint32_t khf[8][2], klf[8][2];
#pragma unroll
                for (int nb = 0; nb < 4; nb++) {
                    uint32_t so = fsw(nb * 16 + b_tr, ks * 2 + b_kq);
                    LDSM_X4(khf[nb*2][0], khf[nb*2][1], khf[nb*2+1][0], khf[nb*2+1][1], kvb + FO_KH + so);
                    LDSM_X4(klf[nb*2][0], klf[nb*2][1], klf[nb*2+1][0], klf[nb*2+1][1], kvb + FO_KL + so);
                }
#pragma unroll
                for (int na = 0; na < 8; na++) {
                    MMA16816(sc[na], qhf[ks], khf[na]);
                    MMA16816(sc[na], qhf[ks], klf[na]);
                    MMA16816(sc[na], qlf[ks], khf[na]);
                }
            }

            if (k0 + 63 > qw_last - 15) {
#pragma unroll
                for (int na = 0; na < 8; na++)
#pragma unroll
                    for (int e = 0; e < 4; e++) {
                        int qr = q0 + wid * 16 + g + ((e >> 1) << 3);
                        int kc = k0 + na * 8 + 2 * t + (e & 1);
                        sc[na][e] = (kc > qr) ? -1e30f : sc[na][e] * scale;
                    }
            } else {
#pragma unroll
                for (int na = 0; na < 8; na++)
#pragma unroll
                    for (int e = 0; e < 4; e++) sc[na][e] *= scale;
            }

            float mx0 = -1e30f, mx1 = -1e30f;
#pragma unroll
            for (int na = 0; na < 8; na++) {
                mx0 = fmaxf(mx0, fmaxf(sc[na][0], sc[na][1]));
                mx1 = fmaxf(mx1, fmaxf(sc[na][2], sc[na][3]));
            }
            mx0 = fmaxf(mx0, __shfl_xor_sync(0xffffffffu, mx0, 1));
            mx0 = fmaxf(mx0, __shfl_xor_sync(0xffffffffu, mx0, 2));
            mx1 = fmaxf(mx1, __shfl_xor_sync(0xffffffffu, mx1, 1));
            mx1 = fmaxf(mx1, __shfl_xor_sync(0xffffffffu, mx1, 2));

            float mn0 = fmaxf(mI0, mx0), mn1 = fmaxf(mI1, mx1);
            float al0 = __expf(mI0 - mn0), al1 = __expf(mI1 - mn1);
            mI0 = mn0; mI1 = mn1;

            float rs0 = 0.f, rs1 = 0.f;
#pragma unroll
            for (int na = 0; na < 8; na++) {
                sc[na][0] = __expf(sc[na][0] - mn0); rs0 += sc[na][0];
                sc[na][1] = __expf(sc[na][1] - mn0); rs0 += sc[na][1];
                sc[na][2] = __expf(sc[na][2] - mn1); rs1 += sc[na][2];
                sc[na][3] = __expf(sc[na][3] - mn1); rs1 += sc[na][3];
            }
            rs0 += __shfl_xor_sync(0xffffffffu, rs0, 1);
            rs0 += __shfl_xor_sync(0xffffffffu, rs0, 2);
            rs1 += __shfl_xor_sync(0xffffffffu, rs1, 1);
            rs1 += __shfl_xor_sync(0xffffffffu, rs1, 2);
            lI0 = lI0 * al0 + rs0;
            lI1 = lI1 * al1 + rs1;

#pragma unroll
            for (int na = 0; na < 8; na++) {
                O[na][0] *= al0; O[na][1] *= al0;
                O[na][2] *= al1; O[na][3] *= al1;
            }

#pragma unroll
            for (int kk = 0; kk < 4; kk++) {
                uint32_t pah[4], pal[4];
                split2(sc[2*kk][0],   sc[2*kk][1],   pah[0], pal[0]);
                split2(sc[2*kk][2],   sc[2*kk][3],   pah[1], pal[1]);
                split2(sc[2*kk+1][0], sc[2*kk+1][1], pah[2], pal[2]);
                split2(sc[2*kk+1][2], sc[2*kk+1][3], pah[3], pal[3]);
                uint32_t vhf[8][2], vlf[8][2];
#pragma unroll
                for (int nb = 0; nb < 4; nb++) {
                    uint32_t so = vsw(nb * 16 + b_tr, kk * 2 + b_kq);
                    LDSM_X4(vhf[nb*2][0], vhf[nb*2][1], vhf[nb*2+1][0], vhf[nb*2+1][1], kvb + FO_VH + so);
                    LDSM_X4(vlf[nb*2][0], vlf[nb*2][1], vlf[nb*2+1][0], vlf[nb*2+1][1], kvb + FO_VL + so);
                }
#pragma unroll
                for (int na = 0; na < 8; na++) {
                    MMA16816(O[na], pah, vhf[na]);
                    MMA16816(O[na], pal, vhf[na]);
                    MMA16816(O[na], pah, vlf[na]);
                }
            }
        }
    }

    const int b = bh >> 4, h = bh & 15;
    const float inv0 = 1.f / lI0, inv1 = 1.f / lI1;
    const int qr0 = q0 + wid * 16 + g;
#pragma unroll
    for (int na = 0; na < 8; na++) {
        int col = h * CHD + na * 8 + 2 * t;
        uint32_t h0, l0;
        split2(O[na][0] * inv0, O[na][1] * inv0, h0, l0);
        *(uint32_t*)(Yh + (size_t)(b*CS + qr0) * CE + col) = h0;
        *(uint32_t*)(Yl + (size_t)(b*CS + qr0) * CE + col) = l0;
        split2(O[na][2] * inv1, O[na][3] * inv1, h0, l0);
        *(uint32_t*)(Yh + (size_t)(b*CS + qr0 + 8) * CE + col) = h0;
        *(uint32_t*)(Yl + (size_t)(b*CS + qr0 + 8) * CE + col) = l0;
    }
}

// ============================== launcher ===================================
extern "C" void kernel_launch(void* const* d_in, const int* in_sizes, int n_in,
                              void* d_out, int out_size)
{
    const float* x        = (const float*)d_in[0];
    const float* wq_down  = (const float*)d_in[1];
    const float* wk_rope  = (const float*)d_in[2];
    const float* wkv_down = (const float*)d_in[3];
    const float* wq_rope  = (const float*)d_in[4];
    const float* wq_up    = (const float*)d_in[5];
    const float* wk_up    = (const float*)d_in[6];
    const float* wv_up    = (const float*)d_in[7];
    const float* wo       = (const float*)d_in[8];
    float* out = (float*)d_out;

    __nv_bfloat16 *xh,*xl,*lath,*latl,*Yh,*Yl,*wdh,*wdl,*wuh,*wul,*w7h,*w7l;
    __nv_bfloat16 *Qbh,*Qbl,*Kbh,*Kbl,*Vbh,*Vbl;
    float* rtab;
    cudaGetSymbolAddress((void**)&xh,   g_xh);   cudaGetSymbolAddress((void**)&xl,   g_xl);
    cudaGetSymbolAddress((void**)&lath, g_lath); cudaGetSymbolAddress((void**)&latl, g_latl);
    cudaGetSymbolAddress((void**)&Yh,   g_Yh);   cudaGetSymbolAddress((void**)&Yl,   g_Yl);
    cudaGetSymbolAddress((void**)&wdh,  g_wdh);  cudaGetSymbolAddress((void**)&wdl,  g_wdl);
    cudaGetSymbolAddress((void**)&wuh,  g_wuh);  cudaGetSymbolAddress((void**)&wul,  g_wul);
    cudaGetSymbolAddress((void**)&w7h,  g_w7h);  cudaGetSymbolAddress((void**)&w7l,  g_w7l);
    cudaGetSymbolAddress((void**)&Qbh,  g_Qbh);  cudaGetSymbolAddress((void**)&Qbl,  g_Qbl);
    cudaGetSymbolAddress((void**)&Kbh,  g_Kbh);  cudaGetSymbolAddress((void**)&Kbl,  g_Kbl);
    cudaGetSymbolAddress((void**)&Vbh,  g_Vbh);  cudaGetSymbolAddress((void**)&Vbl,  g_Vbl);
    cudaGetSymbolAddress((void**)&rtab, g_ropetab);

    cudaFuncSetAttribute(gemm64<0>, cudaFuncAttributeMaxDynamicSharedMemorySize, G64_SMEM);
    cudaFuncSetAttribute(gemm64<1>, cudaFuncAttributeMaxDynamicSharedMemorySize, G64_SMEM);
    cudaFuncSetAttribute(gemm_up,   cudaFuncAttributeMaxDynamicSharedMemorySize, GEMM_SMEM);
    cudaFuncSetAttribute(flash_attn_mma, cudaFuncAttributeMaxDynamicSharedMemorySize, FLASH_SMEM);

    // prep (3 launches)
    build_rope_tab<<<(CS*32) / 256, 256>>>(rtab);
    cvt_split<<<(MTOK*CE + 255) / 256, 256>>>(x, xh, xl, MTOK*CE);
    cvt_weights<<<(8*WSEG + CE*CE + 255) / 256, 256>>>(
        wq_down, wk_rope, wkv_down, wq_rope, wq_up, wk_up, wv_up, wo,
        wdh, wdl, wuh, wul, w7h, w7l);

    // fused down projection: lat[4096,768] = x @ [wq_down|wk_rope|wkv_down]^T
    gemm64<1><<<dim3(NLAT/128, MTOK/64), 128, G64_SMEM>>>(
        xh, xl, CE, wdh, wdl, CE, nullptr, lath, latl, NLAT, CE);

    // mega up-projection: all 5 up-GEMMs in one launch -> Q, K, V
    gemm_up<<<dim3(40, MTOK/128), 256, GEMM_SMEM>>>(
        lath, latl, NLAT, wuh, wul, CR, Qbh, Qbl, Kbh, Kbl, Vbh, Vbl, rtab, CR);

    // causal flash attention (LPT-ordered grid) -> Yh/Yl
    flash_attn_mma<<<dim3(CB*CH, NQB), 256, FLASH_SMEM>>>(
        Qbh, Qbl, Kbh, Kbl, Vbh, Vbl, Yh, Yl);

    // output projection: Y @ wo^T -> out (fp32)
    gemm64<0><<<dim3(CE/128, MTOK/64), 128, G64_SMEM>>>(
        Yh, Yl, CE, w7h, w7l, CE, out, nullptr, nullptr, CE, CE);
}

// round 17
// speedup vs baseline: 3.8751x; 1.0160x over previous
#include <cuda_runtime.h>
#include <cuda_bf16.h>
#include <cstdint>
#include <math.h>

#define CB   2
#define CS   2048
#define CE   1024
#define CR   256
#define CH   16
#define CHD  64
#define CDQK 128
#define MTOK (CB*CS)   // 4096
#define NLAT 768
#define WSEG (CR*CE)   // 262144

// ---------------- scratch -------------------------------------------------
__device__ __nv_bfloat16 g_xh [MTOK*CE],  g_xl [MTOK*CE];
__device__ __nv_bfloat16 g_lath[MTOK*NLAT], g_latl[MTOK*NLAT];
__device__ __nv_bfloat16 g_Yh [MTOK*CE],  g_Yl [MTOK*CE];
__device__ __nv_bfloat16 g_wdh[NLAT*CE],  g_wdl[NLAT*CE];      // wq_down|wk_rope|wkv_down
__device__ __nv_bfloat16 g_wuh[5*WSEG],   g_wul[5*WSEG];       // wq_rope|wq_up|wk_up|wk_up|wv_up
__device__ __nv_bfloat16 g_w7h[CE*CE],    g_w7l[CE*CE];        // wo
__device__ float g_ropetab[CS*64];

__device__ __nv_bfloat16 g_Qbh[CB*CH*CS*CDQK], g_Qbl[CB*CH*CS*CDQK];
__device__ __nv_bfloat16 g_Kbh[CB*CH*CS*CDQK], g_Kbl[CB*CH*CS*CDQK];
__device__ __nv_bfloat16 g_Vbh[CB*CH*CHD*CS],  g_Vbl[CB*CH*CHD*CS];

// ===================== generic helpers =====================================
__device__ __forceinline__ uint32_t smem_to_u32(const void* p) {
    uint32_t a;
    asm("{ .reg .u64 t; cvta.to.shared.u64 t, %1; cvt.u32.u64 %0, t; }" : "=r"(a) : "l"(p));
    return a;
}

#define LDSM_X4(r0,r1,r2,r3, addr) \
    asm volatile("ldmatrix.sync.aligned.m8n8.x4.shared.b16 {%0,%1,%2,%3}, [%4];" \
        : "=r"(r0), "=r"(r1), "=r"(r2), "=r"(r3) : "r"(addr))

#define MMA16816(c, a, b) \
    asm volatile("mma.sync.aligned.m16n8k16.row.col.f32.bf16.bf16.f32 " \
        "{%0,%1,%2,%3}, {%4,%5,%6,%7}, {%8,%9}, {%0,%1,%2,%3};" \
        : "+f"((c)[0]), "+f"((c)[1]), "+f"((c)[2]), "+f"((c)[3]) \
        : "r"((a)[0]), "r"((a)[1]), "r"((a)[2]), "r"((a)[3]), "r"((b)[0]), "r"((b)[1]))

#define CP_ASYNC16(dst, src) \
    asm volatile("cp.async.cg.shared.global [%0], [%1], 16;" :: "r"(dst), "l"(src))
#define CP_COMMIT() asm volatile("cp.async.commit_group;" ::: "memory")
#define CP_WAIT(n)  asm volatile("cp.async.wait_group %0;" :: "n"(n) : "memory")

__device__ __forceinline__ void split2(float a, float b, uint32_t& hi, uint32_t& lo) {
    __nv_bfloat16 ha = __float2bfloat16(a), hb = __float2bfloat16(b);
    float ra = a - __bfloat162float(ha);
    float rb = b - __bfloat162float(hb);
    __nv_bfloat162 hh; hh.x = ha; hh.y = hb;
    hi = *(uint32_t*)&hh;
    __nv_bfloat162 ll = __floats2bfloat162_rn(ra, rb);
    lo = *(uint32_t*)&ll;
}

#define ROPE_L 0.41524101186109f

// ===================== fused prep kernel ===================================
// One launch: cvt x, cvt all weights (wk_up duplicated), build rope LUT.
#define PREP_X   (MTOK*CE)                     // 4194304
#define PREP_W   (PREP_X + 8*WSEG)             // 6291456
#define PREP_WO  (PREP_W + CE*CE)              // 7340032
#define PREP_TAB (PREP_WO + CS*32)             // 7405568

__global__ void prep_all(
    const float* __restrict__ x,
    const float* __restrict__ wq_down, const float* __restrict__ wk_rope,
    const float* __restrict__ wkv_down, const float* __restrict__ wq_rope,
    const float* __restrict__ wq_up,   const float* __restrict__ wk_up,
    const float* __restrict__ wv_up,   const float* __restrict__ wo,
    __nv_bfloat16* __restrict__ xh,   __nv_bfloat16* __restrict__ xl,
    __nv_bfloat16* __restrict__ wdh,  __nv_bfloat16* __restrict__ wdl,
    __nv_bfloat16* __restrict__ wuh,  __nv_bfloat16* __restrict__ wul,
    __nv_bfloat16* __restrict__ w7h,  __nv_bfloat16* __restrict__ w7l,
    float* __restrict__ tab)
{
    int i = blockIdx.x * blockDim.x + threadIdx.x;
    if (i < PREP_X) {
        float v = x[i];
        __nv_bfloat16 h = __float2bfloat16(v);
        xh[i] = h;
        xl[i] = __float2bfloat16(v - __bfloat162float(h));
    } else if (i < PREP_W) {
        int j = i - PREP_X;
        int seg = j / WSEG;
        int off = j - seg * WSEG;
        const float* src;
        __nv_bfloat16 *dh, *dl;
        switch (seg) {
            case 0: src = wq_down;  dh = wdh;          dl = wdl;          break;
            case 1: src = wk_rope;  dh = wdh + WSEG;   dl = wdl + WSEG;   break;
            case 2: src = wkv_down; dh = wdh + 2*WSEG; dl = wdl + 2*WSEG; break;
            case 3: src = wq_rope;  dh = wuh;          dl = wul;          break;
            case 4: src = wq_up;    dh = wuh + WSEG;   dl = wul + WSEG;   break;
            case 5: src = wk_up;    dh = wuh + 2*WSEG; dl = wul + 2*WSEG; break;
            case 6: src = wk_up;    dh = wuh + 3*WSEG; dl = wul + 3*WSEG; break;
            default: src = wv_up;   dh = wuh + 4*WSEG; dl = wul + 4*WSEG; break;
        }
        float v = src[off];
        __nv_bfloat16 h = __float2bfloat16(v);
        dh[off] = h;
        dl[off] = __float2bfloat16(v - __bfloat162float(h));
    } else if (i < PREP_WO) {
        int off = i - PREP_W;
        float v = wo[off];
        __nv_bfloat16 h = __float2bfloat16(v);
        w7h[off] = h;
        w7l[off] = __float2bfloat16(v - __bfloat162float(h));
    } else if (i < PREP_TAB) {
        int idx = i - PREP_WO;             // CS*32
        int s = idx >> 5, d = idx & 31;
        float ang = (float)s * exp2f(-(float)d * ROPE_L);
        float sn, cs;
        sincosf(ang, &sn, &cs);
        tab[(idx << 1)]     = cs;
        tab[(idx << 1) + 1] = sn;
    }
}

__device__ __forceinline__ uint32_t msw(int row, int c) {
    return (uint32_t)(row * 64 + ((c ^ ((row >> 1) & 3)) << 4));
}

// ======= GEMM-64: 64x128 CTA tile, 128 threads, 3 CTAs/SM (K=1024 GEMMs) ===
#define G64_AH 0
#define G64_AL 4096
#define G64_BH 8192
#define G64_BL 16384
#define G64_STAGE 24576
#define G64_SMEM (3*24576)

template<int MODE>
__global__ __launch_bounds__(128, 3) void gemm64(
    const __nv_bfloat16* __restrict__ Ah, const __nv_bfloat16* __restrict__ Al, int lda,
    const __nv_bfloat16* __restrict__ Bh, const __nv_bfloat16* __restrict__ Bl, int ldb,
    float* __restrict__ Cf, __nv_bfloat16* __restrict__ Ch, __nv_bfloat16* __restrict__ Cl,
    int ldc, int K)
{
    extern __shared__ char smem[];
    const int tid = threadIdx.x, wid = tid >> 5, lid = tid & 31;
    const int m0 = blockIdx.y * 64, n0 = blockIdx.x * 128;
    uint32_t sb = smem_to_u32(smem);

    const int mw = wid & 1, nw = wid >> 1;
    const int a_tr = (lid & 7) + ((lid >> 3) & 1) * 8;
    const int a_kq = lid >> 4;
    const int b_tr = (lid & 7) + (lid >> 4) * 8;
    const int b_kq = (lid >> 3) & 1;

    float acc[2][8][4];
#pragma unroll
    for (int i = 0; i < 2; i++)
#pragma unroll
        for (int j = 0; j < 8; j++)
#pragma unroll
            for (int q = 0; q < 4; q++) acc[i][j][q] = 0.f;

    auto issue = [&](int stg, int k0) {
        uint32_t base = sb + stg * G64_STAGE;
#pragma unroll
        for (int it = 0; it < 2; it++) {
            int ch = it * 128 + tid;
            int row = ch >> 2, c = ch & 3;
            uint32_t so = msw(row, c);
            size_t ga = (size_t)(m0 + row) * lda + k0 + c * 8;
            CP_ASYNC16(base + G64_AH + so, Ah + ga);
            CP_ASYNC16(base + G64_AL + so, Al + ga);
        }
#pragma unroll
        for (int it = 0; it < 4; it++) {
            int ch = it * 128 + tid;
            int row = ch >> 2, c = ch & 3;
            uint32_t so = msw(row, c);
            size_t gb = (size_t)(n0 + row) * ldb + k0 + c * 8;
            CP_ASYNC16(base + G64_BH + so, Bh + gb);
            CP_ASYNC16(base + G64_BL + so, Bl + gb);
        }
        CP_COMMIT();
    };

    const int niter = K >> 5;
    issue(0, 0);
    if (niter > 1) issue(1, 32);

    for (int it = 0; it < niter; it++) {
        if (it + 1 < niter) { CP_WAIT(1); } else { CP_WAIT(0); }
        __syncthreads();
        if (it + 2 < niter) issue((it + 2) % 3, (it + 2) * 32);

        uint32_t base = sb + (it % 3) * G64_STAGE;
#pragma unroll
        for (int ks = 0; ks < 2; ks++) {
            uint32_t ah[2][4], al[2][4], bh[8][2], bl[8][2];
#pragma unroll
            for (int ma = 0; ma < 2; ma++) {
                int row = mw * 32 + ma * 16 + a_tr;
                int c = ks * 2 + a_kq;
                LDSM_X4(ah[ma][0], ah[ma][1], ah[ma][2], ah[ma][3], base + G64_AH + msw(row, c));
                LDSM_X4(al[ma][0], al[ma][1], al[ma][2], al[ma][3], base + G64_AL + msw(row, c));
            }
#pragma unroll
            for (int nb = 0; nb < 4; nb++) {
                int row = nw * 64 + nb * 16 + b_tr;
                int c = ks * 2 + b_kq;
                LDSM_X4(bh[nb*2][0], bh[nb*2][1], bh[nb*2+1][0], bh[nb*2+1][1], base + G64_BH + msw(row, c));
                LDSM_X4(bl[nb*2][0], bl[nb*2][1], bl[nb*2+1][0], bl[nb*2+1][1], base + G64_BL + msw(row, c));
            }
#pragma unroll
            for (int ma = 0; ma < 2; ma++)
#pragma unroll
                for (int na = 0; na < 8; na++) {
                    MMA16816(acc[ma][na], ah[ma], bh[na]);
                    MMA16816(acc[ma][na], ah[ma], bl[na]);
                    MMA16816(acc[ma][na], al[ma], bh[na]);
                }
        }
    }

    const int g = lid >> 2, t4 = lid & 3;
    const int ncol = n0 + nw * 64;

    if (MODE == 0) {
#pragma unroll
        for (int ma = 0; ma < 2; ma++) {
            int row0 = m0 + mw * 32 + ma * 16 + g;
#pragma unroll
            for (int na = 0; na < 8; na++) {
                int col = ncol + na * 8 + t4 * 2;
                *(float2*)(Cf + (size_t)row0 * ldc + col) =
                    make_float2(acc[ma][na][0], acc[ma][na][1]);
                *(float2*)(Cf + (size_t)(row0 + 8) * ldc + col) =
                    make_float2(acc[ma][na][2], acc[ma][na][3]);
            }
        }
    } else {
#pragma unroll
        for (int ma = 0; ma < 2; ma++) {
            int row0 = m0 + mw * 32 + ma * 16 + g;
#pragma unroll
            for (int na = 0; na < 8; na++) {
                int col = ncol + na * 8 + t4 * 2;
                uint32_t h0, l0;
                split2(acc[ma][na][0], acc[ma][na][1], h0, l0);
                *(uint32_t*)(Ch + (size_t)row0 * ldc + col) = h0;
                *(uint32_t*)(Cl + (size_t)row0 * ldc + col) = l0;
                split2(acc[ma][na][2], acc[ma][na][3], h0, l0);
                *(uint32_t*)(Ch + (size_t)(row0 + 8) * ldc + col) = h0;
                *(uint32_t*)(Cl + (size_t)(row0 + 8) * ldc + col) = l0;
            }
        }
    }
}

// ======= mega up-projection GEMM: 128x128 tile, 256 threads, 2 CTAs/SM =====
#define GEMM_SMEM (3*32768)
#define MS_AH 0
#define MS_AL 8192
#define MS_BH 16384
#define MS_BL 24576
#define MS_STAGE 32768

__global__ __launch_bounds__(256, 2) void gemm_up(
    const __nv_bfloat16* __restrict__ Ah, const __nv_bfloat16* __restrict__ Al, int lda,
    const __nv_bfloat16* __restrict__ Bh, const __nv_bfloat16* __restrict__ Bl, int ldb,
    __nv_bfloat16* __restrict__ Ch, __nv_bfloat16* __restrict__ Cl,
    __nv_bfloat16* __restrict__ Dh, __nv_bfloat16* __restrict__ Dl,
    __nv_bfloat16* __restrict__ Eh, __nv_bfloat16* __restrict__ El,
    const float* __restrict__ Rt, int K)
{
    extern __shared__ char smem[];
    const int tid = threadIdx.x, wid = tid >> 5, lid = tid & 31;
    const int m0 = blockIdx.y * 128, n0 = blockIdx.x * 128;
    uint32_t sb = smem_to_u32(smem);

    {
        int nb = blockIdx.x;
        int aoff = (nb < 16) ? 0 : ((nb < 24) ? CR : 2 * CR);
        Ah += aoff; Al += aoff;
    }

    const int mw = wid & 3, nw = wid >> 2;
    const int a_tr = (lid & 7) + ((lid >> 3) & 1) * 8;
    const int a_kq = lid >> 4;
    const int b_tr = (lid & 7) + (lid >> 4) * 8;
    const int b_kq = (lid >> 3) & 1;

    float acc[2][8][4];
#pragma unroll
    for (int i = 0; i < 2; i++)
#pragma unroll
        for (int j = 0; j < 8; j++)
#pragma unroll
            for (int q = 0; q < 4; q++) acc[i][j][q] = 0.f;

    auto issue = [&](int stg, int k0) {
        uint32_t base = sb + stg * MS_STAGE;
#pragma unroll
        for (int it = 0; it < 2; it++) {
            int ch = it * 256 + tid;
            int row = ch >> 2, c = ch & 3;
            uint32_t so = msw(row, c);
            size_t ga = (size_t)(m0 + row) * lda + k0 + c * 8;
            size_t gb = (size_t)(n0 + row) * ldb + k0 + c * 8;
            CP_ASYNC16(base + MS_AH + so, Ah + ga);
            CP_ASYNC16(base + MS_AL + so, Al + ga);
            CP_ASYNC16(base + MS_BH + so, Bh + gb);
            CP_ASYNC16(base + MS_BL + so, Bl + gb);
        }
        CP_COMMIT();
    };

    const int niter = K >> 5;
    issue(0, 0);
    if (niter > 1) issue(1, 32);

    for (int it = 0; it < niter; it++) {
        if (it + 1 < niter) { CP_WAIT(1); } else { CP_WAIT(0); }
        __syncthreads();
        if (it + 2 < niter) issue((it + 2) % 3, (it + 2) * 32);

        uint32_t base = sb + (it % 3) * MS_STAGE;
#pragma unroll
        for (int ks = 0; ks < 2; ks++) {
            uint32_t ah[2][4], al[2][4], bh[8][2], bl[8][2];
#pragma unroll
            for (int ma = 0; ma < 2; ma++) {
                int row = mw * 32 + ma * 16 + a_tr;
                int c = ks * 2 + a_kq;
                LDSM_X4(ah[ma][0], ah[ma][1], ah[ma][2], ah[ma][3], base + MS_AH + msw(row, c));
                LDSM_X4(al[ma][0], al[ma][1], al[ma][2], al[ma][3], base + MS_AL + msw(row, c));
            }
#pragma unroll
            for (int nb = 0; nb < 4; nb++) {
                int row = nw * 64 + nb * 16 + b_tr;
                int c = ks * 2 + b_kq;
                LDSM_X4(bh[nb*2][0], bh[nb*2][1], bh[nb*2+1][0], bh[nb*2+1][1], base + MS_BH + msw(row, c));
                LDSM_X4(bl[nb*2][0], bl[nb*2][1], bl[nb*2+1][0], bl[nb*2+1][1], base + MS_BL + msw(row, c));
            }
#pragma unroll
            for (int ma = 0; ma < 2; ma++)
#pragma unroll
                for (int na = 0; na < 8; na++) {
                    MMA16816(acc[ma][na], ah[ma], bh[na]);
                    MMA16816(acc[ma][na], ah[ma], bl[na]);
                    MMA16816(acc[ma][na], al[ma], bh[na]);
                }
        }
    }

    const int g = lid >> 2, t4 = lid & 3;
    const int ncol = n0 + nw * 64;

    const bool is_rope = (ncol < CE) || (ncol >= 2*CE && ncol < 3*CE);
    const bool is_v    = (ncol >= 4*CE);
    __nv_bfloat16 *Oh, *Ol;
    int hq;
    if (ncol < CE)           { Oh = Ch; Ol = Cl; hq = ncol >> 6; }
    else if (ncol < 2*CE)    { Oh = Ch; Ol = Cl; hq = (ncol - CE) >> 6; }
    else if (ncol < 3*CE)    { Oh = Dh; Ol = Dl; hq = (ncol - 2*CE) >> 6; }
    else if (ncol < 4*CE)    { Oh = Dh; Ol = Dl; hq = (ncol - 3*CE) >> 6; }
    else                     { Oh = Eh; Ol = El; hq = (ncol - 4*CE) >> 6; }

    if (is_rope) {
#pragma unroll
        for (int ma = 0; ma < 2; ma++) {
            int r0 = m0 + mw * 32 + ma * 16 + g;
            int b = r0 >> 11;
            size_t bb = (size_t)((b << 4) + hq) * CS * CDQK;
#pragma unroll
            for (int rh = 0; rh < 2; rh++) {
                int s = (r0 + rh * 8) & (CS - 1);
                size_t base = bb + (size_t)s * CDQK;
                const float* rt = Rt + s * 64;
#pragma unroll
                for (int na = 0; na < 4; na++) {
                    int e = rh * 2;
                    int i0 = na * 8 + t4 * 2;
                    float x1a = acc[ma][na][e],   x1b = acc[ma][na][e+1];
                    float x2a = acc[ma][na+4][e], x2b = acc[ma][na+4][e+1];
                    float4 cs4 = *(const float4*)(rt + i0 * 2);
                    float o1a = x1a*cs4.x - x2a*cs4.y, o1b = x1b*cs4.z - x2b*cs4.w;
                    float o2a = x2a*cs4.x + x1a*cs4.y, o2b = x2b*cs4.z + x1b*cs4.w;
                    uint32_t h0, l0;
                    split2(o1a, o1b, h0, l0);
                    *(uint32_t*)(Oh + base + i0) = h0;
                    *(uint32_t*)(Ol + base + i0) = l0;
                    split2(o2a, o2b, h0, l0);
                    *(uint32_t*)(Oh + base + 32 + i0) = h0;
                    *(uint32_t*)(Ol + base + 32 + i0) = l0;
                }
            }
        }
    } else if (!is_v) {
#pragma unroll
        for (int ma = 0; ma < 2; ma++) {
            int r0 = m0 + mw * 32 + ma * 16 + g;
            int b = r0 >> 11;
            size_t bb = (size_t)((b << 4) + hq) * CS * CDQK;
#pragma unroll
            for (int rh = 0; rh < 2; rh++) {
                int s = (r0 + rh * 8) & (CS - 1);
                size_t base = bb + (size_t)s * CDQK + 64;
#pragma unroll
                for (int na = 0; na < 8; na++) {
                    int d0 = na * 8 + t4 * 2;
                    uint32_t h0, l0;
                    split2(acc[ma][na][rh*2], acc[ma][na][rh*2+1], h0, l0);
                    *(uint32_t*)(Oh + base + d0) = h0;
                    *(uint32_t*)(Ol + base + d0) = l0;
                }
            }
        }
    } else {
#pragma unroll
        for (int ma = 0; ma < 2; ma++) {
            int r0 = m0 + mw * 32 + ma * 16 + g;
            int b = r0 >> 11;
            size_t bb = (size_t)((b << 4) + hq) * CHD;
#pragma unroll
            for (int rh = 0; rh < 2; rh++) {
                int s = (r0 + rh * 8) & (CS - 1);
#pragma unroll
                for (int na = 0; na < 8; na++) {
#pragma unroll
                    for (int j = 0; j < 2; j++) {
                        int d = na * 8 + t4 * 2 + j;
                        float v = acc[ma][na][rh*2 + j];
                        __nv_bfloat16 hv = __float2bfloat16(v);
                        size_t o = (bb + d) * CS + s;
                        Oh[o] = hv;
                        Ol[o] = __float2bfloat16(v - __bfloat162float(hv));
                    }
                }
            }
        }
    }
}

// =================== causal flash attention ================================
// BQ=128, 256 threads; K/V 3-stage; Q frags in regs; exp interleaved with PV.
#define FQH 0
#define FQL 32768
#define FKV0 65536
#define FKV_STAGE 49152
#define FO_KH 0
#define FO_KL 16384
#define FO_VH 32768
#define FO_VL 40960
#define FLASH_SMEM (65536 + 3*49152)
#define NQB (CS/128)

__device__ __forceinline__ uint32_t fsw(int row, int chunk) {
    return (uint32_t)(row * 256 + ((chunk >> 3) << 7) + (((chunk & 7) ^ (row & 7)) << 4));
}
__device__ __forceinline__ uint32_t vsw(int row, int chunk) {
    return (uint32_t)(row * 128 + ((chunk ^ (row & 7)) << 4));
}

__global__ __launch_bounds__(256) void flash_attn_mma(
    const __nv_bfloat16* __restrict__ Qh, const __nv_bfloat16* __restrict__ Ql,
    const __nv_bfloat16* __restrict__ Kh, const __nv_bfloat16* __restrict__ Kl,
    const __nv_bfloat16* __restrict__ Vh, const __nv_bfloat16* __restrict__ Vl,
    __nv_bfloat16* __restrict__ Yh, __nv_bfloat16* __restrict__ Yl)
{
    extern __shared__ char smem[];
    uint32_t sb = smem_to_u32(smem);
    const int tid = threadIdx.x, wid = tid >> 5, lid = tid & 31;
    const int bh = blockIdx.x;
    const int qb = NQB - 1 - blockIdx.y;   // LPT
    const int q0 = qb * 128;
    const int g = lid >> 2, t = lid & 3;

    const __nv_bfloat16* Qhg = Qh + (size_t)bh * CS * CDQK;
    const __nv_bfloat16* Qlg = Ql + (size_t)bh * CS * CDQK;
    const __nv_bfloat16* Khg = Kh + (size_t)bh * CS * CDQK;
    const __nv_bfloat16* Klg = Kl + (size_t)bh * CS * CDQK;
    const __nv_bfloat16* Vhg = Vh + (size_t)bh * CHD * CS;
    const __nv_bfloat16* Vlg = Vl + (size_t)bh * CHD * CS;

    auto issue_kv = [&](int stg, int k0) {
        uint32_t base = sb + FKV0 + stg * FKV_STAGE;
#pragma unroll
        for (int it = 0; it < 4; it++) {
            int i = it * 256 + tid;
            int row = i >> 4, ch = i & 15;
            size_t off = (size_t)(k0 + row) * CDQK + ch * 8;
            uint32_t so = fsw(row, ch);
            CP_ASYNC16(base + FO_KH + so, Khg + off);
            CP_ASYNC16(base + FO_KL + so, Klg + off);
        }
#pragma unroll
        for (int it = 0; it < 2; it++) {
            int i = it * 256 + tid;
            int row = i >> 3, ch = i & 7;
            size_t off = (size_t)row * CS + k0 + ch * 8;
            uint32_t so = vsw(row, ch);
            CP_ASYNC16(base + FO_VH + so, Vhg + off);
            CP_ASYNC16(base + FO_VL + so, Vlg + off);
        }
        CP_COMMIT();
    };

    const int nkb = 2 * qb + 2;
    issue_kv(0, 0);
    if (nkb > 1) issue_kv(1, 64);

#pragma unroll
    for (int it = 0; it < 8; it++) {
        int i = it * 256 + tid;
        int row = i >> 4, ch = i & 15;
        size_t off = (size_t)(q0 + row) * CDQK + ch * 8;
        *(uint4*)(smem + FQH + fsw(row, ch)) = *(const uint4*)(Qhg + off);
        *(uint4*)(smem + FQL + fsw(row, ch)) = *(const uint4*)(Qlg + off);
    }
    __syncthreads();

    const int a_tr = (lid & 7) + ((lid >> 3) & 1) * 8;
    const int a_kq = lid >> 4;
    const int b_tr = (lid & 7) + (lid >> 4) * 8;
    const int b_kq = (lid >> 3) & 1;

    uint32_t qhf[8][4], qlf[8][4];
#pragma unroll
    for (int ks = 0; ks < 8; ks++) {
        LDSM_X4(qhf[ks][0], qhf[ks][1], qhf[ks][2], qhf[ks][3],
                sb + FQH + fsw(wid * 16 + a_tr, ks * 2 + a_kq));
        LDSM_X4(qlf[ks][0], qlf[ks][1], qlf[ks][2], qlf[ks][3],
                sb + FQL + fsw(wid * 16 + a_tr, ks * 2 + a_kq));
    }

    float O[8][4];
#pragma unroll
    for (int na = 0; na < 8; na++)
#pragma unroll
        for (int e = 0; e < 4; e++) O[na][e] = 0.f;
    float mI0 = -1e30f, mI1 = -1e30f, lI0 = 0.f, lI1 = 0.f;
    const float scale = 0.08838834764831845f;

    const int qw_last = q0 + wid * 16 + 15;

    for (int kb = 0; kb < nkb; kb++) {
        const int k0 = kb * 64;
        if (kb + 1 < nkb) { CP_WAIT(1); } else { CP_WAIT(0); }
        __syncthreads();
        if (kb + 2 < nkb) issue_kv((kb + 2) % 3, (kb + 2) * 64);

        if (k0 <= qw_last) {
            uint32_t kvb = sb + FKV0 + (kb % 3) * FKV_STAGE;

            float sc[8][4];
#pragma unroll
            for (int na = 0; na < 8; na++)
#pragma unroll
                for (int e = 0; e < 4; e++) sc[na][e] = 0.f;

#pragma unroll
            for (int ks = 0; ks < 8; ks++) {
                uint32_t khf[8][2], klf[8][2];
#pragma unroll
                for (int nb = 0; nb < 4; nb++) {
                    uint32_t so = fsw(nb * 16 + b_tr, ks * 2 + b_kq);
                    LDSM_X4(khf[nb*2][0], khf[nb*2][1], khf[nb*2+1][0], khf[nb*2+1][1], kvb + FO_KH + so);
                    LDSM_X4(klf[nb*2][0], klf[nb*2][1], klf[nb*2+1][0], klf[nb*2+1][1], kvb + FO_KL + so);
                }
#pragma unroll
                for (int na = 0; na < 8; na++) {
                    MMA16816(sc[na], qhf[ks], khf[na]);
                    MMA16816(sc[na], qhf[ks], klf[na]);
                    MMA16816(sc[na], qlf[ks], khf[na]);
                }
            }

            if (k0 + 63 > qw_last - 15) {
#pragma unroll
                for (int na = 0; na < 8; na++)
#pragma unroll
                    for (int e = 0; e < 4; e++) {
                        int qr = q0 + wid * 16 + g + ((e >> 1) << 3);
                        int kc = k0 + na * 8 + 2 * t + (e & 1);
                        sc[na][e] = (kc > qr) ? -1e30f : sc[na][e] * scale;
                    }
            } else {
#pragma unroll
                for (int na = 0; na < 8; na++)
#pragma unroll
                    for (int e = 0; e < 4; e++) sc[na][e] *= scale;
            }

            // ---- row max + alpha (true dependency before PV) ----
            float mx0 = -1e30f, mx1 = -1e30f;
#pragma unroll
            for (int na = 0; na < 8; na++) {
                mx0 = fmaxf(mx0, fmaxf(sc[na][0], sc[na][1]));
                mx1 = fmaxf(mx1, fmaxf(sc[na][2], sc[na][3]));
            }
            mx0 = fmaxf(mx0, __shfl_xor_sync(0xffffffffu, mx0, 1));
            mx0 = fmaxf(mx0, __shfl_xor_sync(0xffffffffu, mx0, 2));
            mx1 = fmaxf(mx1, __shfl_xor_sync(0xffffffffu, mx1, 1));
            mx1 = fmaxf(mx1, __shfl_xor_sync(0xffffffffu, mx1, 2));

            float mn0 = fmaxf(mI0, mx0), mn1 = fmaxf(mI1, mx1);
            float al0 = __expf(mI0 - mn0), al1 = __expf(mI1 - mn1);
            mI0 = mn0; mI1 = mn1;

#pragma unroll
            for (int na = 0; na < 8; na++) {
                O[na][0] *= al0; O[na][1] *= al0;
                O[na][2] *= al1; O[na][3] *= al1;
            }

            // ---- PV with exp interleaved per kk (MUFU overlaps tensor) ----
            float rs0 = 0.f, rs1 = 0.f;
#pragma unroll
            for (int kk = 0; kk < 4; kk++) {
#pragma unroll
                for (int j = 0; j < 2; j++) {
                    int na = 2 * kk + j;
                    sc[na][0] = __expf(sc[na][0] - mn0); rs0 += sc[na][0];
                    sc[na][1] = __expf(sc[na][1] - mn0); rs0 += sc[na][1];
                    sc[na][2] = __expf(sc[na][2] - mn1); rs1 += sc[na][2];
                    sc[na][3] = __expf(sc[na][3] - mn1); rs1 += sc[na][3];
                }
                uint32_t pah[4], pal[4];
                split2(sc[2*kk][0],   sc[2*kk][1],   pah[0], pal[0]);
                split2(sc[2*kk][2],   sc[2*kk][3],   pah[1], pal[1]);
                split2(sc[2*kk+1][0], sc[2*kk+1][1], pah[2], pal[2]);
                split2(sc[2*kk+1][2], sc[2*kk+1][3], pah[3], pal[3]);
                uint32_t vhf[8][2], vlf[8][2];
#pragma unroll
                for (int nb = 0; nb < 4; nb++) {
                    uint32_t so = vsw(nb * 16 + b_tr, kk * 2 + b_kq);
                    LDSM_X4(vhf[nb*2][0], vhf[nb*2][1], vhf[nb*2+1][0], vhf[nb*2+1][1], kvb + FO_VH + so);
                    LDSM_X4(vlf[nb*2][0], vlf[nb*2][1], vlf[nb*2+1][0], vlf[nb*2+1][1], kvb + FO_VL + so);
                }
#pragma unroll
                for (int na = 0; na < 8; na++) {
                    MMA16816(O[na], pah, vhf[na]);
                    MMA16816(O[na], pal, vhf[na]);
                    MMA16816(O[na], pah, vlf[na]);
                }
            }

            // ---- deferred l reduction ----
            rs0 += __shfl_xor_sync(0xffffffffu, rs0, 1);
            rs0 += __shfl_xor_sync(0xffffffffu, rs0, 2);
            rs1 += __shfl_xor_sync(0xffffffffu, rs1, 1);
            rs1 += __shfl_xor_sync(0xffffffffu, rs1, 2);
            lI0 = lI0 * al0 + rs0;
            lI1 = lI1 * al1 + rs1;
        }
    }

    const int b = bh >> 4, h = bh & 15;
    const float inv0 = 1.f / lI0, inv1 = 1.f / lI1;
    const int qr0 = q0 + wid * 16 + g;
#pragma unroll
    for (int na = 0; na < 8; na++) {
        int col = h * CHD + na * 8 + 2 * t;
        uint32_t h0, l0;
        split2(O[na][0] * inv0, O[na][1] * inv0, h0, l0);
        *(uint32_t*)(Yh + (size_t)(b*CS + qr0) * CE + col) = h0;
        *(uint32_t*)(Yl + (size_t)(b*CS + qr0) * CE + col) = l0;
        split2(O[na][2] * inv1, O[na][3] * inv1, h0, l0);
        *(uint32_t*)(Yh + (size_t)(b*CS + qr0 + 8) * CE + col) = h0;
        *(uint32_t*)(Yl + (size_t)(b*CS + qr0 + 8) * CE + col) = l0;
    }
}

// ============================== launcher ===================================
extern "C" void kernel_launch(void* const* d_in, const int* in_sizes, int n_in,
                              void* d_out, int out_size)
{
    const float* x        = (const float*)d_in[0];
    const float* wq_down  = (const float*)d_in[1];
    const float* wk_rope  = (const float*)d_in[2];
    const float* wkv_down = (const float*)d_in[3];
    const float* wq_rope  = (const float*)d_in[4];
    const float* wq_up    = (const float*)d_in[5];
    const float* wk_up    = (const float*)d_in[6];
    const float* wv_up    = (const float*)d_in[7];
    const float* wo       = (const float*)d_in[8];
    float* out = (float*)d_out;

    __nv_bfloat16 *xh,*xl,*lath,*latl,*Yh,*Yl,*wdh,*wdl,*wuh,*wul,*w7h,*w7l;
    __nv_bfloat16 *Qbh,*Qbl,*Kbh,*Kbl,*Vbh,*Vbl;
    float* rtab;
    cudaGetSymbolAddress((void**)&xh,   g_xh);   cudaGetSymbolAddress((void**)&xl,   g_xl);
    cudaGetSymbolAddress((void**)&lath, g_lath); cudaGetSymbolAddress((void**)&latl, g_latl);
    cudaGetSymbolAddress((void**)&Yh,   g_Yh);   cudaGetSymbolAddress((void**)&Yl,   g_Yl);
    cudaGetSymbolAddress((void**)&wdh,  g_wdh);  cudaGetSymbolAddress((void**)&wdl,  g_wdl);
    cudaGetSymbolAddress((void**)&wuh,  g_wuh);  cudaGetSymbolAddress((void**)&wul,  g_wul);
    cudaGetSymbolAddress((void**)&w7h,  g_w7h);  cudaGetSymbolAddress((void**)&w7l,  g_w7l);
    cudaGetSymbolAddress((void**)&Qbh,  g_Qbh);  cudaGetSymbolAddress((void**)&Qbl,  g_Qbl);
    cudaGetSymbolAddress((void**)&Kbh,  g_Kbh);  cudaGetSymbolAddress((void**)&Kbl,  g_Kbl);
    cudaGetSymbolAddress((void**)&Vbh,  g_Vbh);  cudaGetSymbolAddress((void**)&Vbl,  g_Vbl);
    cudaGetSymbolAddress((void**)&rtab, g_ropetab);

    cudaFuncSetAttribute(gemm64<0>, cudaFuncAttributeMaxDynamicSharedMemorySize, G64_SMEM);
    cudaFuncSetAttribute(gemm64<1>, cudaFuncAttributeMaxDynamicSharedMemorySize, G64_SMEM);
    cudaFuncSetAttribute(gemm_up,   cudaFuncAttributeMaxDynamicSharedMemorySize, GEMM_SMEM);
    cudaFuncSetAttribute(flash_attn_mma, cudaFuncAttributeMaxDynamicSharedMemorySize, FLASH_SMEM);

    // fused prep: one launch for x-cvt + all weight cvts + rope LUT
    prep_all<<<(PREP_TAB + 255) / 256, 256>>>(
        x, wq_down, wk_rope, wkv_down, wq_rope, wq_up, wk_up, wv_up, wo,
        xh, xl, wdh, wdl, wuh, wul, w7h, w7l, rtab);

    // fused down projection: lat[4096,768] = x @ [wq_down|wk_rope|wkv_down]^T
    gemm64<1><<<dim3(NLAT/128, MTOK/64), 128, G64_SMEM>>>(
        xh, xl, CE, wdh, wdl, CE, nullptr, lath, latl, NLAT, CE);

    // mega up-projection: all 5 up-GEMMs in one launch -> Q, K, V
    gemm_up<<<dim3(40, MTOK/128), 256, GEMM_SMEM>>>(
        lath, latl, NLAT, wuh, wul, CR, Qbh, Qbl, Kbh, Kbl, Vbh, Vbl, rtab, CR);

    // causal flash attention (LPT-ordered grid) -> Yh/Yl
    flash_attn_mma<<<dim3(CB*CH, NQB), 256, FLASH_SMEM>>>(
        Qbh, Qbl, Kbh, Kbl, Vbh, Vbl, Yh, Yl);

    // output projection: Y @ wo^T -> out (fp32)
    gemm64<0><<<dim3(CE/128, MTOK/64), 128, G64_SMEM>>>(
        Yh, Yl, CE, w7h, w7l, CE, out, nullptr, nullptr, CE, CE);
}